// round 1
// baseline (speedup 1.0000x reference)
#include <cuda_runtime.h>
#include <cuda_bf16.h>
#include <cmath>

// Problem constants
#define Bq     2
#define Sq     2048
#define Dm     1024
#define NQ     16
#define NKV    4
#define GRP    4
#define DQh    64
#define DVh    64

// Scratch (device globals — no allocation allowed)
__device__ float g_xnq[Bq*Sq*Dm];
__device__ float g_xnk[Bq*Sq*Dm];
__device__ float g_xnv[Bq*Sq*Dm];
__device__ float g_Q  [Bq*Sq*NQ*DQh];   // 4,194,304
__device__ float g_K  [Bq*Sq*NKV*DQh];  // 1,048,576
__device__ float g_V  [Bq*Sq*NKV*DVh];
__device__ float g_O  [Bq*Sq*NQ*DVh];
__device__ float g_m  [Bq*NQ*Sq];
__device__ float g_l  [Bq*NQ*Sq];

// ---------------------------------------------------------------------------
// LayerNorm: one block per row of 1024
// ---------------------------------------------------------------------------
__global__ void ln_kernel(const float* __restrict__ x,
                          const float* __restrict__ gamma,
                          const float* __restrict__ beta,
                          float* __restrict__ y)
{
    int row = blockIdx.x;
    int tid = threadIdx.x;                  // 256 threads, 4 elems each
    const float4* xr = (const float4*)(x + (size_t)row * Dm);
    float4 v = xr[tid];
    float s  = v.x + v.y + v.z + v.w;
    float ss = v.x*v.x + v.y*v.y + v.z*v.z + v.w*v.w;
    #pragma unroll
    for (int o = 16; o > 0; o >>= 1) {
        s  += __shfl_down_sync(0xffffffffu, s,  o);
        ss += __shfl_down_sync(0xffffffffu, ss, o);
    }
    __shared__ float as[8], bs[8];
    __shared__ float s_mu, s_inv;
    if ((tid & 31) == 0) { as[tid >> 5] = s; bs[tid >> 5] = ss; }
    __syncthreads();
    if (tid == 0) {
        float S = 0.f, SS = 0.f;
        #pragma unroll
        for (int i = 0; i < 8; i++) { S += as[i]; SS += bs[i]; }
        float mu  = S * (1.0f / Dm);
        float var = SS * (1.0f / Dm) - mu * mu;
        s_mu  = mu;
        s_inv = rsqrtf(var + 1e-5f);
    }
    __syncthreads();
    float mu = s_mu, inv = s_inv;
    float4 g  = ((const float4*)gamma)[tid];
    float4 bb = ((const float4*)beta )[tid];
    float4 o;
    o.x = (v.x - mu) * inv * g.x + bb.x;
    o.y = (v.y - mu) * inv * g.y + bb.y;
    o.z = (v.z - mu) * inv * g.z + bb.z;
    o.w = (v.w - mu) * inv * g.w + bb.w;
    ((float4*)(y + (size_t)row * Dm))[tid] = o;
}

// ---------------------------------------------------------------------------
// Tiled fp32 GEMM with bias: C[M,N] = A[M,K] @ B[K,N] + bias
// 64x64 block tile, 16-deep K tile, 256 threads, 4x4 microtile
// Requires M%64==0, N%64==0, K%16==0
// ---------------------------------------------------------------------------
__global__ void gemm_bias_kernel(const float* __restrict__ A,
                                 const float* __restrict__ B,
                                 const float* __restrict__ bias,
                                 float* __restrict__ C,
                                 int M, int N, int K)
{
    __shared__ float As[16][64];
    __shared__ float Bs[16][64];
    int tid = threadIdx.x;
    int tx = tid & 15, ty = tid >> 4;
    int mb = blockIdx.y * 64, nb = blockIdx.x * 64;

    int ar = tid >> 2;            // 0..63
    int ak = (tid & 3) * 4;       // 0..12
    int bk = tid >> 4;            // 0..15
    int bn = (tid & 15) * 4;      // 0..60

    float acc[4][4];
    #pragma unroll
    for (int i = 0; i < 4; i++)
        #pragma unroll
        for (int j = 0; j < 4; j++) acc[i][j] = 0.f;

    for (int k0 = 0; k0 < K; k0 += 16) {
        float4 av = *(const float4*)&A[(size_t)(mb + ar) * K + k0 + ak];
        As[ak + 0][ar] = av.x;
        As[ak + 1][ar] = av.y;
        As[ak + 2][ar] = av.z;
        As[ak + 3][ar] = av.w;
        float4 bv = *(const float4*)&B[(size_t)(k0 + bk) * N + nb + bn];
        *(float4*)&Bs[bk][bn] = bv;
        __syncthreads();
        #pragma unroll
        for (int kk = 0; kk < 16; kk++) {
            float4 a  = *(const float4*)&As[kk][ty * 4];
            float4 b4 = *(const float4*)&Bs[kk][tx * 4];
            float ai[4] = {a.x, a.y, a.z, a.w};
            float bj[4] = {b4.x, b4.y, b4.z, b4.w};
            #pragma unroll
            for (int i = 0; i < 4; i++)
                #pragma unroll
                for (int j = 0; j < 4; j++)
                    acc[i][j] += ai[i] * bj[j];
        }
        __syncthreads();
    }

    float4 bsv = *(const float4*)&bias[nb + tx * 4];
    #pragma unroll
    for (int i = 0; i < 4; i++) {
        float4 o;
        o.x = acc[i][0] + bsv.x;
        o.y = acc[i][1] + bsv.y;
        o.z = acc[i][2] + bsv.z;
        o.w = acc[i][3] + bsv.w;
        *(float4*)&C[(size_t)(mb + ty * 4 + i) * N + nb + tx * 4] = o;
    }
}

// ---------------------------------------------------------------------------
// RoPE (interleaved pairs), in place. p indexes pairs; memory pair = 2p.
// ---------------------------------------------------------------------------
__global__ void rope_kernel(float* __restrict__ X, int heads, int total_pairs)
{
    int p = blockIdx.x * blockDim.x + threadIdx.x;
    if (p >= total_pairs) return;
    int i = p & 31;                          // freq index 0..31
    int t = (p / (32 * heads)) & (Sq - 1);   // sequence position
    float invf = powf(10000.0f, -((float)(2 * i)) / 64.0f);
    float ang  = (float)t * invf;
    float sn, cs;
    sincosf(ang, &sn, &cs);
    size_t e = (size_t)p * 2;
    float x1 = X[e], x2 = X[e + 1];
    X[e]     = x1 * cs - x2 * sn;
    X[e + 1] = x1 * sn + x2 * cs;
}

// ---------------------------------------------------------------------------
// Attention pass 1: flash-style. Per block: one (b, qh, 64-row q tile).
// Writes masked raw scores into attn buffer, tracks (m,l), accumulates O.
// ---------------------------------------------------------------------------
#define ATTN_SMEM_FLOATS (4096*3 + 64*65 + 64*3 + 256)
__global__ void attn_kernel(const int* __restrict__ lens,
                            float* __restrict__ attn)
{
    extern __shared__ float sm[];
    float* Qst  = sm;            // [64k][64m]
    float* Kst  = sm + 4096;     // [64k][64n]
    float* Vs   = sm + 8192;     // [64n][64d]
    float* Ps   = sm + 12288;    // [64m][65]
    float* mrow = sm + 12288 + 64 * 65;
    float* lrow = mrow + 64;
    float* fac  = lrow + 64;
    float* sred = fac + 64;      // [4][64]

    int tid = threadIdx.x;
    int tx = tid & 15, ty = tid >> 4;
    int m0 = ty * 4, n0 = tx * 4;
    int mt = blockIdx.x, qh = blockIdx.y, b = blockIdx.z;
    int kvh = qh >> 2;
    int grp = qh & 3;
    int len = lens[b];

    // Load Q tile (64 rows x 64 d) transposed to k-major
    #pragma unroll
    for (int i = 0; i < 4; i++) {
        int lin = tid + i * 256;
        int r = lin >> 4, c4 = (lin & 15) * 4;
        float4 v = *(const float4*)&g_Q[((size_t)(b * Sq + mt * 64 + r)) * (NQ * DQh) + qh * 64 + c4];
        Qst[(c4 + 0) * 64 + r] = v.x;
        Qst[(c4 + 1) * 64 + r] = v.y;
        Qst[(c4 + 2) * 64 + r] = v.z;
        Qst[(c4 + 3) * 64 + r] = v.w;
    }
    if (tid < 64) { mrow[tid] = -3.0e38f; lrow[tid] = 0.f; }

    float o[4][4];
    #pragma unroll
    for (int i = 0; i < 4; i++)
        #pragma unroll
        for (int j = 0; j < 4; j++) o[i][j] = 0.f;

    int jend = min(mt, (len - 1) >> 6);
    size_t attn_head = (((size_t)(b * GRP + grp)) * NKV + kvh) * Sq;

    for (int jt = 0; jt <= jend; jt++) {
        __syncthreads();
        // Load K tile transposed, V tile direct
        #pragma unroll
        for (int i = 0; i < 4; i++) {
            int lin = tid + i * 256;
            int r = lin >> 4, c4 = (lin & 15) * 4;
            size_t gidx = ((size_t)(b * Sq + jt * 64 + r)) * (NKV * DQh) + kvh * 64 + c4;
            float4 kv = *(const float4*)&g_K[gidx];
            Kst[(c4 + 0) * 64 + r] = kv.x;
            Kst[(c4 + 1) * 64 + r] = kv.y;
            Kst[(c4 + 2) * 64 + r] = kv.z;
            Kst[(c4 + 3) * 64 + r] = kv.w;
            float4 vv = *(const float4*)&g_V[gidx];
            *(float4*)&Vs[r * 64 + c4] = vv;
        }
        __syncthreads();

        // S = Q K^T
        float s[4][4];
        #pragma unroll
        for (int i = 0; i < 4; i++)
            #pragma unroll
            for (int j = 0; j < 4; j++) s[i][j] = 0.f;
        #pragma unroll 16
        for (int kk = 0; kk < 64; kk++) {
            float4 a  = *(const float4*)&Qst[kk * 64 + m0];
            float4 b4 = *(const float4*)&Kst[kk * 64 + n0];
            float ai[4] = {a.x, a.y, a.z, a.w};
            float bj[4] = {b4.x, b4.y, b4.z, b4.w};
            #pragma unroll
            for (int i = 0; i < 4; i++)
                #pragma unroll
                for (int j = 0; j < 4; j++)
                    s[i][j] += ai[i] * bj[j];
        }

        // scale, mask, store to Ps + gmem raw scores
        #pragma unroll
        for (int i = 0; i < 4; i++) {
            int qr = mt * 64 + m0 + i;
            float4 w;
            float vals[4];
            #pragma unroll
            for (int j = 0; j < 4; j++) {
                int kc = jt * 64 + n0 + j;
                float val = s[i][j] * 0.125f;
                if (kc > qr || kc >= len) val = -1.0e30f;
                vals[j] = val;
                Ps[(m0 + i) * 65 + n0 + j] = val;
            }
            w.x = vals[0]; w.y = vals[1]; w.z = vals[2]; w.w = vals[3];
            *(float4*)&attn[(attn_head + qr) * Sq + jt * 64 + n0] = w;
        }
        __syncthreads();

        // row max (distributed 4 threads/row)
        {
            int r = tid & 63, q = tid >> 6;
            float tmax = -3.0e38f;
            #pragma unroll
            for (int k = 0; k < 16; k++)
                tmax = fmaxf(tmax, Ps[r * 65 + q * 16 + k]);
            sred[q * 64 + r] = tmax;
        }
        __syncthreads();
        if (tid < 64) {
            float mn = fmaxf(fmaxf(sred[tid], sred[64 + tid]),
                             fmaxf(sred[128 + tid], sred[192 + tid]));
            mn = fmaxf(mn, mrow[tid]);
            fac[tid] = __expf(mrow[tid] - mn);
            mrow[tid] = mn;
        }
        __syncthreads();
        // exponentiate + partial sums
        {
            int r = tid & 63, q = tid >> 6;
            float mn = mrow[r];
            float sum = 0.f;
            #pragma unroll
            for (int k = 0; k < 16; k++) {
                float p = __expf(Ps[r * 65 + q * 16 + k] - mn);
                Ps[r * 65 + q * 16 + k] = p;
                sum += p;
            }
            sred[q * 64 + r] = sum;
        }
        __syncthreads();
        if (tid < 64)
            lrow[tid] = lrow[tid] * fac[tid]
                      + (sred[tid] + sred[64 + tid] + sred[128 + tid] + sred[192 + tid]);
        __syncthreads();

        // rescale accumulator + O += P @ V
        float f[4] = {fac[m0], fac[m0 + 1], fac[m0 + 2], fac[m0 + 3]};
        #pragma unroll
        for (int i = 0; i < 4; i++)
            #pragma unroll
            for (int j = 0; j < 4; j++) o[i][j] *= f[i];

        #pragma unroll 8
        for (int n = 0; n < 64; n++) {
            float4 v4 = *(const float4*)&Vs[n * 64 + n0];
            float vj[4] = {v4.x, v4.y, v4.z, v4.w};
            float pi[4] = {Ps[(m0 + 0) * 65 + n], Ps[(m0 + 1) * 65 + n],
                           Ps[(m0 + 2) * 65 + n], Ps[(m0 + 3) * 65 + n]};
            #pragma unroll
            for (int i = 0; i < 4; i++)
                #pragma unroll
                for (int j = 0; j < 4; j++)
                    o[i][j] += pi[i] * vj[j];
        }
    }
    __syncthreads();

    // epilogue: O /= l ; write O, write stats
    #pragma unroll
    for (int i = 0; i < 4; i++) {
        float inv = 1.0f / lrow[m0 + i];
        int qr = mt * 64 + m0 + i;
        float4 w;
        w.x = o[i][0] * inv; w.y = o[i][1] * inv;
        w.z = o[i][2] * inv; w.w = o[i][3] * inv;
        *(float4*)&g_O[((size_t)(b * Sq + qr)) * (NQ * DVh) + qh * 64 + n0] = w;
    }
    if (tid < 64) {
        size_t si = ((size_t)b * NQ + qh) * Sq + mt * 64 + tid;
        g_m[si] = mrow[tid];
        g_l[si] = lrow[tid];
    }
}

// ---------------------------------------------------------------------------
// Attention pass 2: normalize probabilities (and zero the masked region).
// One block per attn row; 256 threads x 8 cols.
// ---------------------------------------------------------------------------
__global__ void attn_norm_kernel(const int* __restrict__ lens,
                                 float* __restrict__ attn)
{
    size_t row = blockIdx.x;
    int t   = (int)(row & (Sq - 1));
    int kvh = (int)((row >> 11) & 3);
    int grp = (int)((row >> 13) & 3);
    int n   = (int)(row >> 15);
    int qh  = kvh * GRP + grp;
    int len = lens[n];
    size_t si = ((size_t)n * NQ + qh) * Sq + t;
    float mn  = g_m[si];
    float inv = 1.0f / g_l[si];
    float* rp = attn + row * (size_t)Sq;
    int lim = min(t, len - 1);          // valid cols: 0..lim
    int c0 = threadIdx.x * 8;
    #pragma unroll
    for (int u = 0; u < 8; u += 4) {
        int c = c0 + u;
        float4 v;
        if (c + 3 <= lim) {
            float4 s4 = *(const float4*)&rp[c];
            v.x = __expf(s4.x - mn) * inv;
            v.y = __expf(s4.y - mn) * inv;
            v.z = __expf(s4.z - mn) * inv;
            v.w = __expf(s4.w - mn) * inv;
        } else {
            v.x = (c + 0 <= lim) ? __expf(rp[c + 0] - mn) * inv : 0.f;
            v.y = (c + 1 <= lim) ? __expf(rp[c + 1] - mn) * inv : 0.f;
            v.z = (c + 2 <= lim) ? __expf(rp[c + 2] - mn) * inv : 0.f;
            v.w = (c + 3 <= lim) ? __expf(rp[c + 3] - mn) * inv : 0.f;
        }
        *(float4*)&rp[c] = v;
    }
}

// ---------------------------------------------------------------------------
// Launch
// ---------------------------------------------------------------------------
extern "C" void kernel_launch(void* const* d_in, const int* in_sizes, int n_in,
                              void* d_out, int out_size)
{
    const float* x_q  = (const float*)d_in[0];
    const float* x_k  = (const float*)d_in[1];
    const float* x_v  = (const float*)d_in[2];
    const int*   lens = (const int*)  d_in[3];
    const float* gam  = (const float*)d_in[4];
    const float* bet  = (const float*)d_in[5];
    const float* Wq   = (const float*)d_in[6];
    const float* bq   = (const float*)d_in[7];
    const float* Wk   = (const float*)d_in[8];
    const float* bk   = (const float*)d_in[9];
    const float* Wv   = (const float*)d_in[10];
    const float* bv   = (const float*)d_in[11];
    const float* Wo   = (const float*)d_in[12];
    const float* bo   = (const float*)d_in[13];

    float* out  = (float*)d_out;                       // (B, S, 1024)
    float* attn = out + (size_t)Bq * Sq * Dm;          // (B, GRP, NKV, S, S)

    float *xnq, *xnk, *xnv, *Qb, *Kb, *Vb, *Ob;
    cudaGetSymbolAddress((void**)&xnq, g_xnq);
    cudaGetSymbolAddress((void**)&xnk, g_xnk);
    cudaGetSymbolAddress((void**)&xnv, g_xnv);
    cudaGetSymbolAddress((void**)&Qb,  g_Q);
    cudaGetSymbolAddress((void**)&Kb,  g_K);
    cudaGetSymbolAddress((void**)&Vb,  g_V);
    cudaGetSymbolAddress((void**)&Ob,  g_O);

    const int M = Bq * Sq;   // 4096

    // 1) LayerNorms
    ln_kernel<<<M, 256>>>(x_q, gam, bet, xnq);
    ln_kernel<<<M, 256>>>(x_k, gam, bet, xnk);
    ln_kernel<<<M, 256>>>(x_v, gam, bet, xnv);

    // 2) Projections
    gemm_bias_kernel<<<dim3(Dm / 64, M / 64), 256>>>(xnq, Wq, bq, Qb, M, NQ * DQh, Dm);
    gemm_bias_kernel<<<dim3((NKV * DQh) / 64, M / 64), 256>>>(xnk, Wk, bk, Kb, M, NKV * DQh, Dm);
    gemm_bias_kernel<<<dim3((NKV * DVh) / 64, M / 64), 256>>>(xnv, Wv, bv, Vb, M, NKV * DVh, Dm);

    // 3) RoPE (Q: 16 heads, K: 4 heads)
    {
        int pq = Bq * Sq * NQ * 32;
        int pk = Bq * Sq * NKV * 32;
        rope_kernel<<<(pq + 255) / 256, 256>>>(Qb, NQ, pq);
        rope_kernel<<<(pk + 255) / 256, 256>>>(Kb, NKV, pk);
    }

    // 4) Attention pass 1 (scores + online softmax stats + O)
    {
        size_t smem = ATTN_SMEM_FLOATS * sizeof(float);
        cudaFuncSetAttribute(attn_kernel, cudaFuncAttributeMaxDynamicSharedMemorySize, (int)smem);
        attn_kernel<<<dim3(Sq / 64, NQ, Bq), 256, smem>>>(lens, attn);
    }

    // 5) Attention pass 2 (normalize probs / zero-fill)
    attn_norm_kernel<<<Bq * GRP * NKV * Sq, 256>>>(lens, attn);

    // 6) Output projection
    gemm_bias_kernel<<<dim3(Dm / 64, M / 64), 256>>>(Ob, Wo, bo, out, M, Dm, Dm);
}

// round 2
// speedup vs baseline: 1.1108x; 1.1108x over previous
#include <cuda_runtime.h>
#include <cuda_bf16.h>
#include <cmath>

// Problem constants
#define Bq     2
#define Sq     2048
#define Dm     1024
#define NQ     16
#define NKV    4
#define GRP    4
#define DQh    64
#define DVh    64

// Scratch (device globals — no allocation allowed)
__device__ float g_xnq[Bq*Sq*Dm];
__device__ float g_xnk[Bq*Sq*Dm];
__device__ float g_xnv[Bq*Sq*Dm];
__device__ float g_Q  [Bq*Sq*NQ*DQh];
__device__ float g_K  [Bq*Sq*NKV*DQh];
__device__ float g_V  [Bq*Sq*NKV*DVh];
__device__ float g_O  [Bq*Sq*NQ*DVh];
__device__ float g_m  [Bq*NQ*Sq];
__device__ float g_l  [Bq*NQ*Sq];

// ---------------------------------------------------------------------------
// LayerNorm: one block per row of 1024
// ---------------------------------------------------------------------------
__global__ void ln_kernel(const float* __restrict__ x,
                          const float* __restrict__ gamma,
                          const float* __restrict__ beta,
                          float* __restrict__ y)
{
    int row = blockIdx.x;
    int tid = threadIdx.x;                  // 256 threads, 4 elems each
    const float4* xr = (const float4*)(x + (size_t)row * Dm);
    float4 v = xr[tid];
    float s  = v.x + v.y + v.z + v.w;
    float ss = v.x*v.x + v.y*v.y + v.z*v.z + v.w*v.w;
    #pragma unroll
    for (int o = 16; o > 0; o >>= 1) {
        s  += __shfl_down_sync(0xffffffffu, s,  o);
        ss += __shfl_down_sync(0xffffffffu, ss, o);
    }
    __shared__ float as[8], bs[8];
    __shared__ float s_mu, s_inv;
    if ((tid & 31) == 0) { as[tid >> 5] = s; bs[tid >> 5] = ss; }
    __syncthreads();
    if (tid == 0) {
        float S = 0.f, SS = 0.f;
        #pragma unroll
        for (int i = 0; i < 8; i++) { S += as[i]; SS += bs[i]; }
        float mu  = S * (1.0f / Dm);
        float var = SS * (1.0f / Dm) - mu * mu;
        s_mu  = mu;
        s_inv = rsqrtf(var + 1e-5f);
    }
    __syncthreads();
    float mu = s_mu, inv = s_inv;
    float4 g  = ((const float4*)gamma)[tid];
    float4 bb = ((const float4*)beta )[tid];
    float4 o;
    o.x = (v.x - mu) * inv * g.x + bb.x;
    o.y = (v.y - mu) * inv * g.y + bb.y;
    o.z = (v.z - mu) * inv * g.z + bb.z;
    o.w = (v.w - mu) * inv * g.w + bb.w;
    ((float4*)(y + (size_t)row * Dm))[tid] = o;
}

// ---------------------------------------------------------------------------
// Big fp32 GEMM with bias: C[M,N] = A[M,K] @ B[K,N] + bias
// 128x128 block tile, K-tile 8, 256 threads, 8x8 microtile, double-buffered.
// Requires M%128==0, N%128==0, K%8==0.
// ---------------------------------------------------------------------------
__global__ void gemm_bias_128(const float* __restrict__ A,
                              const float* __restrict__ B,
                              const float* __restrict__ bias,
                              float* __restrict__ C,
                              int M, int N, int K)
{
    __shared__ float As[2][8][128];
    __shared__ float Bs[2][8][128];
    int tid = threadIdx.x;
    int tx = tid & 15, ty = tid >> 4;
    int mb = blockIdx.y * 128, nb = blockIdx.x * 128;

    int ar = tid >> 1, ak = (tid & 1) * 4;   // A: row 0..127, k 0/4
    int bk = tid >> 5, bn = (tid & 31) * 4;  // B: k 0..7, col 0..124

    const float* Aptr = A + (size_t)(mb + ar) * K + ak;
    const float* Bptr = B + (size_t)bk * N + nb + bn;

    float acc[8][8];
    #pragma unroll
    for (int i = 0; i < 8; i++)
        #pragma unroll
        for (int j = 0; j < 8; j++) acc[i][j] = 0.f;

    // preload tile 0
    {
        float4 av = *(const float4*)Aptr;
        As[0][ak + 0][ar] = av.x;
        As[0][ak + 1][ar] = av.y;
        As[0][ak + 2][ar] = av.z;
        As[0][ak + 3][ar] = av.w;
        float4 bv = *(const float4*)Bptr;
        *(float4*)&Bs[0][bk][bn] = bv;
    }
    __syncthreads();

    int nt = K >> 3;
    for (int t = 0; t < nt; t++) {
        int cur = t & 1, nxt = cur ^ 1;
        float4 a2, b2;
        bool more = (t + 1 < nt);
        if (more) {
            a2 = *(const float4*)(Aptr + (size_t)(t + 1) * 8);
            b2 = *(const float4*)(Bptr + (size_t)(t + 1) * 8 * N);
        }
        #pragma unroll
        for (int kk = 0; kk < 8; kk++) {
            float4 a0 = *(const float4*)&As[cur][kk][ty * 8];
            float4 a1 = *(const float4*)&As[cur][kk][ty * 8 + 4];
            float4 b0 = *(const float4*)&Bs[cur][kk][tx * 8];
            float4 b1 = *(const float4*)&Bs[cur][kk][tx * 8 + 4];
            float ai[8] = {a0.x, a0.y, a0.z, a0.w, a1.x, a1.y, a1.z, a1.w};
            float bj[8] = {b0.x, b0.y, b0.z, b0.w, b1.x, b1.y, b1.z, b1.w};
            #pragma unroll
            for (int i = 0; i < 8; i++)
                #pragma unroll
                for (int j = 0; j < 8; j++)
                    acc[i][j] += ai[i] * bj[j];
        }
        if (more) {
            As[nxt][ak + 0][ar] = a2.x;
            As[nxt][ak + 1][ar] = a2.y;
            As[nxt][ak + 2][ar] = a2.z;
            As[nxt][ak + 3][ar] = a2.w;
            *(float4*)&Bs[nxt][bk][bn] = b2;
            __syncthreads();
        }
    }

    float4 bs0 = *(const float4*)&bias[nb + tx * 8];
    float4 bs1 = *(const float4*)&bias[nb + tx * 8 + 4];
    float bj[8] = {bs0.x, bs0.y, bs0.z, bs0.w, bs1.x, bs1.y, bs1.z, bs1.w};
    #pragma unroll
    for (int i = 0; i < 8; i++) {
        float* cp = &C[(size_t)(mb + ty * 8 + i) * N + nb + tx * 8];
        float4 o0, o1;
        o0.x = acc[i][0] + bj[0]; o0.y = acc[i][1] + bj[1];
        o0.z = acc[i][2] + bj[2]; o0.w = acc[i][3] + bj[3];
        o1.x = acc[i][4] + bj[4]; o1.y = acc[i][5] + bj[5];
        o1.z = acc[i][6] + bj[6]; o1.w = acc[i][7] + bj[7];
        *(float4*)cp = o0;
        *(float4*)(cp + 4) = o1;
    }
}

// ---------------------------------------------------------------------------
// Small-N GEMM with bias (64x64 tile, 4x4 microtile) — for K/V projections
// ---------------------------------------------------------------------------
__global__ void gemm_bias_kernel(const float* __restrict__ A,
                                 const float* __restrict__ B,
                                 const float* __restrict__ bias,
                                 float* __restrict__ C,
                                 int M, int N, int K)
{
    __shared__ float As[16][64];
    __shared__ float Bs[16][64];
    int tid = threadIdx.x;
    int tx = tid & 15, ty = tid >> 4;
    int mb = blockIdx.y * 64, nb = blockIdx.x * 64;

    int ar = tid >> 2;
    int ak = (tid & 3) * 4;
    int bk = tid >> 4;
    int bn = (tid & 15) * 4;

    float acc[4][4];
    #pragma unroll
    for (int i = 0; i < 4; i++)
        #pragma unroll
        for (int j = 0; j < 4; j++) acc[i][j] = 0.f;

    for (int k0 = 0; k0 < K; k0 += 16) {
        float4 av = *(const float4*)&A[(size_t)(mb + ar) * K + k0 + ak];
        As[ak + 0][ar] = av.x;
        As[ak + 1][ar] = av.y;
        As[ak + 2][ar] = av.z;
        As[ak + 3][ar] = av.w;
        float4 bv = *(const float4*)&B[(size_t)(k0 + bk) * N + nb + bn];
        *(float4*)&Bs[bk][bn] = bv;
        __syncthreads();
        #pragma unroll
        for (int kk = 0; kk < 16; kk++) {
            float4 a  = *(const float4*)&As[kk][ty * 4];
            float4 b4 = *(const float4*)&Bs[kk][tx * 4];
            float ai[4] = {a.x, a.y, a.z, a.w};
            float bj[4] = {b4.x, b4.y, b4.z, b4.w};
            #pragma unroll
            for (int i = 0; i < 4; i++)
                #pragma unroll
                for (int j = 0; j < 4; j++)
                    acc[i][j] += ai[i] * bj[j];
        }
        __syncthreads();
    }

    float4 bsv = *(const float4*)&bias[nb + tx * 4];
    #pragma unroll
    for (int i = 0; i < 4; i++) {
        float4 o;
        o.x = acc[i][0] + bsv.x;
        o.y = acc[i][1] + bsv.y;
        o.z = acc[i][2] + bsv.z;
        o.w = acc[i][3] + bsv.w;
        *(float4*)&C[(size_t)(mb + ty * 4 + i) * N + nb + tx * 4] = o;
    }
}

// ---------------------------------------------------------------------------
// RoPE (interleaved pairs), in place.
// ---------------------------------------------------------------------------
__global__ void rope_kernel(float* __restrict__ X, int heads, int total_pairs)
{
    int p = blockIdx.x * blockDim.x + threadIdx.x;
    if (p >= total_pairs) return;
    int i = p & 31;
    int t = (p / (32 * heads)) & (Sq - 1);
    float invf = powf(10000.0f, -((float)(2 * i)) / 64.0f);
    float ang  = (float)t * invf;
    float sn, cs;
    sincosf(ang, &sn, &cs);
    size_t e = (size_t)p * 2;
    float x1 = X[e], x2 = X[e + 1];
    X[e]     = x1 * cs - x2 * sn;
    X[e + 1] = x1 * sn + x2 * cs;
}

// ---------------------------------------------------------------------------
// Attention pass 1: flash-style, Mq=128 q-rows x Nk=64 k-cols per iteration.
// 256 threads, 8x4 microtiles for S and O.
// Writes masked raw scores into attn buffer, tracks (m,l), accumulates O.
// ---------------------------------------------------------------------------
#define ATTN_SMEM_FLOATS (128*64 + 64*64 + 64*64 + 128*65 + 128*3 + 256)
__global__ void attn_kernel(const int* __restrict__ lens,
                            float* __restrict__ attn)
{
    extern __shared__ float sm[];
    float* Qst  = sm;                       // [64 k][128 m]
    float* Kst  = Qst + 128 * 64;           // [64 k][64 n]
    float* Vs   = Kst + 64 * 64;            // [64 n][64 d]
    float* Ps   = Vs + 64 * 64;             // [128 m][65]
    float* mrow = Ps + 128 * 65;            // [128]
    float* lrow = mrow + 128;
    float* fac  = lrow + 128;
    float* sred = fac + 128;                // [2][128]

    int tid = threadIdx.x;
    int tx = tid & 15, ty = tid >> 4;
    int m0 = ty * 8, n0 = tx * 4;
    int mt = blockIdx.x, qh = blockIdx.y, b = blockIdx.z;
    int kvh = qh >> 2;
    int grp = qh & 3;
    int len = lens[b];

    // Load Q tile (128 rows x 64 d) transposed to k-major
    #pragma unroll
    for (int i = 0; i < 8; i++) {
        int lin = tid + i * 256;
        int r = lin >> 4, c4 = (lin & 15) * 4;
        float4 v = *(const float4*)&g_Q[((size_t)(b * Sq + mt * 128 + r)) * (NQ * DQh) + qh * 64 + c4];
        Qst[(c4 + 0) * 128 + r] = v.x;
        Qst[(c4 + 1) * 128 + r] = v.y;
        Qst[(c4 + 2) * 128 + r] = v.z;
        Qst[(c4 + 3) * 128 + r] = v.w;
    }
    if (tid < 128) { mrow[tid] = -3.0e38f; lrow[tid] = 0.f; }

    float o[8][4];
    #pragma unroll
    for (int i = 0; i < 8; i++)
        #pragma unroll
        for (int j = 0; j < 4; j++) o[i][j] = 0.f;

    int jend = min(2 * mt + 1, (len - 1) >> 6);
    size_t attn_head = (((size_t)(b * GRP + grp)) * NKV + kvh) * Sq;

    for (int jt = 0; jt <= jend; jt++) {
        __syncthreads();
        // Load K tile transposed, V tile direct (64 x 64 each)
        #pragma unroll
        for (int i = 0; i < 4; i++) {
            int lin = tid + i * 256;
            int r = lin >> 4, c4 = (lin & 15) * 4;
            size_t gidx = ((size_t)(b * Sq + jt * 64 + r)) * (NKV * DQh) + kvh * 64 + c4;
            float4 kv = *(const float4*)&g_K[gidx];
            Kst[(c4 + 0) * 64 + r] = kv.x;
            Kst[(c4 + 1) * 64 + r] = kv.y;
            Kst[(c4 + 2) * 64 + r] = kv.z;
            Kst[(c4 + 3) * 64 + r] = kv.w;
            float4 vv = *(const float4*)&g_V[gidx];
            *(float4*)&Vs[r * 64 + c4] = vv;
        }
        __syncthreads();

        // S = Q K^T  (8x4 per thread)
        float s[8][4];
        #pragma unroll
        for (int i = 0; i < 8; i++)
            #pragma unroll
            for (int j = 0; j < 4; j++) s[i][j] = 0.f;
        #pragma unroll 8
        for (int kk = 0; kk < 64; kk++) {
            float4 a0 = *(const float4*)&Qst[kk * 128 + m0];
            float4 a1 = *(const float4*)&Qst[kk * 128 + m0 + 4];
            float4 b4 = *(const float4*)&Kst[kk * 64 + n0];
            float ai[8] = {a0.x, a0.y, a0.z, a0.w, a1.x, a1.y, a1.z, a1.w};
            float bj[4] = {b4.x, b4.y, b4.z, b4.w};
            #pragma unroll
            for (int i = 0; i < 8; i++)
                #pragma unroll
                for (int j = 0; j < 4; j++)
                    s[i][j] += ai[i] * bj[j];
        }

        // scale, mask, store to Ps + gmem raw scores
        #pragma unroll
        for (int i = 0; i < 8; i++) {
            int qr = mt * 128 + m0 + i;
            float vals[4];
            #pragma unroll
            for (int j = 0; j < 4; j++) {
                int kc = jt * 64 + n0 + j;
                float val = s[i][j] * 0.125f;
                if (kc > qr || kc >= len) val = -1.0e30f;
                vals[j] = val;
                Ps[(m0 + i) * 65 + n0 + j] = val;
            }
            float4 w;
            w.x = vals[0]; w.y = vals[1]; w.z = vals[2]; w.w = vals[3];
            *(float4*)&attn[(attn_head + qr) * Sq + jt * 64 + n0] = w;
        }
        __syncthreads();

        // row max (2 threads per row, 32 cols each)
        {
            int r = tid & 127, half = tid >> 7;
            float tmax = -3.0e38f;
            #pragma unroll
            for (int k = 0; k < 32; k++)
                tmax = fmaxf(tmax, Ps[r * 65 + half * 32 + k]);
            sred[half * 128 + r] = tmax;
        }
        __syncthreads();
        if (tid < 128) {
            float mn = fmaxf(sred[tid], sred[128 + tid]);
            mn = fmaxf(mn, mrow[tid]);
            fac[tid] = __expf(mrow[tid] - mn);
            mrow[tid] = mn;
        }
        __syncthreads();
        // exponentiate + partial sums
        {
            int r = tid & 127, half = tid >> 7;
            float mn = mrow[r];
            float sum = 0.f;
            #pragma unroll
            for (int k = 0; k < 32; k++) {
                float p = __expf(Ps[r * 65 + half * 32 + k] - mn);
                Ps[r * 65 + half * 32 + k] = p;
                sum += p;
            }
            sred[half * 128 + r] = sum;
        }
        __syncthreads();
        if (tid < 128)
            lrow[tid] = lrow[tid] * fac[tid] + (sred[tid] + sred[128 + tid]);
        __syncthreads();

        // rescale accumulator + O += P @ V
        float f[8];
        #pragma unroll
        for (int i = 0; i < 8; i++) f[i] = fac[m0 + i];
        #pragma unroll
        for (int i = 0; i < 8; i++)
            #pragma unroll
            for (int j = 0; j < 4; j++) o[i][j] *= f[i];

        #pragma unroll 8
        for (int n = 0; n < 64; n++) {
            float4 v4 = *(const float4*)&Vs[n * 64 + n0];
            float vj[4] = {v4.x, v4.y, v4.z, v4.w};
            float pi[8];
            #pragma unroll
            for (int i = 0; i < 8; i++) pi[i] = Ps[(m0 + i) * 65 + n];
            #pragma unroll
            for (int i = 0; i < 8; i++)
                #pragma unroll
                for (int j = 0; j < 4; j++)
                    o[i][j] += pi[i] * vj[j];
        }
    }
    __syncthreads();

    // epilogue: O /= l ; write O, write stats
    #pragma unroll
    for (int i = 0; i < 8; i++) {
        float inv = 1.0f / lrow[m0 + i];
        int qr = mt * 128 + m0 + i;
        float4 w;
        w.x = o[i][0] * inv; w.y = o[i][1] * inv;
        w.z = o[i][2] * inv; w.w = o[i][3] * inv;
        *(float4*)&g_O[((size_t)(b * Sq + qr)) * (NQ * DVh) + qh * 64 + n0] = w;
    }
    if (tid < 128) {
        size_t si = ((size_t)b * NQ + qh) * Sq + mt * 128 + tid;
        g_m[si] = mrow[tid];
        g_l[si] = lrow[tid];
    }
}

// ---------------------------------------------------------------------------
// Attention pass 2: normalize probabilities (and zero the masked region).
// ---------------------------------------------------------------------------
__global__ void attn_norm_kernel(const int* __restrict__ lens,
                                 float* __restrict__ attn)
{
    size_t row = blockIdx.x;
    int t   = (int)(row & (Sq - 1));
    int kvh = (int)((row >> 11) & 3);
    int grp = (int)((row >> 13) & 3);
    int n   = (int)(row >> 15);
    int qh  = kvh * GRP + grp;
    int len = lens[n];
    size_t si = ((size_t)n * NQ + qh) * Sq + t;
    float mn  = g_m[si];
    float inv = 1.0f / g_l[si];
    float* rp = attn + row * (size_t)Sq;
    int lim = min(t, len - 1);
    int c0 = threadIdx.x * 8;
    #pragma unroll
    for (int u = 0; u < 8; u += 4) {
        int c = c0 + u;
        float4 v;
        if (c + 3 <= lim) {
            float4 s4 = *(const float4*)&rp[c];
            v.x = __expf(s4.x - mn) * inv;
            v.y = __expf(s4.y - mn) * inv;
            v.z = __expf(s4.z - mn) * inv;
            v.w = __expf(s4.w - mn) * inv;
        } else {
            v.x = (c + 0 <= lim) ? __expf(rp[c + 0] - mn) * inv : 0.f;
            v.y = (c + 1 <= lim) ? __expf(rp[c + 1] - mn) * inv : 0.f;
            v.z = (c + 2 <= lim) ? __expf(rp[c + 2] - mn) * inv : 0.f;
            v.w = (c + 3 <= lim) ? __expf(rp[c + 3] - mn) * inv : 0.f;
        }
        *(float4*)&rp[c] = v;
    }
}

// ---------------------------------------------------------------------------
// Launch
// ---------------------------------------------------------------------------
extern "C" void kernel_launch(void* const* d_in, const int* in_sizes, int n_in,
                              void* d_out, int out_size)
{
    const float* x_q  = (const float*)d_in[0];
    const float* x_k  = (const float*)d_in[1];
    const float* x_v  = (const float*)d_in[2];
    const int*   lens = (const int*)  d_in[3];
    const float* gam  = (const float*)d_in[4];
    const float* bet  = (const float*)d_in[5];
    const float* Wq   = (const float*)d_in[6];
    const float* bq   = (const float*)d_in[7];
    const float* Wk   = (const float*)d_in[8];
    const float* bk   = (const float*)d_in[9];
    const float* Wv   = (const float*)d_in[10];
    const float* bv   = (const float*)d_in[11];
    const float* Wo   = (const float*)d_in[12];
    const float* bo   = (const float*)d_in[13];

    float* out  = (float*)d_out;                       // (B, S, 1024)
    float* attn = out + (size_t)Bq * Sq * Dm;          // (B, GRP, NKV, S, S)

    float *xnq, *xnk, *xnv, *Qb, *Kb, *Vb, *Ob;
    cudaGetSymbolAddress((void**)&xnq, g_xnq);
    cudaGetSymbolAddress((void**)&xnk, g_xnk);
    cudaGetSymbolAddress((void**)&xnv, g_xnv);
    cudaGetSymbolAddress((void**)&Qb,  g_Q);
    cudaGetSymbolAddress((void**)&Kb,  g_K);
    cudaGetSymbolAddress((void**)&Vb,  g_V);
    cudaGetSymbolAddress((void**)&Ob,  g_O);

    const int M = Bq * Sq;   // 4096

    // 1) LayerNorms
    ln_kernel<<<M, 256>>>(x_q, gam, bet, xnq);
    ln_kernel<<<M, 256>>>(x_k, gam, bet, xnk);
    ln_kernel<<<M, 256>>>(x_v, gam, bet, xnv);

    // 2) Projections (big GEMM for Q; small kernel for K/V since N=256)
    gemm_bias_128<<<dim3(Dm / 128, M / 128), 256>>>(xnq, Wq, bq, Qb, M, NQ * DQh, Dm);
    gemm_bias_kernel<<<dim3((NKV * DQh) / 64, M / 64), 256>>>(xnk, Wk, bk, Kb, M, NKV * DQh, Dm);
    gemm_bias_kernel<<<dim3((NKV * DVh) / 64, M / 64), 256>>>(xnv, Wv, bv, Vb, M, NKV * DVh, Dm);

    // 3) RoPE
    {
        int pq = Bq * Sq * NQ * 32;
        int pk = Bq * Sq * NKV * 32;
        rope_kernel<<<(pq + 255) / 256, 256>>>(Qb, NQ, pq);
        rope_kernel<<<(pk + 255) / 256, 256>>>(Kb, NKV, pk);
    }

    // 4) Attention pass 1 (scores + online softmax stats + O)
    {
        size_t smem = ATTN_SMEM_FLOATS * sizeof(float);
        cudaFuncSetAttribute(attn_kernel, cudaFuncAttributeMaxDynamicSharedMemorySize, (int)smem);
        attn_kernel<<<dim3(Sq / 128, NQ, Bq), 256, smem>>>(lens, attn);
    }

    // 5) Attention pass 2 (normalize probs / zero-fill)
    attn_norm_kernel<<<Bq * GRP * NKV * Sq, 256>>>(lens, attn);

    // 6) Output projection
    gemm_bias_128<<<dim3(Dm / 128, M / 128), 256>>>(Ob, Wo, bo, out, M, Dm, Dm);
}

// round 3
// speedup vs baseline: 1.8176x; 1.6364x over previous
#include <cuda_runtime.h>
#include <cuda_bf16.h>
#include <cmath>

// Problem constants
#define Bq     2
#define Sq     2048
#define Dm     1024
#define NQ     16
#define NKV    4
#define GRP    4
#define DQh    64
#define DVh    64

// Scratch (device globals — no allocation allowed)
__device__ float g_xnq[Bq*Sq*Dm];
__device__ float g_xnk[Bq*Sq*Dm];
__device__ float g_xnv[Bq*Sq*Dm];
__device__ float g_Q  [Bq*Sq*NQ*DQh];
__device__ float g_K  [Bq*Sq*NKV*DQh];
__device__ float g_V  [Bq*Sq*NKV*DVh];
__device__ float g_O  [Bq*Sq*NQ*DVh];
__device__ float g_m  [Bq*NQ*Sq];
__device__ float g_l  [Bq*NQ*Sq];

// tf32 helpers
__device__ __forceinline__ unsigned f2tf(float x) {
    unsigned u;
    asm("cvt.rna.tf32.f32 %0, %1;" : "=r"(u) : "f"(x));
    return u;
}
__device__ __forceinline__ float f2tff(float x) { return __uint_as_float(f2tf(x)); }

#define MMA_TF32(c, a, b)                                                      \
    asm volatile("mma.sync.aligned.m16n8k8.row.col.f32.tf32.tf32.f32 "         \
                 "{%0,%1,%2,%3},{%4,%5,%6,%7},{%8,%9},{%0,%1,%2,%3};"          \
                 : "+f"((c)[0]), "+f"((c)[1]), "+f"((c)[2]), "+f"((c)[3])      \
                 : "r"((a)[0]), "r"((a)[1]), "r"((a)[2]), "r"((a)[3]),         \
                   "r"((b)[0]), "r"((b)[1]))

// ---------------------------------------------------------------------------
// LayerNorm: one block per row of 1024
// ---------------------------------------------------------------------------
__global__ void ln_kernel(const float* __restrict__ x,
                          const float* __restrict__ gamma,
                          const float* __restrict__ beta,
                          float* __restrict__ y)
{
    int row = blockIdx.x;
    int tid = threadIdx.x;
    const float4* xr = (const float4*)(x + (size_t)row * Dm);
    float4 v = xr[tid];
    float s  = v.x + v.y + v.z + v.w;
    float ss = v.x*v.x + v.y*v.y + v.z*v.z + v.w*v.w;
    #pragma unroll
    for (int o = 16; o > 0; o >>= 1) {
        s  += __shfl_down_sync(0xffffffffu, s,  o);
        ss += __shfl_down_sync(0xffffffffu, ss, o);
    }
    __shared__ float as[8], bs[8];
    __shared__ float s_mu, s_inv;
    if ((tid & 31) == 0) { as[tid >> 5] = s; bs[tid >> 5] = ss; }
    __syncthreads();
    if (tid == 0) {
        float S = 0.f, SS = 0.f;
        #pragma unroll
        for (int i = 0; i < 8; i++) { S += as[i]; SS += bs[i]; }
        float mu  = S * (1.0f / Dm);
        float var = SS * (1.0f / Dm) - mu * mu;
        s_mu  = mu;
        s_inv = rsqrtf(var + 1e-5f);
    }
    __syncthreads();
    float mu = s_mu, inv = s_inv;
    float4 g  = ((const float4*)gamma)[tid];
    float4 bb = ((const float4*)beta )[tid];
    float4 o;
    o.x = (v.x - mu) * inv * g.x + bb.x;
    o.y = (v.y - mu) * inv * g.y + bb.y;
    o.z = (v.z - mu) * inv * g.z + bb.z;
    o.w = (v.w - mu) * inv * g.w + bb.w;
    ((float4*)(y + (size_t)row * Dm))[tid] = o;
}

// ---------------------------------------------------------------------------
// tf32 tensor-core GEMM with bias: C[M,N] = A[M,K]@B[K,N] + bias
// 128x128 block, BK=32, 256 threads (8 warps, 2m x 4n grid, warp tile 64x32)
// mma.m16n8k8, double-buffered smem. M%128==0, N%128==0, K%32==0.
// ---------------------------------------------------------------------------
#define G_AS (128*36)
#define G_BS (32*136)
#define GEMM_SMEM ((2*G_AS + 2*G_BS)*4)

__global__ void gemm_tf32(const float* __restrict__ A,
                          const float* __restrict__ B,
                          const float* __restrict__ bias,
                          float* __restrict__ C,
                          int M, int N, int K)
{
    extern __shared__ float smem[];
    float* As = smem;               // [2][128][36]
    float* Bs = smem + 2 * G_AS;    // [2][32][136]

    int tid  = threadIdx.x;
    int lane = tid & 31, wid = tid >> 5;
    int wm = (wid & 1) * 64, wn = (wid >> 1) * 32;
    int l4 = lane >> 2, lk = lane & 3;
    int mb = blockIdx.y * 128, nb = blockIdx.x * 128;

    int ar = tid >> 1, ak = (tid & 1) * 16;
    int bk = tid >> 3, bn = (tid & 7) * 16;
    const float* Ap = A + (size_t)(mb + ar) * K + ak;
    const float* Bp = B + (size_t)bk * N + nb + bn;

    float c[4][4][4];
    #pragma unroll
    for (int mi = 0; mi < 4; mi++)
        #pragma unroll
        for (int nj = 0; nj < 4; nj++)
            #pragma unroll
            for (int q = 0; q < 4; q++) c[mi][nj][q] = 0.f;

    // preload tile 0
    #pragma unroll
    for (int i = 0; i < 4; i++) {
        float4 v = *(const float4*)(Ap + i * 4);
        float4 w; w.x = f2tff(v.x); w.y = f2tff(v.y); w.z = f2tff(v.z); w.w = f2tff(v.w);
        *(float4*)&As[ar * 36 + ak + i * 4] = w;
        float4 u = *(const float4*)(Bp + i * 4);
        float4 z; z.x = f2tff(u.x); z.y = f2tff(u.y); z.z = f2tff(u.z); z.w = f2tff(u.w);
        *(float4*)&Bs[bk * 136 + bn + i * 4] = z;
    }
    __syncthreads();

    int nt = K >> 5;
    for (int t = 0; t < nt; t++) {
        int cur = t & 1, nxt = cur ^ 1;
        float4 pa[4], pb[4];
        bool more = (t + 1 < nt);
        if (more) {
            #pragma unroll
            for (int i = 0; i < 4; i++) {
                pa[i] = *(const float4*)(Ap + (size_t)(t + 1) * 32 + i * 4);
                pb[i] = *(const float4*)(Bp + (size_t)(t + 1) * 32 * N + i * 4);
            }
        }
        const float* Ab = As + cur * G_AS;
        const float* Bb = Bs + cur * G_BS;
        #pragma unroll
        for (int kk = 0; kk < 4; kk++) {
            int k0 = kk * 8;
            unsigned af[4][4], bf[4][2];
            #pragma unroll
            for (int mi = 0; mi < 4; mi++) {
                int r = wm + mi * 16 + l4;
                af[mi][0] = __float_as_uint(Ab[r * 36 + k0 + lk]);
                af[mi][1] = __float_as_uint(Ab[(r + 8) * 36 + k0 + lk]);
                af[mi][2] = __float_as_uint(Ab[r * 36 + k0 + lk + 4]);
                af[mi][3] = __float_as_uint(Ab[(r + 8) * 36 + k0 + lk + 4]);
            }
            #pragma unroll
            for (int nj = 0; nj < 4; nj++) {
                int cc = wn + nj * 8 + l4;
                bf[nj][0] = __float_as_uint(Bb[(k0 + lk) * 136 + cc]);
                bf[nj][1] = __float_as_uint(Bb[(k0 + lk + 4) * 136 + cc]);
            }
            #pragma unroll
            for (int mi = 0; mi < 4; mi++)
                #pragma unroll
                for (int nj = 0; nj < 4; nj++)
                    MMA_TF32(c[mi][nj], af[mi], bf[nj]);
        }
        if (more) {
            float* An = As + nxt * G_AS;
            float* Bn = Bs + nxt * G_BS;
            #pragma unroll
            for (int i = 0; i < 4; i++) {
                float4 w; w.x = f2tff(pa[i].x); w.y = f2tff(pa[i].y);
                w.z = f2tff(pa[i].z); w.w = f2tff(pa[i].w);
                *(float4*)&An[ar * 36 + ak + i * 4] = w;
                float4 z; z.x = f2tff(pb[i].x); z.y = f2tff(pb[i].y);
                z.z = f2tff(pb[i].z); z.w = f2tff(pb[i].w);
                *(float4*)&Bn[bk * 136 + bn + i * 4] = z;
            }
            __syncthreads();
        }
    }

    // epilogue
    #pragma unroll
    for (int nj = 0; nj < 4; nj++) {
        int col = nb + wn + nj * 8 + 2 * lk;
        float2 bj = *(const float2*)&bias[col];
        #pragma unroll
        for (int mi = 0; mi < 4; mi++) {
            int r0 = mb + wm + mi * 16 + l4;
            float2 o0, o1;
            o0.x = c[mi][nj][0] + bj.x; o0.y = c[mi][nj][1] + bj.y;
            o1.x = c[mi][nj][2] + bj.x; o1.y = c[mi][nj][3] + bj.y;
            *(float2*)&C[(size_t)r0 * N + col] = o0;
            *(float2*)&C[(size_t)(r0 + 8) * N + col] = o1;
        }
    }
}

// ---------------------------------------------------------------------------
// RoPE (interleaved pairs), in place.
// ---------------------------------------------------------------------------
__global__ void rope_kernel(float* __restrict__ X, int heads, int total_pairs)
{
    int p = blockIdx.x * blockDim.x + threadIdx.x;
    if (p >= total_pairs) return;
    int i = p & 31;
    int t = (p / (32 * heads)) & (Sq - 1);
    float invf = powf(10000.0f, -((float)(2 * i)) / 64.0f);
    float ang  = (float)t * invf;
    float sn, cs;
    sincosf(ang, &sn, &cs);
    size_t e = (size_t)p * 2;
    float x1 = X[e], x2 = X[e + 1];
    X[e]     = x1 * cs - x2 * sn;
    X[e + 1] = x1 * sn + x2 * cs;
}

// ---------------------------------------------------------------------------
// Attention pass 1 (tensor cores): 128 q-rows per block, 64-wide k tiles.
// QK^T and P@V via tf32 mma; softmax bookkeeping SIMT in smem.
// Writes masked raw scores to attn buffer; stores (m,l); accumulates O.
// ---------------------------------------------------------------------------
#define A_QS (128*68)
#define A_KS (64*72)
#define A_VS (64*72)
#define A_PS (128*68)
#define ATTN_SMEM ((A_QS + A_KS + A_VS + A_PS + 128*3 + 256) * 4)

__global__ void attn_kernel(const int* __restrict__ lens,
                            float* __restrict__ attn)
{
    extern __shared__ float sm[];
    float* Qs   = sm;                        // [128][68] tf32 q (A operand)
    float* Ks   = Qs + A_QS;                 // [64 d][72 n] tf32 k^T (B operand)
    float* Vs   = Ks + A_KS;                 // [64 j][72 d] tf32 v (B operand)
    float* Ps   = Vs + A_VS;                 // [128][68] scores / probs
    float* mrow = Ps + A_PS;                 // [128]
    float* lrow = mrow + 128;
    float* fac  = lrow + 128;
    float* sred = fac + 128;                 // [2][128]

    int tid  = threadIdx.x;
    int lane = tid & 31, wid = tid >> 5;
    int wm = (wid & 1) * 64;                 // warp m offset (0/64)
    int wn = (wid >> 1) * 16;                // warp n offset (0..48)
    int l4 = lane >> 2, lk = lane & 3;

    int mt = blockIdx.x, qh = blockIdx.y, b = blockIdx.z;
    int kvh = qh >> 2;
    int grp = qh & 3;
    int len = lens[b];

    // Load Q tile (128 x 64), row-major, tf32-rounded
    #pragma unroll
    for (int i = 0; i < 8; i++) {
        int lin = tid + i * 256;
        int r = lin >> 4, c4 = (lin & 15) * 4;
        float4 v = *(const float4*)&g_Q[((size_t)(b * Sq + mt * 128 + r)) * (NQ * DQh) + qh * 64 + c4];
        float4 w; w.x = f2tff(v.x); w.y = f2tff(v.y); w.z = f2tff(v.z); w.w = f2tff(v.w);
        *(float4*)&Qs[r * 68 + c4] = w;
    }
    if (tid < 128) { mrow[tid] = -3.0e38f; lrow[tid] = 0.f; }

    float o[4][2][4];
    #pragma unroll
    for (int mi = 0; mi < 4; mi++)
        #pragma unroll
        for (int nj = 0; nj < 2; nj++)
            #pragma unroll
            for (int q = 0; q < 4; q++) o[mi][nj][q] = 0.f;

    int jend = min(2 * mt + 1, (len - 1) >> 6);
    size_t attn_head = (((size_t)(b * GRP + grp)) * NKV + kvh) * Sq;

    for (int jt = 0; jt <= jend; jt++) {
        __syncthreads();
        // Load K (transposed -> Ks[d][j]) and V (direct -> Vs[j][d]), tf32
        #pragma unroll
        for (int i = 0; i < 4; i++) {
            int lin = tid + i * 256;
            int r = lin >> 4, c4 = (lin & 15) * 4;
            size_t gidx = ((size_t)(b * Sq + jt * 64 + r)) * (NKV * DQh) + kvh * 64 + c4;
            float4 kv = *(const float4*)&g_K[gidx];
            Ks[(c4 + 0) * 72 + r] = f2tff(kv.x);
            Ks[(c4 + 1) * 72 + r] = f2tff(kv.y);
            Ks[(c4 + 2) * 72 + r] = f2tff(kv.z);
            Ks[(c4 + 3) * 72 + r] = f2tff(kv.w);
            float4 vv = *(const float4*)&g_V[gidx];
            float4 vw; vw.x = f2tff(vv.x); vw.y = f2tff(vv.y);
            vw.z = f2tff(vv.z); vw.w = f2tff(vv.w);
            *(float4*)&Vs[r * 72 + c4] = vw;
        }
        __syncthreads();

        // S = Q K^T via mma: warp tile 64m x 16n, k(d) loop of 8
        float s[4][2][4];
        #pragma unroll
        for (int mi = 0; mi < 4; mi++)
            #pragma unroll
            for (int nj = 0; nj < 2; nj++)
                #pragma unroll
                for (int q = 0; q < 4; q++) s[mi][nj][q] = 0.f;

        #pragma unroll
        for (int kk = 0; kk < 8; kk++) {
            int k0 = kk * 8;
            unsigned af[4][4], bf[2][2];
            #pragma unroll
            for (int mi = 0; mi < 4; mi++) {
                int r = wm + mi * 16 + l4;
                af[mi][0] = __float_as_uint(Qs[r * 68 + k0 + lk]);
                af[mi][1] = __float_as_uint(Qs[(r + 8) * 68 + k0 + lk]);
                af[mi][2] = __float_as_uint(Qs[r * 68 + k0 + lk + 4]);
                af[mi][3] = __float_as_uint(Qs[(r + 8) * 68 + k0 + lk + 4]);
            }
            #pragma unroll
            for (int nj = 0; nj < 2; nj++) {
                int cc = wn + nj * 8 + l4;
                bf[nj][0] = __float_as_uint(Ks[(k0 + lk) * 72 + cc]);
                bf[nj][1] = __float_as_uint(Ks[(k0 + lk + 4) * 72 + cc]);
            }
            #pragma unroll
            for (int mi = 0; mi < 4; mi++)
                #pragma unroll
                for (int nj = 0; nj < 2; nj++)
                    MMA_TF32(s[mi][nj], af[mi], bf[nj]);
        }

        // scale + mask into Ps
        #pragma unroll
        for (int mi = 0; mi < 4; mi++) {
            int r0 = wm + mi * 16 + l4;
            #pragma unroll
            for (int nj = 0; nj < 2; nj++) {
                int c0 = wn + nj * 8 + 2 * lk;
                int qr0 = mt * 128 + r0, qr1 = qr0 + 8;
                int kc0 = jt * 64 + c0, kc1 = kc0 + 1;
                float v0 = s[mi][nj][0] * 0.125f;
                float v1 = s[mi][nj][1] * 0.125f;
                float v2 = s[mi][nj][2] * 0.125f;
                float v3 = s[mi][nj][3] * 0.125f;
                if (kc0 > qr0 || kc0 >= len) v0 = -1.0e30f;
                if (kc1 > qr0 || kc1 >= len) v1 = -1.0e30f;
                if (kc0 > qr1 || kc0 >= len) v2 = -1.0e30f;
                if (kc1 > qr1 || kc1 >= len) v3 = -1.0e30f;
                Ps[r0 * 68 + c0] = v0;
                Ps[r0 * 68 + c0 + 1] = v1;
                Ps[(r0 + 8) * 68 + c0] = v2;
                Ps[(r0 + 8) * 68 + c0 + 1] = v3;
            }
        }
        __syncthreads();

        // write raw masked scores to gmem (coalesced)
        #pragma unroll
        for (int i = 0; i < 8; i++) {
            int lin = tid + i * 256;
            int r = lin >> 4, c4 = (lin & 15) * 4;
            float4 v = *(const float4*)&Ps[r * 68 + c4];
            *(float4*)&attn[(attn_head + mt * 128 + r) * Sq + jt * 64 + c4] = v;
        }

        // row max (2 threads/row x 32 cols)
        {
            int r = tid & 127, half = tid >> 7;
            float tmax = -3.0e38f;
            #pragma unroll
            for (int k = 0; k < 32; k++)
                tmax = fmaxf(tmax, Ps[r * 68 + half * 32 + k]);
            sred[half * 128 + r] = tmax;
        }
        __syncthreads();
        if (tid < 128) {
            float mn = fmaxf(sred[tid], sred[128 + tid]);
            mn = fmaxf(mn, mrow[tid]);
            fac[tid] = __expf(mrow[tid] - mn);
            mrow[tid] = mn;
        }
        __syncthreads();
        // exponentiate (tf32-round probs) + partial sums
        {
            int r = tid & 127, half = tid >> 7;
            float mn = mrow[r];
            float sum = 0.f;
            #pragma unroll
            for (int k = 0; k < 32; k++) {
                float p = f2tff(__expf(Ps[r * 68 + half * 32 + k] - mn));
                Ps[r * 68 + half * 32 + k] = p;
                sum += p;
            }
            sred[half * 128 + r] = sum;
        }
        __syncthreads();
        if (tid < 128)
            lrow[tid] = lrow[tid] * fac[tid] + (sred[tid] + sred[128 + tid]);
        __syncthreads();

        // rescale O frags by fac, then O += P @ V (warp tile 64m x 16d)
        #pragma unroll
        for (int mi = 0; mi < 4; mi++) {
            int r0 = wm + mi * 16 + l4;
            float f0 = fac[r0], f1 = fac[r0 + 8];
            #pragma unroll
            for (int nj = 0; nj < 2; nj++) {
                o[mi][nj][0] *= f0; o[mi][nj][1] *= f0;
                o[mi][nj][2] *= f1; o[mi][nj][3] *= f1;
            }
        }
        #pragma unroll
        for (int kk = 0; kk < 8; kk++) {
            int k0 = kk * 8;
            unsigned af[4][4], bf[2][2];
            #pragma unroll
            for (int mi = 0; mi < 4; mi++) {
                int r = wm + mi * 16 + l4;
                af[mi][0] = __float_as_uint(Ps[r * 68 + k0 + lk]);
                af[mi][1] = __float_as_uint(Ps[(r + 8) * 68 + k0 + lk]);
                af[mi][2] = __float_as_uint(Ps[r * 68 + k0 + lk + 4]);
                af[mi][3] = __float_as_uint(Ps[(r + 8) * 68 + k0 + lk + 4]);
            }
            #pragma unroll
            for (int nj = 0; nj < 2; nj++) {
                int cc = wn + nj * 8 + l4;
                bf[nj][0] = __float_as_uint(Vs[(k0 + lk) * 72 + cc]);
                bf[nj][1] = __float_as_uint(Vs[(k0 + lk + 4) * 72 + cc]);
            }
            #pragma unroll
            for (int mi = 0; mi < 4; mi++)
                #pragma unroll
                for (int nj = 0; nj < 2; nj++)
                    MMA_TF32(o[mi][nj], af[mi], bf[nj]);
        }
    }
    __syncthreads();

    // epilogue: O /= l ; write O; write stats
    #pragma unroll
    for (int mi = 0; mi < 4; mi++) {
        int r0 = wm + mi * 16 + l4;
        float inv0 = 1.0f / lrow[r0];
        float inv1 = 1.0f / lrow[r0 + 8];
        int gr0 = b * Sq + mt * 128 + r0;
        #pragma unroll
        for (int nj = 0; nj < 2; nj++) {
            int col = qh * 64 + wn + nj * 8 + 2 * lk;
            float2 w0, w1;
            w0.x = o[mi][nj][0] * inv0; w0.y = o[mi][nj][1] * inv0;
            w1.x = o[mi][nj][2] * inv1; w1.y = o[mi][nj][3] * inv1;
            *(float2*)&g_O[(size_t)gr0 * (NQ * DVh) + col] = w0;
            *(float2*)&g_O[(size_t)(gr0 + 8) * (NQ * DVh) + col] = w1;
        }
    }
    if (tid < 128) {
        size_t si = ((size_t)b * NQ + qh) * Sq + mt * 128 + tid;
        g_m[si] = mrow[tid];
        g_l[si] = lrow[tid];
    }
}

// ---------------------------------------------------------------------------
// Attention pass 2: normalize probabilities (and zero the masked region).
// ---------------------------------------------------------------------------
__global__ void attn_norm_kernel(const int* __restrict__ lens,
                                 float* __restrict__ attn)
{
    size_t row = blockIdx.x;
    int t   = (int)(row & (Sq - 1));
    int kvh = (int)((row >> 11) & 3);
    int grp = (int)((row >> 13) & 3);
    int n   = (int)(row >> 15);
    int qh  = kvh * GRP + grp;
    int len = lens[n];
    size_t si = ((size_t)n * NQ + qh) * Sq + t;
    float mn  = g_m[si];
    float inv = 1.0f / g_l[si];
    float* rp = attn + row * (size_t)Sq;
    int lim = min(t, len - 1);
    int c0 = threadIdx.x * 8;
    #pragma unroll
    for (int u = 0; u < 8; u += 4) {
        int c = c0 + u;
        float4 v;
        if (c + 3 <= lim) {
            float4 s4 = *(const float4*)&rp[c];
            v.x = __expf(s4.x - mn) * inv;
            v.y = __expf(s4.y - mn) * inv;
            v.z = __expf(s4.z - mn) * inv;
            v.w = __expf(s4.w - mn) * inv;
        } else {
            v.x = (c + 0 <= lim) ? __expf(rp[c + 0] - mn) * inv : 0.f;
            v.y = (c + 1 <= lim) ? __expf(rp[c + 1] - mn) * inv : 0.f;
            v.z = (c + 2 <= lim) ? __expf(rp[c + 2] - mn) * inv : 0.f;
            v.w = (c + 3 <= lim) ? __expf(rp[c + 3] - mn) * inv : 0.f;
        }
        *(float4*)&rp[c] = v;
    }
}

// ---------------------------------------------------------------------------
// Launch
// ---------------------------------------------------------------------------
extern "C" void kernel_launch(void* const* d_in, const int* in_sizes, int n_in,
                              void* d_out, int out_size)
{
    const float* x_q  = (const float*)d_in[0];
    const float* x_k  = (const float*)d_in[1];
    const float* x_v  = (const float*)d_in[2];
    const int*   lens = (const int*)  d_in[3];
    const float* gam  = (const float*)d_in[4];
    const float* bet  = (const float*)d_in[5];
    const float* Wq   = (const float*)d_in[6];
    const float* bq   = (const float*)d_in[7];
    const float* Wk   = (const float*)d_in[8];
    const float* bk   = (const float*)d_in[9];
    const float* Wv   = (const float*)d_in[10];
    const float* bv   = (const float*)d_in[11];
    const float* Wo   = (const float*)d_in[12];
    const float* bo   = (const float*)d_in[13];

    float* out  = (float*)d_out;                       // (B, S, 1024)
    float* attn = out + (size_t)Bq * Sq * Dm;          // (B, GRP, NKV, S, S)

    float *xnq, *xnk, *xnv, *Qb, *Kb, *Vb, *Ob;
    cudaGetSymbolAddress((void**)&xnq, g_xnq);
    cudaGetSymbolAddress((void**)&xnk, g_xnk);
    cudaGetSymbolAddress((void**)&xnv, g_xnv);
    cudaGetSymbolAddress((void**)&Qb,  g_Q);
    cudaGetSymbolAddress((void**)&Kb,  g_K);
    cudaGetSymbolAddress((void**)&Vb,  g_V);
    cudaGetSymbolAddress((void**)&Ob,  g_O);

    const int M = Bq * Sq;   // 4096

    static bool attr_set = false;
    if (!attr_set) {
        cudaFuncSetAttribute(gemm_tf32, cudaFuncAttributeMaxDynamicSharedMemorySize, GEMM_SMEM);
        cudaFuncSetAttribute(attn_kernel, cudaFuncAttributeMaxDynamicSharedMemorySize, ATTN_SMEM);
        attr_set = true;
    }

    // 1) LayerNorms
    ln_kernel<<<M, 256>>>(x_q, gam, bet, xnq);
    ln_kernel<<<M, 256>>>(x_k, gam, bet, xnk);
    ln_kernel<<<M, 256>>>(x_v, gam, bet, xnv);

    // 2) Projections (tf32 tensor cores)
    gemm_tf32<<<dim3(Dm / 128, M / 128), 256, GEMM_SMEM>>>(xnq, Wq, bq, Qb, M, NQ * DQh, Dm);
    gemm_tf32<<<dim3((NKV * DQh) / 128, M / 128), 256, GEMM_SMEM>>>(xnk, Wk, bk, Kb, M, NKV * DQh, Dm);
    gemm_tf32<<<dim3((NKV * DVh) / 128, M / 128), 256, GEMM_SMEM>>>(xnv, Wv, bv, Vb, M, NKV * DVh, Dm);

    // 3) RoPE
    {
        int pq = Bq * Sq * NQ * 32;
        int pk = Bq * Sq * NKV * 32;
        rope_kernel<<<(pq + 255) / 256, 256>>>(Qb, NQ, pq);
        rope_kernel<<<(pk + 255) / 256, 256>>>(Kb, NKV, pk);
    }

    // 4) Attention pass 1 (tensor cores)
    attn_kernel<<<dim3(Sq / 128, NQ, Bq), 256, ATTN_SMEM>>>(lens, attn);

    // 5) Attention pass 2 (normalize probs / zero-fill)
    attn_norm_kernel<<<Bq * GRP * NKV * Sq, 256>>>(lens, attn);

    // 6) Output projection (tensor cores)
    gemm_tf32<<<dim3(Dm / 128, M / 128), 256, GEMM_SMEM>>>(Ob, Wo, bo, out, M, Dm, Dm);
}

// round 4
// speedup vs baseline: 2.0578x; 1.1321x over previous
#include <cuda_runtime.h>
#include <cuda_bf16.h>
#include <cmath>

// Problem constants
#define Bq     2
#define Sq     2048
#define Dm     1024
#define NQ     16
#define NKV    4
#define GRP    4
#define DQh    64
#define DVh    64

// Scratch (device globals — no allocation allowed)
__device__ float g_xnq[Bq*Sq*Dm];
__device__ float g_xnk[Bq*Sq*Dm];
__device__ float g_xnv[Bq*Sq*Dm];
__device__ float g_Q  [Bq*Sq*NQ*DQh];
__device__ float g_K  [Bq*Sq*NKV*DQh];
__device__ float g_V  [Bq*Sq*NKV*DVh];
__device__ float g_O  [Bq*Sq*NQ*DVh];
__device__ float g_m  [Bq*NQ*Sq];
__device__ float g_l  [Bq*NQ*Sq];

// tf32 helpers
__device__ __forceinline__ unsigned f2tf(float x) {
    unsigned u;
    asm("cvt.rna.tf32.f32 %0, %1;" : "=r"(u) : "f"(x));
    return u;
}
__device__ __forceinline__ float f2tff(float x) { return __uint_as_float(f2tf(x)); }

#define MMA_TF32(c, a, b)                                                      \
    asm volatile("mma.sync.aligned.m16n8k8.row.col.f32.tf32.tf32.f32 "         \
                 "{%0,%1,%2,%3},{%4,%5,%6,%7},{%8,%9},{%0,%1,%2,%3};"          \
                 : "+f"((c)[0]), "+f"((c)[1]), "+f"((c)[2]), "+f"((c)[3])      \
                 : "r"((a)[0]), "r"((a)[1]), "r"((a)[2]), "r"((a)[3]),         \
                   "r"((b)[0]), "r"((b)[1]))

// ldmatrix x4: loads full m16k8 tf32 A-fragment (a0..a3).
// Per-lane address must point at the 16B row:
//   row = r0 + ((lane>>3)&1)*8 + (lane&7), colf32 = k0 + (lane>>4)*4
__device__ __forceinline__ void ldsmx4(unsigned r[4], unsigned saddr) {
    asm volatile("ldmatrix.sync.aligned.m8n8.x4.shared.b16 {%0,%1,%2,%3}, [%4];"
                 : "=r"(r[0]), "=r"(r[1]), "=r"(r[2]), "=r"(r[3])
                 : "r"(saddr));
}
__device__ __forceinline__ unsigned lane_frag_addr(const float* base, int lane,
                                                   int r0, int ldm) {
    const float* p = base + (size_t)(r0 + ((lane >> 3) & 1) * 8 + (lane & 7)) * ldm
                          + (lane >> 4) * 4;
    return (unsigned)__cvta_generic_to_shared(p);
}

// ---------------------------------------------------------------------------
// LayerNorm: one block per row of 1024
// ---------------------------------------------------------------------------
__global__ void ln_kernel(const float* __restrict__ x,
                          const float* __restrict__ gamma,
                          const float* __restrict__ beta,
                          float* __restrict__ y)
{
    int row = blockIdx.x;
    int tid = threadIdx.x;
    const float4* xr = (const float4*)(x + (size_t)row * Dm);
    float4 v = xr[tid];
    float s  = v.x + v.y + v.z + v.w;
    float ss = v.x*v.x + v.y*v.y + v.z*v.z + v.w*v.w;
    #pragma unroll
    for (int o = 16; o > 0; o >>= 1) {
        s  += __shfl_down_sync(0xffffffffu, s,  o);
        ss += __shfl_down_sync(0xffffffffu, ss, o);
    }
    __shared__ float as[8], bs[8];
    __shared__ float s_mu, s_inv;
    if ((tid & 31) == 0) { as[tid >> 5] = s; bs[tid >> 5] = ss; }
    __syncthreads();
    if (tid == 0) {
        float S = 0.f, SS = 0.f;
        #pragma unroll
        for (int i = 0; i < 8; i++) { S += as[i]; SS += bs[i]; }
        float mu  = S * (1.0f / Dm);
        float var = SS * (1.0f / Dm) - mu * mu;
        s_mu  = mu;
        s_inv = rsqrtf(var + 1e-5f);
    }
    __syncthreads();
    float mu = s_mu, inv = s_inv;
    float4 g  = ((const float4*)gamma)[tid];
    float4 bb = ((const float4*)beta )[tid];
    float4 o;
    o.x = (v.x - mu) * inv * g.x + bb.x;
    o.y = (v.y - mu) * inv * g.y + bb.y;
    o.z = (v.z - mu) * inv * g.z + bb.z;
    o.w = (v.w - mu) * inv * g.w + bb.w;
    ((float4*)(y + (size_t)row * Dm))[tid] = o;
}

// ---------------------------------------------------------------------------
// tf32 tensor-core GEMM with bias (device body)
// 128x128 block, BK=32, 256 threads (8 warps, 2m x 4n, warp tile 64x32)
// A-fragments via ldmatrix; double-buffered smem.
// ---------------------------------------------------------------------------
#define G_AS (128*36)
#define G_BS (32*136)
#define GEMM_SMEM ((2*G_AS + 2*G_BS)*4)

__device__ __forceinline__ void gemm_body(const float* __restrict__ A,
                                          const float* __restrict__ B,
                                          const float* __restrict__ bias,
                                          float* __restrict__ C,
                                          int M, int N, int K,
                                          float* smem)
{
    float* As = smem;               // [2][128][36]
    float* Bs = smem + 2 * G_AS;    // [2][32][136]

    int tid  = threadIdx.x;
    int lane = tid & 31, wid = tid >> 5;
    int wm = (wid & 1) * 64, wn = (wid >> 1) * 32;
    int l4 = lane >> 2, lk = lane & 3;
    int mb = blockIdx.y * 128, nb = blockIdx.x * 128;

    int ar = tid >> 1, ak = (tid & 1) * 16;
    int bk = tid >> 3, bn = (tid & 7) * 16;
    const float* Ap = A + (size_t)(mb + ar) * K + ak;
    const float* Bp = B + (size_t)bk * N + nb + bn;

    float c[4][4][4];
    #pragma unroll
    for (int mi = 0; mi < 4; mi++)
        #pragma unroll
        for (int nj = 0; nj < 4; nj++)
            #pragma unroll
            for (int q = 0; q < 4; q++) c[mi][nj][q] = 0.f;

    // preload tile 0
    #pragma unroll
    for (int i = 0; i < 4; i++) {
        float4 v = *(const float4*)(Ap + i * 4);
        float4 w; w.x = f2tff(v.x); w.y = f2tff(v.y); w.z = f2tff(v.z); w.w = f2tff(v.w);
        *(float4*)&As[ar * 36 + ak + i * 4] = w;
        float4 u = *(const float4*)(Bp + i * 4);
        float4 z; z.x = f2tff(u.x); z.y = f2tff(u.y); z.z = f2tff(u.z); z.w = f2tff(u.w);
        *(float4*)&Bs[bk * 136 + bn + i * 4] = z;
    }
    __syncthreads();

    int nt = K >> 5;
    for (int t = 0; t < nt; t++) {
        int cur = t & 1, nxt = cur ^ 1;
        float4 pa[4], pb[4];
        bool more = (t + 1 < nt);
        if (more) {
            #pragma unroll
            for (int i = 0; i < 4; i++) {
                pa[i] = *(const float4*)(Ap + (size_t)(t + 1) * 32 + i * 4);
                pb[i] = *(const float4*)(Bp + (size_t)(t + 1) * 32 * N + i * 4);
            }
        }
        const float* Ab = As + cur * G_AS;
        const float* Bb = Bs + cur * G_BS;
        unsigned a_ptr[4];
        #pragma unroll
        for (int mi = 0; mi < 4; mi++)
            a_ptr[mi] = lane_frag_addr(Ab, lane, wm + mi * 16, 36);

        #pragma unroll
        for (int kk = 0; kk < 4; kk++) {
            int k0 = kk * 8;
            unsigned af[4][4], bf[4][2];
            #pragma unroll
            for (int mi = 0; mi < 4; mi++)
                ldsmx4(af[mi], a_ptr[mi] + kk * 32);
            #pragma unroll
            for (int nj = 0; nj < 4; nj++) {
                int cc = wn + nj * 8 + l4;
                bf[nj][0] = __float_as_uint(Bb[(k0 + lk) * 136 + cc]);
                bf[nj][1] = __float_as_uint(Bb[(k0 + lk + 4) * 136 + cc]);
            }
            #pragma unroll
            for (int mi = 0; mi < 4; mi++)
                #pragma unroll
                for (int nj = 0; nj < 4; nj++)
                    MMA_TF32(c[mi][nj], af[mi], bf[nj]);
        }
        if (more) {
            float* An = As + nxt * G_AS;
            float* Bn = Bs + nxt * G_BS;
            #pragma unroll
            for (int i = 0; i < 4; i++) {
                float4 w; w.x = f2tff(pa[i].x); w.y = f2tff(pa[i].y);
                w.z = f2tff(pa[i].z); w.w = f2tff(pa[i].w);
                *(float4*)&An[ar * 36 + ak + i * 4] = w;
                float4 z; z.x = f2tff(pb[i].x); z.y = f2tff(pb[i].y);
                z.z = f2tff(pb[i].z); z.w = f2tff(pb[i].w);
                *(float4*)&Bn[bk * 136 + bn + i * 4] = z;
            }
            __syncthreads();
        }
    }

    // epilogue
    #pragma unroll
    for (int nj = 0; nj < 4; nj++) {
        int col = nb + wn + nj * 8 + 2 * lk;
        float2 bj = *(const float2*)&bias[col];
        #pragma unroll
        for (int mi = 0; mi < 4; mi++) {
            int r0 = mb + wm + mi * 16 + l4;
            float2 o0, o1;
            o0.x = c[mi][nj][0] + bj.x; o0.y = c[mi][nj][1] + bj.y;
            o1.x = c[mi][nj][2] + bj.x; o1.y = c[mi][nj][3] + bj.y;
            *(float2*)&C[(size_t)r0 * N + col] = o0;
            *(float2*)&C[(size_t)(r0 + 8) * N + col] = o1;
        }
    }
}

__global__ void gemm_tf32(const float* __restrict__ A,
                          const float* __restrict__ B,
                          const float* __restrict__ bias,
                          float* __restrict__ C,
                          int M, int N, int K)
{
    extern __shared__ float smem[];
    gemm_body(A, B, bias, C, M, N, K, smem);
}

// Fused K+V projections: blockIdx.z selects which GEMM.
__global__ void gemm_tf32_kv(const float* __restrict__ Ak,
                             const float* __restrict__ Av,
                             const float* __restrict__ Wk,
                             const float* __restrict__ Wv,
                             const float* __restrict__ bk_,
                             const float* __restrict__ bv_,
                             float* __restrict__ Ck,
                             float* __restrict__ Cv,
                             int M, int N, int K)
{
    extern __shared__ float smem[];
    if (blockIdx.z == 0) gemm_body(Ak, Wk, bk_, Ck, M, N, K, smem);
    else                 gemm_body(Av, Wv, bv_, Cv, M, N, K, smem);
}

// ---------------------------------------------------------------------------
// RoPE (interleaved pairs), in place.
// ---------------------------------------------------------------------------
__global__ void rope_kernel(float* __restrict__ X, int heads, int total_pairs)
{
    int p = blockIdx.x * blockDim.x + threadIdx.x;
    if (p >= total_pairs) return;
    int i = p & 31;
    int t = (p / (32 * heads)) & (Sq - 1);
    float invf = powf(10000.0f, -((float)(2 * i)) / 64.0f);
    float ang  = (float)t * invf;
    float sn, cs;
    sincosf(ang, &sn, &cs);
    size_t e = (size_t)p * 2;
    float x1 = X[e], x2 = X[e + 1];
    X[e]     = x1 * cs - x2 * sn;
    X[e + 1] = x1 * sn + x2 * cs;
}

// ---------------------------------------------------------------------------
// Attention pass 1 (tensor cores + ldmatrix): 128 q-rows/block, 64-wide tiles.
// ---------------------------------------------------------------------------
#define A_QS (128*68)
#define A_KS (64*72)
#define A_VS (64*72)
#define A_PS (128*68)
#define ATTN_SMEM ((A_QS + A_KS + A_VS + A_PS + 128*3 + 256) * 4)

__global__ void attn_kernel(const int* __restrict__ lens,
                            float* __restrict__ attn)
{
    extern __shared__ float sm[];
    float* Qs   = sm;                        // [128][68] tf32 q (A operand)
    float* Ks   = Qs + A_QS;                 // [64 d][72 n] tf32 k^T (B operand)
    float* Vs   = Ks + A_KS;                 // [64 j][72 d] tf32 v (B operand)
    float* Ps   = Vs + A_VS;                 // [128][68] scores / probs
    float* mrow = Ps + A_PS;                 // [128]
    float* lrow = mrow + 128;
    float* fac  = lrow + 128;
    float* sred = fac + 128;                 // [2][128]

    int tid  = threadIdx.x;
    int lane = tid & 31, wid = tid >> 5;
    int wm = (wid & 1) * 64;                 // warp m offset (0/64)
    int wn = (wid >> 1) * 16;                // warp n offset (0..48)
    int l4 = lane >> 2, lk = lane & 3;

    int mt = blockIdx.x, qh = blockIdx.y, b = blockIdx.z;
    int kvh = qh >> 2;
    int grp = qh & 3;
    int len = lens[b];

    // Load Q tile (128 x 64), row-major, tf32-rounded
    #pragma unroll
    for (int i = 0; i < 8; i++) {
        int lin = tid + i * 256;
        int r = lin >> 4, c4 = (lin & 15) * 4;
        float4 v = *(const float4*)&g_Q[((size_t)(b * Sq + mt * 128 + r)) * (NQ * DQh) + qh * 64 + c4];
        float4 w; w.x = f2tff(v.x); w.y = f2tff(v.y); w.z = f2tff(v.z); w.w = f2tff(v.w);
        *(float4*)&Qs[r * 68 + c4] = w;
    }
    if (tid < 128) { mrow[tid] = -3.0e38f; lrow[tid] = 0.f; }

    // fragment ldmatrix lane-pointers (fixed all iterations)
    unsigned q_ptr[4], p_ptr[4];
    #pragma unroll
    for (int mi = 0; mi < 4; mi++) {
        q_ptr[mi] = lane_frag_addr(Qs, lane, wm + mi * 16, 68);
        p_ptr[mi] = lane_frag_addr(Ps, lane, wm + mi * 16, 68);
    }

    float o[4][2][4];
    #pragma unroll
    for (int mi = 0; mi < 4; mi++)
        #pragma unroll
        for (int nj = 0; nj < 2; nj++)
            #pragma unroll
            for (int q = 0; q < 4; q++) o[mi][nj][q] = 0.f;

    int jend = min(2 * mt + 1, (len - 1) >> 6);
    size_t attn_head = (((size_t)(b * GRP + grp)) * NKV + kvh) * Sq;

    for (int jt = 0; jt <= jend; jt++) {
        __syncthreads();
        // Load K (transposed -> Ks[d][j]) and V (direct -> Vs[j][d]), tf32
        #pragma unroll
        for (int i = 0; i < 4; i++) {
            int lin = tid + i * 256;
            int r = lin >> 4, c4 = (lin & 15) * 4;
            size_t gidx = ((size_t)(b * Sq + jt * 64 + r)) * (NKV * DQh) + kvh * 64 + c4;
            float4 kv = *(const float4*)&g_K[gidx];
            Ks[(c4 + 0) * 72 + r] = f2tff(kv.x);
            Ks[(c4 + 1) * 72 + r] = f2tff(kv.y);
            Ks[(c4 + 2) * 72 + r] = f2tff(kv.z);
            Ks[(c4 + 3) * 72 + r] = f2tff(kv.w);
            float4 vv = *(const float4*)&g_V[gidx];
            float4 vw; vw.x = f2tff(vv.x); vw.y = f2tff(vv.y);
            vw.z = f2tff(vv.z); vw.w = f2tff(vv.w);
            *(float4*)&Vs[r * 72 + c4] = vw;
        }
        __syncthreads();

        // S = Q K^T via mma: warp tile 64m x 16n, k(d) loop of 8
        float s[4][2][4];
        #pragma unroll
        for (int mi = 0; mi < 4; mi++)
            #pragma unroll
            for (int nj = 0; nj < 2; nj++)
                #pragma unroll
                for (int q = 0; q < 4; q++) s[mi][nj][q] = 0.f;

        #pragma unroll
        for (int kk = 0; kk < 8; kk++) {
            int k0 = kk * 8;
            unsigned af[4][4], bf[2][2];
            #pragma unroll
            for (int mi = 0; mi < 4; mi++)
                ldsmx4(af[mi], q_ptr[mi] + kk * 32);
            #pragma unroll
            for (int nj = 0; nj < 2; nj++) {
                int cc = wn + nj * 8 + l4;
                bf[nj][0] = __float_as_uint(Ks[(k0 + lk) * 72 + cc]);
                bf[nj][1] = __float_as_uint(Ks[(k0 + lk + 4) * 72 + cc]);
            }
            #pragma unroll
            for (int mi = 0; mi < 4; mi++)
                #pragma unroll
                for (int nj = 0; nj < 2; nj++)
                    MMA_TF32(s[mi][nj], af[mi], bf[nj]);
        }

        // scale + mask into Ps
        #pragma unroll
        for (int mi = 0; mi < 4; mi++) {
            int r0 = wm + mi * 16 + l4;
            #pragma unroll
            for (int nj = 0; nj < 2; nj++) {
                int c0 = wn + nj * 8 + 2 * lk;
                int qr0 = mt * 128 + r0, qr1 = qr0 + 8;
                int kc0 = jt * 64 + c0, kc1 = kc0 + 1;
                float v0 = s[mi][nj][0] * 0.125f;
                float v1 = s[mi][nj][1] * 0.125f;
                float v2 = s[mi][nj][2] * 0.125f;
                float v3 = s[mi][nj][3] * 0.125f;
                if (kc0 > qr0 || kc0 >= len) v0 = -1.0e30f;
                if (kc1 > qr0 || kc1 >= len) v1 = -1.0e30f;
                if (kc0 > qr1 || kc0 >= len) v2 = -1.0e30f;
                if (kc1 > qr1 || kc1 >= len) v3 = -1.0e30f;
                Ps[r0 * 68 + c0] = v0;
                Ps[r0 * 68 + c0 + 1] = v1;
                Ps[(r0 + 8) * 68 + c0] = v2;
                Ps[(r0 + 8) * 68 + c0 + 1] = v3;
            }
        }
        __syncthreads();

        // write raw masked scores to gmem (coalesced)
        #pragma unroll
        for (int i = 0; i < 8; i++) {
            int lin = tid + i * 256;
            int r = lin >> 4, c4 = (lin & 15) * 4;
            float4 v = *(const float4*)&Ps[r * 68 + c4];
            *(float4*)&attn[(attn_head + mt * 128 + r) * Sq + jt * 64 + c4] = v;
        }

        // row max (2 threads/row x 32 cols)
        {
            int r = tid & 127, half = tid >> 7;
            float tmax = -3.0e38f;
            #pragma unroll
            for (int k = 0; k < 32; k++)
                tmax = fmaxf(tmax, Ps[r * 68 + half * 32 + k]);
            sred[half * 128 + r] = tmax;
        }
        __syncthreads();
        if (tid < 128) {
            float mn = fmaxf(sred[tid], sred[128 + tid]);
            mn = fmaxf(mn, mrow[tid]);
            fac[tid] = __expf(mrow[tid] - mn);
            mrow[tid] = mn;
        }
        __syncthreads();
        // exponentiate (tf32-round probs) + partial sums
        {
            int r = tid & 127, half = tid >> 7;
            float mn = mrow[r];
            float sum = 0.f;
            #pragma unroll
            for (int k = 0; k < 32; k++) {
                float p = f2tff(__expf(Ps[r * 68 + half * 32 + k] - mn));
                Ps[r * 68 + half * 32 + k] = p;
                sum += p;
            }
            sred[half * 128 + r] = sum;
        }
        __syncthreads();
        if (tid < 128)
            lrow[tid] = lrow[tid] * fac[tid] + (sred[tid] + sred[128 + tid]);
        __syncthreads();

        // rescale O frags by fac, then O += P @ V (warp tile 64m x 16d)
        #pragma unroll
        for (int mi = 0; mi < 4; mi++) {
            int r0 = wm + mi * 16 + l4;
            float f0 = fac[r0], f1 = fac[r0 + 8];
            #pragma unroll
            for (int nj = 0; nj < 2; nj++) {
                o[mi][nj][0] *= f0; o[mi][nj][1] *= f0;
                o[mi][nj][2] *= f1; o[mi][nj][3] *= f1;
            }
        }
        #pragma unroll
        for (int kk = 0; kk < 8; kk++) {
            int k0 = kk * 8;
            unsigned af[4][4], bf[2][2];
            #pragma unroll
            for (int mi = 0; mi < 4; mi++)
                ldsmx4(af[mi], p_ptr[mi] + kk * 32);
            #pragma unroll
            for (int nj = 0; nj < 2; nj++) {
                int cc = wn + nj * 8 + l4;
                bf[nj][0] = __float_as_uint(Vs[(k0 + lk) * 72 + cc]);
                bf[nj][1] = __float_as_uint(Vs[(k0 + lk + 4) * 72 + cc]);
            }
            #pragma unroll
            for (int mi = 0; mi < 4; mi++)
                #pragma unroll
                for (int nj = 0; nj < 2; nj++)
                    MMA_TF32(o[mi][nj], af[mi], bf[nj]);
        }
    }
    __syncthreads();

    // epilogue: O /= l ; write O; write stats
    #pragma unroll
    for (int mi = 0; mi < 4; mi++) {
        int r0 = wm + mi * 16 + l4;
        float inv0 = 1.0f / lrow[r0];
        float inv1 = 1.0f / lrow[r0 + 8];
        int gr0 = b * Sq + mt * 128 + r0;
        #pragma unroll
        for (int nj = 0; nj < 2; nj++) {
            int col = qh * 64 + wn + nj * 8 + 2 * lk;
            float2 w0, w1;
            w0.x = o[mi][nj][0] * inv0; w0.y = o[mi][nj][1] * inv0;
            w1.x = o[mi][nj][2] * inv1; w1.y = o[mi][nj][3] * inv1;
            *(float2*)&g_O[(size_t)gr0 * (NQ * DVh) + col] = w0;
            *(float2*)&g_O[(size_t)(gr0 + 8) * (NQ * DVh) + col] = w1;
        }
    }
    if (tid < 128) {
        size_t si = ((size_t)b * NQ + qh) * Sq + mt * 128 + tid;
        g_m[si] = mrow[tid];
        g_l[si] = lrow[tid];
    }
}

// ---------------------------------------------------------------------------
// Attention pass 2: normalize probabilities (and zero the masked region).
// ---------------------------------------------------------------------------
__global__ void attn_norm_kernel(const int* __restrict__ lens,
                                 float* __restrict__ attn)
{
    size_t row = blockIdx.x;
    int t   = (int)(row & (Sq - 1));
    int kvh = (int)((row >> 11) & 3);
    int grp = (int)((row >> 13) & 3);
    int n   = (int)(row >> 15);
    int qh  = kvh * GRP + grp;
    int len = lens[n];
    size_t si = ((size_t)n * NQ + qh) * Sq + t;
    float mn  = g_m[si];
    float inv = 1.0f / g_l[si];
    float* rp = attn + row * (size_t)Sq;
    int lim = min(t, len - 1);
    int c0 = threadIdx.x * 8;
    #pragma unroll
    for (int u = 0; u < 8; u += 4) {
        int c = c0 + u;
        float4 v;
        if (c + 3 <= lim) {
            float4 s4 = *(const float4*)&rp[c];
            v.x = __expf(s4.x - mn) * inv;
            v.y = __expf(s4.y - mn) * inv;
            v.z = __expf(s4.z - mn) * inv;
            v.w = __expf(s4.w - mn) * inv;
        } else {
            v.x = (c + 0 <= lim) ? __expf(rp[c + 0] - mn) * inv : 0.f;
            v.y = (c + 1 <= lim) ? __expf(rp[c + 1] - mn) * inv : 0.f;
            v.z = (c + 2 <= lim) ? __expf(rp[c + 2] - mn) * inv : 0.f;
            v.w = (c + 3 <= lim) ? __expf(rp[c + 3] - mn) * inv : 0.f;
        }
        *(float4*)&rp[c] = v;
    }
}

// ---------------------------------------------------------------------------
// Launch
// ---------------------------------------------------------------------------
extern "C" void kernel_launch(void* const* d_in, const int* in_sizes, int n_in,
                              void* d_out, int out_size)
{
    const float* x_q  = (const float*)d_in[0];
    const float* x_k  = (const float*)d_in[1];
    const float* x_v  = (const float*)d_in[2];
    const int*   lens = (const int*)  d_in[3];
    const float* gam  = (const float*)d_in[4];
    const float* bet  = (const float*)d_in[5];
    const float* Wq   = (const float*)d_in[6];
    const float* bq   = (const float*)d_in[7];
    const float* Wk   = (const float*)d_in[8];
    const float* bk   = (const float*)d_in[9];
    const float* Wv   = (const float*)d_in[10];
    const float* bv   = (const float*)d_in[11];
    const float* Wo   = (const float*)d_in[12];
    const float* bo   = (const float*)d_in[13];

    float* out  = (float*)d_out;                       // (B, S, 1024)
    float* attn = out + (size_t)Bq * Sq * Dm;          // (B, GRP, NKV, S, S)

    float *xnq, *xnk, *xnv, *Qb, *Kb, *Vb, *Ob;
    cudaGetSymbolAddress((void**)&xnq, g_xnq);
    cudaGetSymbolAddress((void**)&xnk, g_xnk);
    cudaGetSymbolAddress((void**)&xnv, g_xnv);
    cudaGetSymbolAddress((void**)&Qb,  g_Q);
    cudaGetSymbolAddress((void**)&Kb,  g_K);
    cudaGetSymbolAddress((void**)&Vb,  g_V);
    cudaGetSymbolAddress((void**)&Ob,  g_O);

    const int M = Bq * Sq;   // 4096

    static bool attr_set = false;
    if (!attr_set) {
        cudaFuncSetAttribute(gemm_tf32, cudaFuncAttributeMaxDynamicSharedMemorySize, GEMM_SMEM);
        cudaFuncSetAttribute(gemm_tf32_kv, cudaFuncAttributeMaxDynamicSharedMemorySize, GEMM_SMEM);
        cudaFuncSetAttribute(attn_kernel, cudaFuncAttributeMaxDynamicSharedMemorySize, ATTN_SMEM);
        attr_set = true;
    }

    // 1) LayerNorms
    ln_kernel<<<M, 256>>>(x_q, gam, bet, xnq);
    ln_kernel<<<M, 256>>>(x_k, gam, bet, xnk);
    ln_kernel<<<M, 256>>>(x_v, gam, bet, xnv);

    // 2) Projections (tf32 tensor cores); K+V fused in one launch
    gemm_tf32<<<dim3(Dm / 128, M / 128), 256, GEMM_SMEM>>>(xnq, Wq, bq, Qb, M, NQ * DQh, Dm);
    gemm_tf32_kv<<<dim3((NKV * DQh) / 128, M / 128, 2), 256, GEMM_SMEM>>>(
        xnk, xnv, Wk, Wv, bk, bv, Kb, Vb, M, NKV * DQh, Dm);

    // 3) RoPE
    {
        int pq = Bq * Sq * NQ * 32;
        int pk = Bq * Sq * NKV * 32;
        rope_kernel<<<(pq + 255) / 256, 256>>>(Qb, NQ, pq);
        rope_kernel<<<(pk + 255) / 256, 256>>>(Kb, NKV, pk);
    }

    // 4) Attention pass 1 (tensor cores + ldmatrix)
    attn_kernel<<<dim3(Sq / 128, NQ, Bq), 256, ATTN_SMEM>>>(lens, attn);

    // 5) Attention pass 2 (normalize probs / zero-fill)
    attn_norm_kernel<<<Bq * GRP * NKV * Sq, 256>>>(lens, attn);

    // 6) Output projection (tensor cores)
    gemm_tf32<<<dim3(Dm / 128, M / 128), 256, GEMM_SMEM>>>(Ob, Wo, bo, out, M, Dm, Dm);
}

// round 5
// speedup vs baseline: 2.3834x; 1.1582x over previous
#include <cuda_runtime.h>
#include <cuda_bf16.h>
#include <cmath>

// Problem constants
#define Bq     2
#define Sq     2048
#define Dm     1024
#define NQ     16
#define NKV    4
#define GRP    4
#define DQh    64
#define DVh    64

// Scratch (device globals — no allocation allowed)
__device__ float g_xnq[Bq*Sq*Dm];
__device__ float g_xnk[Bq*Sq*Dm];
__device__ float g_xnv[Bq*Sq*Dm];
__device__ float g_Q  [Bq*Sq*NQ*DQh];
__device__ float g_K  [Bq*Sq*NKV*DQh];
__device__ float g_V  [Bq*Sq*NKV*DVh];
__device__ float g_O  [Bq*Sq*NQ*DVh];
__device__ float g_m  [Bq*NQ*Sq];
__device__ float g_l  [Bq*NQ*Sq];

// tf32 helpers
__device__ __forceinline__ unsigned f2tf(float x) {
    unsigned u;
    asm("cvt.rna.tf32.f32 %0, %1;" : "=r"(u) : "f"(x));
    return u;
}
__device__ __forceinline__ float f2tff(float x) { return __uint_as_float(f2tf(x)); }

#define MMA_TF32(c, a, b)                                                      \
    asm volatile("mma.sync.aligned.m16n8k8.row.col.f32.tf32.tf32.f32 "         \
                 "{%0,%1,%2,%3},{%4,%5,%6,%7},{%8,%9},{%0,%1,%2,%3};"          \
                 : "+f"((c)[0]), "+f"((c)[1]), "+f"((c)[2]), "+f"((c)[3])      \
                 : "r"((a)[0]), "r"((a)[1]), "r"((a)[2]), "r"((a)[3]),         \
                   "r"((b)[0]), "r"((b)[1]))

__device__ __forceinline__ void ldsmx4(unsigned r[4], unsigned saddr) {
    asm volatile("ldmatrix.sync.aligned.m8n8.x4.shared.b16 {%0,%1,%2,%3}, [%4];"
                 : "=r"(r[0]), "=r"(r[1]), "=r"(r[2]), "=r"(r[3])
                 : "r"(saddr));
}
__device__ __forceinline__ unsigned lane_frag_addr(const float* base, int lane,
                                                   int r0, int ldm) {
    const float* p = base + (size_t)(r0 + ((lane >> 3) & 1) * 8 + (lane & 7)) * ldm
                          + (lane >> 4) * 4;
    return (unsigned)__cvta_generic_to_shared(p);
}

// ---------------------------------------------------------------------------
// Fused LayerNorm x3: grid (rows, 3); blockIdx.y selects tensor
// ---------------------------------------------------------------------------
__global__ void ln3_kernel(const float* __restrict__ xq,
                           const float* __restrict__ xk,
                           const float* __restrict__ xv,
                           const float* __restrict__ gamma,
                           const float* __restrict__ beta,
                           float* __restrict__ yq,
                           float* __restrict__ yk,
                           float* __restrict__ yv)
{
    int row = blockIdx.x;
    int which = blockIdx.y;
    const float* x = (which == 0) ? xq : (which == 1) ? xk : xv;
    float* y       = (which == 0) ? yq : (which == 1) ? yk : yv;
    int tid = threadIdx.x;
    const float4* xr = (const float4*)(x + (size_t)row * Dm);
    float4 v = xr[tid];
    float s  = v.x + v.y + v.z + v.w;
    float ss = v.x*v.x + v.y*v.y + v.z*v.z + v.w*v.w;
    #pragma unroll
    for (int o = 16; o > 0; o >>= 1) {
        s  += __shfl_down_sync(0xffffffffu, s,  o);
        ss += __shfl_down_sync(0xffffffffu, ss, o);
    }
    __shared__ float as[8], bs[8];
    __shared__ float s_mu, s_inv;
    if ((tid & 31) == 0) { as[tid >> 5] = s; bs[tid >> 5] = ss; }
    __syncthreads();
    if (tid == 0) {
        float S = 0.f, SS = 0.f;
        #pragma unroll
        for (int i = 0; i < 8; i++) { S += as[i]; SS += bs[i]; }
        float mu  = S * (1.0f / Dm);
        float var = SS * (1.0f / Dm) - mu * mu;
        s_mu  = mu;
        s_inv = rsqrtf(var + 1e-5f);
    }
    __syncthreads();
    float mu = s_mu, inv = s_inv;
    float4 g  = ((const float4*)gamma)[tid];
    float4 bb = ((const float4*)beta )[tid];
    float4 o;
    o.x = (v.x - mu) * inv * g.x + bb.x;
    o.y = (v.y - mu) * inv * g.y + bb.y;
    o.z = (v.z - mu) * inv * g.z + bb.z;
    o.w = (v.w - mu) * inv * g.w + bb.w;
    ((float4*)(y + (size_t)row * Dm))[tid] = o;
}

// ---------------------------------------------------------------------------
// tf32 tensor-core GEMM with bias: 128x256 block, BK=16, 8 warps of 64x64.
// Requires M%128==0, N%256==0, K%16==0.
// ---------------------------------------------------------------------------
#define G_AS (128*20)
#define G_BS (16*264)
#define GEMM_SMEM ((2*G_AS + 2*G_BS)*4)

__device__ __forceinline__ void gemm_body(const float* __restrict__ A,
                                          const float* __restrict__ B,
                                          const float* __restrict__ bias,
                                          float* __restrict__ C,
                                          int M, int N, int K,
                                          float* smem)
{
    float* As = smem;               // [2][128][20]
    float* Bs = smem + 2 * G_AS;    // [2][16][264]

    int tid  = threadIdx.x;
    int lane = tid & 31, wid = tid >> 5;
    int wm = (wid & 1) * 64, wn = (wid >> 1) * 64;
    int l4 = lane >> 2, lk = lane & 3;
    int mb = blockIdx.y * 128, nb = blockIdx.x * 256;

    int ar = tid >> 1, ak = (tid & 1) * 8;
    int bk = tid >> 4, bn = (tid & 15) * 4;
    const float* Ap = A + (size_t)(mb + ar) * K + ak;
    const float* Bp = B + (size_t)bk * N + nb + bn;

    float c[4][8][4];
    #pragma unroll
    for (int mi = 0; mi < 4; mi++)
        #pragma unroll
        for (int nj = 0; nj < 8; nj++)
            #pragma unroll
            for (int q = 0; q < 4; q++) c[mi][nj][q] = 0.f;

    // preload tile 0
    #pragma unroll
    for (int i = 0; i < 2; i++) {
        float4 v = *(const float4*)(Ap + i * 4);
        float4 w; w.x = f2tff(v.x); w.y = f2tff(v.y); w.z = f2tff(v.z); w.w = f2tff(v.w);
        *(float4*)&As[ar * 20 + ak + i * 4] = w;
    }
    #pragma unroll
    for (int i = 0; i < 4; i++) {
        float4 u = *(const float4*)(Bp + i * 64);
        float4 z; z.x = f2tff(u.x); z.y = f2tff(u.y); z.z = f2tff(u.z); z.w = f2tff(u.w);
        *(float4*)&Bs[bk * 264 + bn + i * 64] = z;
    }
    __syncthreads();

    int nt = K >> 4;
    for (int t = 0; t < nt; t++) {
        int cur = t & 1, nxt = cur ^ 1;
        float4 pa[2], pb[4];
        bool more = (t + 1 < nt);
        if (more) {
            #pragma unroll
            for (int i = 0; i < 2; i++)
                pa[i] = *(const float4*)(Ap + (size_t)(t + 1) * 16 + i * 4);
            #pragma unroll
            for (int i = 0; i < 4; i++)
                pb[i] = *(const float4*)(Bp + (size_t)(t + 1) * 16 * N + i * 64);
        }
        const float* Ab = As + cur * G_AS;
        const float* Bb = Bs + cur * G_BS;
        unsigned a_ptr[4];
        #pragma unroll
        for (int mi = 0; mi < 4; mi++)
            a_ptr[mi] = lane_frag_addr(Ab, lane, wm + mi * 16, 20);

        #pragma unroll
        for (int kk = 0; kk < 2; kk++) {
            int k0 = kk * 8;
            unsigned af[4][4], bf[8][2];
            #pragma unroll
            for (int mi = 0; mi < 4; mi++)
                ldsmx4(af[mi], a_ptr[mi] + kk * 32);
            #pragma unroll
            for (int nj = 0; nj < 8; nj++) {
                int cc = wn + nj * 8 + l4;
                bf[nj][0] = __float_as_uint(Bb[(k0 + lk) * 264 + cc]);
                bf[nj][1] = __float_as_uint(Bb[(k0 + lk + 4) * 264 + cc]);
            }
            #pragma unroll
            for (int mi = 0; mi < 4; mi++)
                #pragma unroll
                for (int nj = 0; nj < 8; nj++)
                    MMA_TF32(c[mi][nj], af[mi], bf[nj]);
        }
        if (more) {
            float* An = As + nxt * G_AS;
            float* Bn = Bs + nxt * G_BS;
            #pragma unroll
            for (int i = 0; i < 2; i++) {
                float4 w; w.x = f2tff(pa[i].x); w.y = f2tff(pa[i].y);
                w.z = f2tff(pa[i].z); w.w = f2tff(pa[i].w);
                *(float4*)&An[ar * 20 + ak + i * 4] = w;
            }
            #pragma unroll
            for (int i = 0; i < 4; i++) {
                float4 z; z.x = f2tff(pb[i].x); z.y = f2tff(pb[i].y);
                z.z = f2tff(pb[i].z); z.w = f2tff(pb[i].w);
                *(float4*)&Bn[bk * 264 + bn + i * 64] = z;
            }
            __syncthreads();
        }
    }

    // epilogue
    #pragma unroll
    for (int nj = 0; nj < 8; nj++) {
        int col = nb + wn + nj * 8 + 2 * lk;
        float2 bj = *(const float2*)&bias[col];
        #pragma unroll
        for (int mi = 0; mi < 4; mi++) {
            int r0 = mb + wm + mi * 16 + l4;
            float2 o0, o1;
            o0.x = c[mi][nj][0] + bj.x; o0.y = c[mi][nj][1] + bj.y;
            o1.x = c[mi][nj][2] + bj.x; o1.y = c[mi][nj][3] + bj.y;
            *(float2*)&C[(size_t)r0 * N + col] = o0;
            *(float2*)&C[(size_t)(r0 + 8) * N + col] = o1;
        }
    }
}

__global__ void __launch_bounds__(256, 1)
gemm_tf32(const float* __restrict__ A, const float* __restrict__ B,
          const float* __restrict__ bias, float* __restrict__ C,
          int M, int N, int K)
{
    extern __shared__ float smem[];
    gemm_body(A, B, bias, C, M, N, K, smem);
}

__global__ void __launch_bounds__(256, 1)
gemm_tf32_kv(const float* __restrict__ Ak, const float* __restrict__ Av,
             const float* __restrict__ Wk, const float* __restrict__ Wv,
             const float* __restrict__ bk_, const float* __restrict__ bv_,
             float* __restrict__ Ck, float* __restrict__ Cv,
             int M, int N, int K)
{
    extern __shared__ float smem[];
    if (blockIdx.z == 0) gemm_body(Ak, Wk, bk_, Ck, M, N, K, smem);
    else                 gemm_body(Av, Wv, bv_, Cv, M, N, K, smem);
}

// ---------------------------------------------------------------------------
// RoPE (interleaved pairs), in place.
// ---------------------------------------------------------------------------
__global__ void rope_kernel(float* __restrict__ X, int heads, int total_pairs)
{
    int p = blockIdx.x * blockDim.x + threadIdx.x;
    if (p >= total_pairs) return;
    int i = p & 31;
    int t = (p / (32 * heads)) & (Sq - 1);
    float invf = powf(10000.0f, -((float)(2 * i)) / 64.0f);
    float ang  = (float)t * invf;
    float sn, cs;
    sincosf(ang, &sn, &cs);
    size_t e = (size_t)p * 2;
    float x1 = X[e], x2 = X[e + 1];
    X[e]     = x1 * cs - x2 * sn;
    X[e + 1] = x1 * sn + x2 * cs;
}

// ---------------------------------------------------------------------------
// Attention pass 1: 128 q-rows/block, 128-wide k tiles.
// Warps: 4m x 2n. QK warp tile 32x64; PV warp tile 32x32.
// K, V stored in natural [j][d] layout (conflict-free for B fragments).
// ---------------------------------------------------------------------------
#define A_QS (128*68)
#define A_KS (128*68)
#define A_VS (128*72)
#define A_PS (128*132)
#define ATTN_SMEM ((A_QS + A_KS + A_VS + A_PS + 128*3 + 256) * 4)

__global__ void __launch_bounds__(256, 1)
attn_kernel(const int* __restrict__ lens, float* __restrict__ attn)
{
    extern __shared__ float sm[];
    float* Qs   = sm;                        // [128 m][68]  (A operand, LDSM)
    float* Ks   = Qs + A_QS;                 // [128 j][68]  natural
    float* Vs   = Ks + A_KS;                 // [128 j][72]  natural
    float* Ps   = Vs + A_VS;                 // [128 m][132] scores / probs
    float* mrow = Ps + A_PS;                 // [128]
    float* lrow = mrow + 128;
    float* fac  = lrow + 128;
    float* sred = fac + 128;                 // [2][128]

    int tid  = threadIdx.x;
    int lane = tid & 31, wid = tid >> 5;
    int wm = (wid >> 1) * 32;                // warp m offset (0..96)
    int wn = (wid & 1) * 64;                 // QK: warp n offset (0/64)
    int wd = (wid & 1) * 32;                 // PV: warp d offset (0/32)
    int l4 = lane >> 2, lk = lane & 3;

    int mt = blockIdx.x, qh = blockIdx.y, b = blockIdx.z;
    int kvh = qh >> 2;
    int grp = qh & 3;
    int len = lens[b];

    // Load Q tile (128 x 64), tf32-rounded
    #pragma unroll
    for (int i = 0; i < 8; i++) {
        int lin = tid + i * 256;
        int r = lin >> 4, c4 = (lin & 15) * 4;
        float4 v = *(const float4*)&g_Q[((size_t)(b * Sq + mt * 128 + r)) * (NQ * DQh) + qh * 64 + c4];
        float4 w; w.x = f2tff(v.x); w.y = f2tff(v.y); w.z = f2tff(v.z); w.w = f2tff(v.w);
        *(float4*)&Qs[r * 68 + c4] = w;
    }
    if (tid < 128) { mrow[tid] = -3.0e38f; lrow[tid] = 0.f; }

    unsigned q_ptr[2], p_ptr[2];
    #pragma unroll
    for (int mi = 0; mi < 2; mi++) {
        q_ptr[mi] = lane_frag_addr(Qs, lane, wm + mi * 16, 68);
        p_ptr[mi] = lane_frag_addr(Ps, lane, wm + mi * 16, 132);
    }

    float o[2][4][4];
    #pragma unroll
    for (int mi = 0; mi < 2; mi++)
        #pragma unroll
        for (int nj = 0; nj < 4; nj++)
            #pragma unroll
            for (int q = 0; q < 4; q++) o[mi][nj][q] = 0.f;

    int jend = min(mt, (len - 1) >> 7);
    size_t attn_head = (((size_t)(b * GRP + grp)) * NKV + kvh) * Sq;

    for (int jt = 0; jt <= jend; jt++) {
        __syncthreads();
        // Load K and V (128 x 64 each), natural layout, tf32
        #pragma unroll
        for (int i = 0; i < 8; i++) {
            int lin = tid + i * 256;
            int r = lin >> 4, c4 = (lin & 15) * 4;
            size_t gidx = ((size_t)(b * Sq + jt * 128 + r)) * (NKV * DQh) + kvh * 64 + c4;
            float4 kv = *(const float4*)&g_K[gidx];
            float4 kw; kw.x = f2tff(kv.x); kw.y = f2tff(kv.y);
            kw.z = f2tff(kv.z); kw.w = f2tff(kv.w);
            *(float4*)&Ks[r * 68 + c4] = kw;
            float4 vv = *(const float4*)&g_V[gidx];
            float4 vw; vw.x = f2tff(vv.x); vw.y = f2tff(vv.y);
            vw.z = f2tff(vv.z); vw.w = f2tff(vv.w);
            *(float4*)&Vs[r * 72 + c4] = vw;
        }
        __syncthreads();

        // S = Q K^T : warp tile 32m x 64n, d loop of 8
        float s[2][8][4];
        #pragma unroll
        for (int mi = 0; mi < 2; mi++)
            #pragma unroll
            for (int nj = 0; nj < 8; nj++)
                #pragma unroll
                for (int q = 0; q < 4; q++) s[mi][nj][q] = 0.f;

        #pragma unroll
        for (int kk = 0; kk < 8; kk++) {
            int k0 = kk * 8;
            unsigned af[2][4], bf[8][2];
            #pragma unroll
            for (int mi = 0; mi < 2; mi++)
                ldsmx4(af[mi], q_ptr[mi] + kk * 32);
            #pragma unroll
            for (int nj = 0; nj < 8; nj++) {
                int cc = wn + nj * 8 + l4;       // key index j
                bf[nj][0] = __float_as_uint(Ks[cc * 68 + k0 + lk]);
                bf[nj][1] = __float_as_uint(Ks[cc * 68 + k0 + lk + 4]);
            }
            #pragma unroll
            for (int mi = 0; mi < 2; mi++)
                #pragma unroll
                for (int nj = 0; nj < 8; nj++)
                    MMA_TF32(s[mi][nj], af[mi], bf[nj]);
        }

        // scale + mask into Ps
        #pragma unroll
        for (int mi = 0; mi < 2; mi++) {
            int r0 = wm + mi * 16 + l4;
            #pragma unroll
            for (int nj = 0; nj < 8; nj++) {
                int c0 = wn + nj * 8 + 2 * lk;
                int qr0 = mt * 128 + r0, qr1 = qr0 + 8;
                int kc0 = jt * 128 + c0, kc1 = kc0 + 1;
                float v0 = s[mi][nj][0] * 0.125f;
                float v1 = s[mi][nj][1] * 0.125f;
                float v2 = s[mi][nj][2] * 0.125f;
                float v3 = s[mi][nj][3] * 0.125f;
                if (kc0 > qr0 || kc0 >= len) v0 = -1.0e30f;
                if (kc1 > qr0 || kc1 >= len) v1 = -1.0e30f;
                if (kc0 > qr1 || kc0 >= len) v2 = -1.0e30f;
                if (kc1 > qr1 || kc1 >= len) v3 = -1.0e30f;
                Ps[r0 * 132 + c0] = v0;
                Ps[r0 * 132 + c0 + 1] = v1;
                Ps[(r0 + 8) * 132 + c0] = v2;
                Ps[(r0 + 8) * 132 + c0 + 1] = v3;
            }
        }
        __syncthreads();

        // write raw masked scores to gmem (coalesced)
        #pragma unroll
        for (int i = 0; i < 16; i++) {
            int lin = tid + i * 256;
            int r = lin >> 5, c4 = (lin & 31) * 4;
            float4 v = *(const float4*)&Ps[r * 132 + c4];
            *(float4*)&attn[(attn_head + mt * 128 + r) * Sq + jt * 128 + c4] = v;
        }

        // row max (2 threads/row x 64 cols)
        {
            int r = tid & 127, half = tid >> 7;
            float tmax = -3.0e38f;
            #pragma unroll 16
            for (int k = 0; k < 64; k++)
                tmax = fmaxf(tmax, Ps[r * 132 + half * 64 + k]);
            sred[half * 128 + r] = tmax;
        }
        __syncthreads();
        if (tid < 128) {
            float mn = fmaxf(sred[tid], sred[128 + tid]);
            mn = fmaxf(mn, mrow[tid]);
            fac[tid] = __expf(mrow[tid] - mn);
            mrow[tid] = mn;
        }
        __syncthreads();
        // exponentiate (tf32-round probs) + partial sums
        {
            int r = tid & 127, half = tid >> 7;
            float mn = mrow[r];
            float sum = 0.f;
            #pragma unroll 16
            for (int k = 0; k < 64; k++) {
                float p = f2tff(__expf(Ps[r * 132 + half * 64 + k] - mn));
                Ps[r * 132 + half * 64 + k] = p;
                sum += p;
            }
            sred[half * 128 + r] = sum;
        }
        __syncthreads();
        if (tid < 128)
            lrow[tid] = lrow[tid] * fac[tid] + (sred[tid] + sred[128 + tid]);
        __syncthreads();

        // rescale O frags, then O += P @ V (warp tile 32m x 32d, j loop 128)
        #pragma unroll
        for (int mi = 0; mi < 2; mi++) {
            int r0 = wm + mi * 16 + l4;
            float f0 = fac[r0], f1 = fac[r0 + 8];
            #pragma unroll
            for (int nj = 0; nj < 4; nj++) {
                o[mi][nj][0] *= f0; o[mi][nj][1] *= f0;
                o[mi][nj][2] *= f1; o[mi][nj][3] *= f1;
            }
        }
        #pragma unroll
        for (int kk = 0; kk < 16; kk++) {
            int k0 = kk * 8;
            unsigned af[2][4], bf[4][2];
            #pragma unroll
            for (int mi = 0; mi < 2; mi++)
                ldsmx4(af[mi], p_ptr[mi] + kk * 32);
            #pragma unroll
            for (int nj = 0; nj < 4; nj++) {
                int cc = wd + nj * 8 + l4;       // d index
                bf[nj][0] = __float_as_uint(Vs[(k0 + lk) * 72 + cc]);
                bf[nj][1] = __float_as_uint(Vs[(k0 + lk + 4) * 72 + cc]);
            }
            #pragma unroll
            for (int mi = 0; mi < 2; mi++)
                #pragma unroll
                for (int nj = 0; nj < 4; nj++)
                    MMA_TF32(o[mi][nj], af[mi], bf[nj]);
        }
    }
    __syncthreads();

    // epilogue: O /= l ; write O; write stats
    #pragma unroll
    for (int mi = 0; mi < 2; mi++) {
        int r0 = wm + mi * 16 + l4;
        float inv0 = 1.0f / lrow[r0];
        float inv1 = 1.0f / lrow[r0 + 8];
        int gr0 = b * Sq + mt * 128 + r0;
        #pragma unroll
        for (int nj = 0; nj < 4; nj++) {
            int col = qh * 64 + wd + nj * 8 + 2 * lk;
            float2 w0, w1;
            w0.x = o[mi][nj][0] * inv0; w0.y = o[mi][nj][1] * inv0;
            w1.x = o[mi][nj][2] * inv1; w1.y = o[mi][nj][3] * inv1;
            *(float2*)&g_O[(size_t)gr0 * (NQ * DVh) + col] = w0;
            *(float2*)&g_O[(size_t)(gr0 + 8) * (NQ * DVh) + col] = w1;
        }
    }
    if (tid < 128) {
        size_t si = ((size_t)b * NQ + qh) * Sq + mt * 128 + tid;
        g_m[si] = mrow[tid];
        g_l[si] = lrow[tid];
    }
}

// ---------------------------------------------------------------------------
// Attention pass 2: normalize probabilities (and zero the masked region).
// ---------------------------------------------------------------------------
__global__ void attn_norm_kernel(const int* __restrict__ lens,
                                 float* __restrict__ attn)
{
    size_t row = blockIdx.x;
    int t   = (int)(row & (Sq - 1));
    int kvh = (int)((row >> 11) & 3);
    int grp = (int)((row >> 13) & 3);
    int n   = (int)(row >> 15);
    int qh  = kvh * GRP + grp;
    int len = lens[n];
    size_t si = ((size_t)n * NQ + qh) * Sq + t;
    float mn  = g_m[si];
    float inv = 1.0f / g_l[si];
    float* rp = attn + row * (size_t)Sq;
    int lim = min(t, len - 1);
    int c0 = threadIdx.x * 8;
    #pragma unroll
    for (int u = 0; u < 8; u += 4) {
        int c = c0 + u;
        float4 v;
        if (c + 3 <= lim) {
            float4 s4 = *(const float4*)&rp[c];
            v.x = __expf(s4.x - mn) * inv;
            v.y = __expf(s4.y - mn) * inv;
            v.z = __expf(s4.z - mn) * inv;
            v.w = __expf(s4.w - mn) * inv;
        } else {
            v.x = (c + 0 <= lim) ? __expf(rp[c + 0] - mn) * inv : 0.f;
            v.y = (c + 1 <= lim) ? __expf(rp[c + 1] - mn) * inv : 0.f;
            v.z = (c + 2 <= lim) ? __expf(rp[c + 2] - mn) * inv : 0.f;
            v.w = (c + 3 <= lim) ? __expf(rp[c + 3] - mn) * inv : 0.f;
        }
        *(float4*)&rp[c] = v;
    }
}

// ---------------------------------------------------------------------------
// Launch
// ---------------------------------------------------------------------------
extern "C" void kernel_launch(void* const* d_in, const int* in_sizes, int n_in,
                              void* d_out, int out_size)
{
    const float* x_q  = (const float*)d_in[0];
    const float* x_k  = (const float*)d_in[1];
    const float* x_v  = (const float*)d_in[2];
    const int*   lens = (const int*)  d_in[3];
    const float* gam  = (const float*)d_in[4];
    const float* bet  = (const float*)d_in[5];
    const float* Wq   = (const float*)d_in[6];
    const float* bq   = (const float*)d_in[7];
    const float* Wk   = (const float*)d_in[8];
    const float* bk   = (const float*)d_in[9];
    const float* Wv   = (const float*)d_in[10];
    const float* bv   = (const float*)d_in[11];
    const float* Wo   = (const float*)d_in[12];
    const float* bo   = (const float*)d_in[13];

    float* out  = (float*)d_out;                       // (B, S, 1024)
    float* attn = out + (size_t)Bq * Sq * Dm;          // (B, GRP, NKV, S, S)

    float *xnq, *xnk, *xnv, *Qb, *Kb, *Vb, *Ob;
    cudaGetSymbolAddress((void**)&xnq, g_xnq);
    cudaGetSymbolAddress((void**)&xnk, g_xnk);
    cudaGetSymbolAddress((void**)&xnv, g_xnv);
    cudaGetSymbolAddress((void**)&Qb,  g_Q);
    cudaGetSymbolAddress((void**)&Kb,  g_K);
    cudaGetSymbolAddress((void**)&Vb,  g_V);
    cudaGetSymbolAddress((void**)&Ob,  g_O);

    const int M = Bq * Sq;   // 4096

    static bool attr_set = false;
    if (!attr_set) {
        cudaFuncSetAttribute(gemm_tf32, cudaFuncAttributeMaxDynamicSharedMemorySize, GEMM_SMEM);
        cudaFuncSetAttribute(gemm_tf32_kv, cudaFuncAttributeMaxDynamicSharedMemorySize, GEMM_SMEM);
        cudaFuncSetAttribute(attn_kernel, cudaFuncAttributeMaxDynamicSharedMemorySize, ATTN_SMEM);
        attr_set = true;
    }

    // 1) LayerNorms (fused, one launch)
    ln3_kernel<<<dim3(M, 3), 256>>>(x_q, x_k, x_v, gam, bet, xnq, xnk, xnv);

    // 2) Projections (tf32 tensor cores); K+V fused in one launch
    gemm_tf32<<<dim3(Dm / 256, M / 128), 256, GEMM_SMEM>>>(xnq, Wq, bq, Qb, M, NQ * DQh, Dm);
    gemm_tf32_kv<<<dim3(1, M / 128, 2), 256, GEMM_SMEM>>>(
        xnk, xnv, Wk, Wv, bk, bv, Kb, Vb, M, NKV * DQh, Dm);

    // 3) RoPE
    {
        int pq = Bq * Sq * NQ * 32;
        int pk = Bq * Sq * NKV * 32;
        rope_kernel<<<(pq + 255) / 256, 256>>>(Qb, NQ, pq);
        rope_kernel<<<(pk + 255) / 256, 256>>>(Kb, NKV, pk);
    }

    // 4) Attention pass 1 (tensor cores, 128-wide key tiles)
    attn_kernel<<<dim3(Sq / 128, NQ, Bq), 256, ATTN_SMEM>>>(lens, attn);

    // 5) Attention pass 2 (normalize probs / zero-fill)
    attn_norm_kernel<<<Bq * GRP * NKV * Sq, 256>>>(lens, attn);

    // 6) Output projection (tensor cores)
    gemm_tf32<<<dim3(Dm / 256, M / 128), 256, GEMM_SMEM>>>(Ob, Wo, bo, out, M, Dm, Dm);
}

// round 6
// speedup vs baseline: 2.4390x; 1.0234x over previous
#include <cuda_runtime.h>
#include <cuda_bf16.h>
#include <cmath>

// Problem constants
#define Bq     2
#define Sq     2048
#define Dm     1024
#define NQ     16
#define NKV    4
#define GRP    4
#define DQh    64
#define DVh    64

// Scratch (device globals — no allocation allowed)
__device__ float g_xnq[Bq*Sq*Dm];
__device__ float g_xnk[Bq*Sq*Dm];
__device__ float g_xnv[Bq*Sq*Dm];
__device__ float g_Q  [Bq*Sq*NQ*DQh];
__device__ float g_K  [Bq*Sq*NKV*DQh];
__device__ float g_V  [Bq*Sq*NKV*DVh];
__device__ float g_O  [Bq*Sq*NQ*DVh];

// tf32 helpers
__device__ __forceinline__ unsigned f2tf(float x) {
    unsigned u;
    asm("cvt.rna.tf32.f32 %0, %1;" : "=r"(u) : "f"(x));
    return u;
}
__device__ __forceinline__ float f2tff(float x) { return __uint_as_float(f2tf(x)); }

#define MMA_TF32(c, a, b)                                                      \
    asm volatile("mma.sync.aligned.m16n8k8.row.col.f32.tf32.tf32.f32 "         \
                 "{%0,%1,%2,%3},{%4,%5,%6,%7},{%8,%9},{%0,%1,%2,%3};"          \
                 : "+f"((c)[0]), "+f"((c)[1]), "+f"((c)[2]), "+f"((c)[3])      \
                 : "r"((a)[0]), "r"((a)[1]), "r"((a)[2]), "r"((a)[3]),         \
                   "r"((b)[0]), "r"((b)[1]))

__device__ __forceinline__ void ldsmx4(unsigned r[4], unsigned saddr) {
    asm volatile("ldmatrix.sync.aligned.m8n8.x4.shared.b16 {%0,%1,%2,%3}, [%4];"
                 : "=r"(r[0]), "=r"(r[1]), "=r"(r[2]), "=r"(r[3])
                 : "r"(saddr));
}
__device__ __forceinline__ unsigned lane_frag_addr(const float* base, int lane,
                                                   int r0, int ldm) {
    const float* p = base + (size_t)(r0 + ((lane >> 3) & 1) * 8 + (lane & 7)) * ldm
                          + (lane >> 4) * 4;
    return (unsigned)__cvta_generic_to_shared(p);
}

// ---------------------------------------------------------------------------
// Fused LayerNorm x3
// ---------------------------------------------------------------------------
__global__ void ln3_kernel(const float* __restrict__ xq,
                           const float* __restrict__ xk,
                           const float* __restrict__ xv,
                           const float* __restrict__ gamma,
                           const float* __restrict__ beta,
                           float* __restrict__ yq,
                           float* __restrict__ yk,
                           float* __restrict__ yv)
{
    int row = blockIdx.x;
    int which = blockIdx.y;
    const float* x = (which == 0) ? xq : (which == 1) ? xk : xv;
    float* y       = (which == 0) ? yq : (which == 1) ? yk : yv;
    int tid = threadIdx.x;
    const float4* xr = (const float4*)(x + (size_t)row * Dm);
    float4 v = xr[tid];
    float s  = v.x + v.y + v.z + v.w;
    float ss = v.x*v.x + v.y*v.y + v.z*v.z + v.w*v.w;
    #pragma unroll
    for (int o = 16; o > 0; o >>= 1) {
        s  += __shfl_down_sync(0xffffffffu, s,  o);
        ss += __shfl_down_sync(0xffffffffu, ss, o);
    }
    __shared__ float as[8], bs[8];
    __shared__ float s_mu, s_inv;
    if ((tid & 31) == 0) { as[tid >> 5] = s; bs[tid >> 5] = ss; }
    __syncthreads();
    if (tid == 0) {
        float S = 0.f, SS = 0.f;
        #pragma unroll
        for (int i = 0; i < 8; i++) { S += as[i]; SS += bs[i]; }
        float mu  = S * (1.0f / Dm);
        float var = SS * (1.0f / Dm) - mu * mu;
        s_mu  = mu;
        s_inv = rsqrtf(var + 1e-5f);
    }
    __syncthreads();
    float mu = s_mu, inv = s_inv;
    float4 g  = ((const float4*)gamma)[tid];
    float4 bb = ((const float4*)beta )[tid];
    float4 o;
    o.x = (v.x - mu) * inv * g.x + bb.x;
    o.y = (v.y - mu) * inv * g.y + bb.y;
    o.z = (v.z - mu) * inv * g.z + bb.z;
    o.w = (v.w - mu) * inv * g.w + bb.w;
    ((float4*)(y + (size_t)row * Dm))[tid] = o;
}

// ---------------------------------------------------------------------------
// tf32 tensor-core GEMM with bias: 128x256 block, BK=16, 8 warps of 64x64.
// ---------------------------------------------------------------------------
#define G_AS (128*20)
#define G_BS (16*264)
#define GEMM_SMEM ((2*G_AS + 2*G_BS)*4)

__device__ __forceinline__ void gemm_body(const float* __restrict__ A,
                                          const float* __restrict__ B,
                                          const float* __restrict__ bias,
                                          float* __restrict__ C,
                                          int M, int N, int K,
                                          float* smem)
{
    float* As = smem;               // [2][128][20]
    float* Bs = smem + 2 * G_AS;    // [2][16][264]

    int tid  = threadIdx.x;
    int lane = tid & 31, wid = tid >> 5;
    int wm = (wid & 1) * 64, wn = (wid >> 1) * 64;
    int l4 = lane >> 2, lk = lane & 3;
    int mb = blockIdx.y * 128, nb = blockIdx.x * 256;

    int ar = tid >> 1, ak = (tid & 1) * 8;
    int bk = tid >> 4, bn = (tid & 15) * 4;
    const float* Ap = A + (size_t)(mb + ar) * K + ak;
    const float* Bp = B + (size_t)bk * N + nb + bn;

    float c[4][8][4];
    #pragma unroll
    for (int mi = 0; mi < 4; mi++)
        #pragma unroll
        for (int nj = 0; nj < 8; nj++)
            #pragma unroll
            for (int q = 0; q < 4; q++) c[mi][nj][q] = 0.f;

    #pragma unroll
    for (int i = 0; i < 2; i++) {
        float4 v = *(const float4*)(Ap + i * 4);
        float4 w; w.x = f2tff(v.x); w.y = f2tff(v.y); w.z = f2tff(v.z); w.w = f2tff(v.w);
        *(float4*)&As[ar * 20 + ak + i * 4] = w;
    }
    #pragma unroll
    for (int i = 0; i < 4; i++) {
        float4 u = *(const float4*)(Bp + i * 64);
        float4 z; z.x = f2tff(u.x); z.y = f2tff(u.y); z.z = f2tff(u.z); z.w = f2tff(u.w);
        *(float4*)&Bs[bk * 264 + bn + i * 64] = z;
    }
    __syncthreads();

    int nt = K >> 4;
    for (int t = 0; t < nt; t++) {
        int cur = t & 1, nxt = cur ^ 1;
        float4 pa[2], pb[4];
        bool more = (t + 1 < nt);
        if (more) {
            #pragma unroll
            for (int i = 0; i < 2; i++)
                pa[i] = *(const float4*)(Ap + (size_t)(t + 1) * 16 + i * 4);
            #pragma unroll
            for (int i = 0; i < 4; i++)
                pb[i] = *(const float4*)(Bp + (size_t)(t + 1) * 16 * N + i * 64);
        }
        const float* Ab = As + cur * G_AS;
        const float* Bb = Bs + cur * G_BS;
        unsigned a_ptr[4];
        #pragma unroll
        for (int mi = 0; mi < 4; mi++)
            a_ptr[mi] = lane_frag_addr(Ab, lane, wm + mi * 16, 20);

        #pragma unroll
        for (int kk = 0; kk < 2; kk++) {
            int k0 = kk * 8;
            unsigned af[4][4], bf[8][2];
            #pragma unroll
            for (int mi = 0; mi < 4; mi++)
                ldsmx4(af[mi], a_ptr[mi] + kk * 32);
            #pragma unroll
            for (int nj = 0; nj < 8; nj++) {
                int cc = wn + nj * 8 + l4;
                bf[nj][0] = __float_as_uint(Bb[(k0 + lk) * 264 + cc]);
                bf[nj][1] = __float_as_uint(Bb[(k0 + lk + 4) * 264 + cc]);
            }
            #pragma unroll
            for (int mi = 0; mi < 4; mi++)
                #pragma unroll
                for (int nj = 0; nj < 8; nj++)
                    MMA_TF32(c[mi][nj], af[mi], bf[nj]);
        }
        if (more) {
            float* An = As + nxt * G_AS;
            float* Bn = Bs + nxt * G_BS;
            #pragma unroll
            for (int i = 0; i < 2; i++) {
                float4 w; w.x = f2tff(pa[i].x); w.y = f2tff(pa[i].y);
                w.z = f2tff(pa[i].z); w.w = f2tff(pa[i].w);
                *(float4*)&An[ar * 20 + ak + i * 4] = w;
            }
            #pragma unroll
            for (int i = 0; i < 4; i++) {
                float4 z; z.x = f2tff(pb[i].x); z.y = f2tff(pb[i].y);
                z.z = f2tff(pb[i].z); z.w = f2tff(pb[i].w);
                *(float4*)&Bn[bk * 264 + bn + i * 64] = z;
            }
            __syncthreads();
        }
    }

    #pragma unroll
    for (int nj = 0; nj < 8; nj++) {
        int col = nb + wn + nj * 8 + 2 * lk;
        float2 bj = *(const float2*)&bias[col];
        #pragma unroll
        for (int mi = 0; mi < 4; mi++) {
            int r0 = mb + wm + mi * 16 + l4;
            float2 o0, o1;
            o0.x = c[mi][nj][0] + bj.x; o0.y = c[mi][nj][1] + bj.y;
            o1.x = c[mi][nj][2] + bj.x; o1.y = c[mi][nj][3] + bj.y;
            *(float2*)&C[(size_t)r0 * N + col] = o0;
            *(float2*)&C[(size_t)(r0 + 8) * N + col] = o1;
        }
    }
}

__global__ void __launch_bounds__(256, 1)
gemm_tf32(const float* __restrict__ A, const float* __restrict__ B,
          const float* __restrict__ bias, float* __restrict__ C,
          int M, int N, int K)
{
    extern __shared__ float smem[];
    gemm_body(A, B, bias, C, M, N, K, smem);
}

__global__ void __launch_bounds__(256, 1)
gemm_tf32_kv(const float* __restrict__ Ak, const float* __restrict__ Av,
             const float* __restrict__ Wk, const float* __restrict__ Wv,
             const float* __restrict__ bk_, const float* __restrict__ bv_,
             float* __restrict__ Ck, float* __restrict__ Cv,
             int M, int N, int K)
{
    extern __shared__ float smem[];
    if (blockIdx.z == 0) gemm_body(Ak, Wk, bk_, Ck, M, N, K, smem);
    else                 gemm_body(Av, Wv, bv_, Cv, M, N, K, smem);
}

// ---------------------------------------------------------------------------
// RoPE (interleaved pairs), in place.
// ---------------------------------------------------------------------------
__global__ void rope_kernel(float* __restrict__ X, int heads, int total_pairs)
{
    int p = blockIdx.x * blockDim.x + threadIdx.x;
    if (p >= total_pairs) return;
    int i = p & 31;
    int t = (p / (32 * heads)) & (Sq - 1);
    // invf = 10000^(-2i/64) = exp2(-log2(10000) * i/32)
    float invf = exp2f(-13.287712379549449f * ((float)i * (1.0f / 32.0f)));
    float ang  = (float)t * invf;
    float sn, cs;
    sincosf(ang, &sn, &cs);
    size_t e = (size_t)p * 2;
    float x1 = X[e], x2 = X[e + 1];
    X[e]     = x1 * cs - x2 * sn;
    X[e + 1] = x1 * sn + x2 * cs;
}

// ---------------------------------------------------------------------------
// Attention (single kernel, two sweeps):
//  Sweep 1: QK^T + register-level online softmax stats (m, l) — no stores.
//  Sweep 2: recompute QK^T, p = exp(s - m)/l (final), write probs to gmem,
//           O += p @ V (already normalized). Zero-fill masked tiles.
// Block: 128 q-rows; key tiles 128 wide. Warps 4m x 2n.
// ---------------------------------------------------------------------------
#define A_QS (128*68)
#define A_KS (128*68)
#define A_VS (128*72)
#define A_PS (128*132)
#define ATTN_SMEM ((A_QS + A_KS + A_VS + A_PS + 128*3 + 256) * 4)

__global__ void __launch_bounds__(256, 1)
attn_kernel(const int* __restrict__ lens, float* __restrict__ attn)
{
    extern __shared__ float sm[];
    float* Qs   = sm;                        // [128 m][68]  (A operand, LDSM)
    float* Ks   = Qs + A_QS;                 // [128 j][68]  natural
    float* Vs   = Ks + A_KS;                 // [128 j][72]  natural
    float* Ps   = Vs + A_VS;                 // [128 m][132] probs staging
    float* mrow = Ps + A_PS;                 // [128]
    float* lrow = mrow + 128;
    float* fac  = lrow + 128;
    float* sred = fac + 128;                 // [2][128]

    int tid  = threadIdx.x;
    int lane = tid & 31, wid = tid >> 5;
    int wm = (wid >> 1) * 32;                // warp m offset (0..96)
    int wn = (wid & 1) * 64;                 // QK: warp n offset (0/64)
    int wnidx = wid & 1;
    int wd = (wid & 1) * 32;                 // PV: warp d offset (0/32)
    int l4 = lane >> 2, lk = lane & 3;

    int mt = (int)gridDim.x - 1 - (int)blockIdx.x;   // heavy-first
    int qh = blockIdx.y, b = blockIdx.z;
    int kvh = qh >> 2;
    int grp = qh & 3;
    int len = lens[b];

    // Load Q tile (128 x 64), tf32-rounded
    #pragma unroll
    for (int i = 0; i < 8; i++) {
        int lin = tid + i * 256;
        int r = lin >> 4, c4 = (lin & 15) * 4;
        float4 v = *(const float4*)&g_Q[((size_t)(b * Sq + mt * 128 + r)) * (NQ * DQh) + qh * 64 + c4];
        float4 w; w.x = f2tff(v.x); w.y = f2tff(v.y); w.z = f2tff(v.z); w.w = f2tff(v.w);
        *(float4*)&Qs[r * 68 + c4] = w;
    }
    if (tid < 128) { mrow[tid] = -3.0e38f; lrow[tid] = 0.f; }

    unsigned q_ptr[2], p_ptr[2];
    #pragma unroll
    for (int mi = 0; mi < 2; mi++) {
        q_ptr[mi] = lane_frag_addr(Qs, lane, wm + mi * 16, 68);
        p_ptr[mi] = lane_frag_addr(Ps, lane, wm + mi * 16, 132);
    }

    int jend = min(mt, (len - 1) >> 7);
    size_t attn_head = (((size_t)(b * GRP + grp)) * NKV + kvh) * Sq;

    // =================== Sweep 1: stats only ===================
    for (int jt = 0; jt <= jend; jt++) {
        __syncthreads();
        // Load K tile (128 x 64), natural layout, tf32
        #pragma unroll
        for (int i = 0; i < 8; i++) {
            int lin = tid + i * 256;
            int r = lin >> 4, c4 = (lin & 15) * 4;
            size_t gidx = ((size_t)(b * Sq + jt * 128 + r)) * (NKV * DQh) + kvh * 64 + c4;
            float4 kv = *(const float4*)&g_K[gidx];
            float4 kw; kw.x = f2tff(kv.x); kw.y = f2tff(kv.y);
            kw.z = f2tff(kv.z); kw.w = f2tff(kv.w);
            *(float4*)&Ks[r * 68 + c4] = kw;
        }
        __syncthreads();

        // S = Q K^T
        float s[2][8][4];
        #pragma unroll
        for (int mi = 0; mi < 2; mi++)
            #pragma unroll
            for (int nj = 0; nj < 8; nj++)
                #pragma unroll
                for (int q = 0; q < 4; q++) s[mi][nj][q] = 0.f;
        #pragma unroll
        for (int kk = 0; kk < 8; kk++) {
            int k0 = kk * 8;
            unsigned af[2][4], bf[8][2];
            #pragma unroll
            for (int mi = 0; mi < 2; mi++)
                ldsmx4(af[mi], q_ptr[mi] + kk * 32);
            #pragma unroll
            for (int nj = 0; nj < 8; nj++) {
                int cc = wn + nj * 8 + l4;
                bf[nj][0] = __float_as_uint(Ks[cc * 68 + k0 + lk]);
                bf[nj][1] = __float_as_uint(Ks[cc * 68 + k0 + lk + 4]);
            }
            #pragma unroll
            for (int mi = 0; mi < 2; mi++)
                #pragma unroll
                for (int nj = 0; nj < 8; nj++)
                    MMA_TF32(s[mi][nj], af[mi], bf[nj]);
        }

        // scale + mask in registers
        #pragma unroll
        for (int mi = 0; mi < 2; mi++) {
            int r0 = wm + mi * 16 + l4;
            int qr0 = mt * 128 + r0, qr1 = qr0 + 8;
            #pragma unroll
            for (int nj = 0; nj < 8; nj++) {
                int kc0 = jt * 128 + wn + nj * 8 + 2 * lk, kc1 = kc0 + 1;
                s[mi][nj][0] = (kc0 > qr0 || kc0 >= len) ? -1.0e30f : s[mi][nj][0] * 0.125f;
                s[mi][nj][1] = (kc1 > qr0 || kc1 >= len) ? -1.0e30f : s[mi][nj][1] * 0.125f;
                s[mi][nj][2] = (kc0 > qr1 || kc0 >= len) ? -1.0e30f : s[mi][nj][2] * 0.125f;
                s[mi][nj][3] = (kc1 > qr1 || kc1 >= len) ? -1.0e30f : s[mi][nj][3] * 0.125f;
            }
        }

        // per-lane row max + shfl over the 4-lane row group
        #pragma unroll
        for (int mi = 0; mi < 2; mi++) {
            float m0 = -3.0e38f, m1 = -3.0e38f;
            #pragma unroll
            for (int nj = 0; nj < 8; nj++) {
                m0 = fmaxf(m0, fmaxf(s[mi][nj][0], s[mi][nj][1]));
                m1 = fmaxf(m1, fmaxf(s[mi][nj][2], s[mi][nj][3]));
            }
            m0 = fmaxf(m0, __shfl_xor_sync(0xffffffffu, m0, 1));
            m0 = fmaxf(m0, __shfl_xor_sync(0xffffffffu, m0, 2));
            m1 = fmaxf(m1, __shfl_xor_sync(0xffffffffu, m1, 1));
            m1 = fmaxf(m1, __shfl_xor_sync(0xffffffffu, m1, 2));
            if (lk == 0) {
                int r0 = wm + mi * 16 + l4;
                sred[wnidx * 128 + r0] = m0;
                sred[wnidx * 128 + r0 + 8] = m1;
            }
        }
        __syncthreads();
        if (tid < 128) {
            float mn = fmaxf(fmaxf(sred[tid], sred[128 + tid]), mrow[tid]);
            fac[tid] = __expf(mrow[tid] - mn);
            mrow[tid] = mn;
        }
        __syncthreads();

        // per-lane exp-sum with new max
        #pragma unroll
        for (int mi = 0; mi < 2; mi++) {
            int r0 = wm + mi * 16 + l4;
            float mm0 = mrow[r0], mm1 = mrow[r0 + 8];
            float s0 = 0.f, s1 = 0.f;
            #pragma unroll
            for (int nj = 0; nj < 8; nj++) {
                s0 += __expf(s[mi][nj][0] - mm0) + __expf(s[mi][nj][1] - mm0);
                s1 += __expf(s[mi][nj][2] - mm1) + __expf(s[mi][nj][3] - mm1);
            }
            s0 += __shfl_xor_sync(0xffffffffu, s0, 1);
            s0 += __shfl_xor_sync(0xffffffffu, s0, 2);
            s1 += __shfl_xor_sync(0xffffffffu, s1, 1);
            s1 += __shfl_xor_sync(0xffffffffu, s1, 2);
            if (lk == 0) {
                sred[wnidx * 128 + r0] = s0;
                sred[wnidx * 128 + r0 + 8] = s1;
            }
        }
        __syncthreads();
        if (tid < 128)
            lrow[tid] = lrow[tid] * fac[tid] + (sred[tid] + sred[128 + tid]);
    }
    __syncthreads();

    // per-lane final stats (4 rows per lane)
    float fm[2][2], fl[2][2];
    #pragma unroll
    for (int mi = 0; mi < 2; mi++) {
        int r0 = wm + mi * 16 + l4;
        fm[mi][0] = mrow[r0];      fm[mi][1] = mrow[r0 + 8];
        fl[mi][0] = 1.0f / lrow[r0]; fl[mi][1] = 1.0f / lrow[r0 + 8];
    }

    float o[2][4][4];
    #pragma unroll
    for (int mi = 0; mi < 2; mi++)
        #pragma unroll
        for (int nj = 0; nj < 4; nj++)
            #pragma unroll
            for (int q = 0; q < 4; q++) o[mi][nj][q] = 0.f;

    // =================== Sweep 2: probs + PV ===================
    for (int jt = 0; jt <= jend; jt++) {
        __syncthreads();
        // Load K and V tiles
        #pragma unroll
        for (int i = 0; i < 8; i++) {
            int lin = tid + i * 256;
            int r = lin >> 4, c4 = (lin & 15) * 4;
            size_t gidx = ((size_t)(b * Sq + jt * 128 + r)) * (NKV * DQh) + kvh * 64 + c4;
            float4 kv = *(const float4*)&g_K[gidx];
            float4 kw; kw.x = f2tff(kv.x); kw.y = f2tff(kv.y);
            kw.z = f2tff(kv.z); kw.w = f2tff(kv.w);
            *(float4*)&Ks[r * 68 + c4] = kw;
            float4 vv = *(const float4*)&g_V[gidx];
            float4 vw; vw.x = f2tff(vv.x); vw.y = f2tff(vv.y);
            vw.z = f2tff(vv.z); vw.w = f2tff(vv.w);
            *(float4*)&Vs[r * 72 + c4] = vw;
        }
        __syncthreads();

        // S = Q K^T
        float s[2][8][4];
        #pragma unroll
        for (int mi = 0; mi < 2; mi++)
            #pragma unroll
            for (int nj = 0; nj < 8; nj++)
                #pragma unroll
                for (int q = 0; q < 4; q++) s[mi][nj][q] = 0.f;
        #pragma unroll
        for (int kk = 0; kk < 8; kk++) {
            int k0 = kk * 8;
            unsigned af[2][4], bf[8][2];
            #pragma unroll
            for (int mi = 0; mi < 2; mi++)
                ldsmx4(af[mi], q_ptr[mi] + kk * 32);
            #pragma unroll
            for (int nj = 0; nj < 8; nj++) {
                int cc = wn + nj * 8 + l4;
                bf[nj][0] = __float_as_uint(Ks[cc * 68 + k0 + lk]);
                bf[nj][1] = __float_as_uint(Ks[cc * 68 + k0 + lk + 4]);
            }
            #pragma unroll
            for (int mi = 0; mi < 2; mi++)
                #pragma unroll
                for (int nj = 0; nj < 8; nj++)
                    MMA_TF32(s[mi][nj], af[mi], bf[nj]);
        }

        // final normalized probs into Ps (masked -> exact 0)
        #pragma unroll
        for (int mi = 0; mi < 2; mi++) {
            int r0 = wm + mi * 16 + l4;
            int qr0 = mt * 128 + r0, qr1 = qr0 + 8;
            float mm0 = fm[mi][0], mm1 = fm[mi][1];
            float il0 = fl[mi][0], il1 = fl[mi][1];
            #pragma unroll
            for (int nj = 0; nj < 8; nj++) {
                int c0 = wn + nj * 8 + 2 * lk;
                int kc0 = jt * 128 + c0, kc1 = kc0 + 1;
                float p0 = (kc0 > qr0 || kc0 >= len) ? 0.f
                         : __expf(s[mi][nj][0] * 0.125f - mm0) * il0;
                float p1 = (kc1 > qr0 || kc1 >= len) ? 0.f
                         : __expf(s[mi][nj][1] * 0.125f - mm0) * il0;
                float p2 = (kc0 > qr1 || kc0 >= len) ? 0.f
                         : __expf(s[mi][nj][2] * 0.125f - mm1) * il1;
                float p3 = (kc1 > qr1 || kc1 >= len) ? 0.f
                         : __expf(s[mi][nj][3] * 0.125f - mm1) * il1;
                Ps[r0 * 132 + c0] = f2tff(p0);
                Ps[r0 * 132 + c0 + 1] = f2tff(p1);
                Ps[(r0 + 8) * 132 + c0] = f2tff(p2);
                Ps[(r0 + 8) * 132 + c0 + 1] = f2tff(p3);
            }
        }
        __syncthreads();

        // write final probs to gmem (coalesced)
        #pragma unroll
        for (int i = 0; i < 16; i++) {
            int lin = tid + i * 256;
            int r = lin >> 5, c4 = (lin & 31) * 4;
            float4 v = *(const float4*)&Ps[r * 132 + c4];
            *(float4*)&attn[(attn_head + mt * 128 + r) * Sq + jt * 128 + c4] = v;
        }

        // O += P @ V (already normalized; no rescale)
        #pragma unroll
        for (int kk = 0; kk < 16; kk++) {
            int k0 = kk * 8;
            unsigned af[2][4], bf[4][2];
            #pragma unroll
            for (int mi = 0; mi < 2; mi++)
                ldsmx4(af[mi], p_ptr[mi] + kk * 32);
            #pragma unroll
            for (int nj = 0; nj < 4; nj++) {
                int cc = wd + nj * 8 + l4;
                bf[nj][0] = __float_as_uint(Vs[(k0 + lk) * 72 + cc]);
                bf[nj][1] = __float_as_uint(Vs[(k0 + lk + 4) * 72 + cc]);
            }
            #pragma unroll
            for (int mi = 0; mi < 2; mi++)
                #pragma unroll
                for (int nj = 0; nj < 4; nj++)
                    MMA_TF32(o[mi][nj], af[mi], bf[nj]);
        }
    }

    // zero-fill fully masked tiles
    for (int jt = jend + 1; jt < Sq / 128; jt++) {
        float4 z = make_float4(0.f, 0.f, 0.f, 0.f);
        #pragma unroll
        for (int i = 0; i < 16; i++) {
            int lin = tid + i * 256;
            int r = lin >> 5, c4 = (lin & 31) * 4;
            *(float4*)&attn[(attn_head + mt * 128 + r) * Sq + jt * 128 + c4] = z;
        }
    }

    // epilogue: write O (already normalized)
    #pragma unroll
    for (int mi = 0; mi < 2; mi++) {
        int r0 = wm + mi * 16 + l4;
        int gr0 = b * Sq + mt * 128 + r0;
        #pragma unroll
        for (int nj = 0; nj < 4; nj++) {
            int col = qh * 64 + wd + nj * 8 + 2 * lk;
            float2 w0, w1;
            w0.x = o[mi][nj][0]; w0.y = o[mi][nj][1];
            w1.x = o[mi][nj][2]; w1.y = o[mi][nj][3];
            *(float2*)&g_O[(size_t)gr0 * (NQ * DVh) + col] = w0;
            *(float2*)&g_O[(size_t)(gr0 + 8) * (NQ * DVh) + col] = w1;
        }
    }
}

// ---------------------------------------------------------------------------
// Launch
// ---------------------------------------------------------------------------
extern "C" void kernel_launch(void* const* d_in, const int* in_sizes, int n_in,
                              void* d_out, int out_size)
{
    const float* x_q  = (const float*)d_in[0];
    const float* x_k  = (const float*)d_in[1];
    const float* x_v  = (const float*)d_in[2];
    const int*   lens = (const int*)  d_in[3];
    const float* gam  = (const float*)d_in[4];
    const float* bet  = (const float*)d_in[5];
    const float* Wq   = (const float*)d_in[6];
    const float* bq   = (const float*)d_in[7];
    const float* Wk   = (const float*)d_in[8];
    const float* bk   = (const float*)d_in[9];
    const float* Wv   = (const float*)d_in[10];
    const float* bv   = (const float*)d_in[11];
    const float* Wo   = (const float*)d_in[12];
    const float* bo   = (const float*)d_in[13];

    float* out  = (float*)d_out;                       // (B, S, 1024)
    float* attn = out + (size_t)Bq * Sq * Dm;          // (B, GRP, NKV, S, S)

    float *xnq, *xnk, *xnv, *Qb, *Kb, *Vb, *Ob;
    cudaGetSymbolAddress((void**)&xnq, g_xnq);
    cudaGetSymbolAddress((void**)&xnk, g_xnk);
    cudaGetSymbolAddress((void**)&xnv, g_xnv);
    cudaGetSymbolAddress((void**)&Qb,  g_Q);
    cudaGetSymbolAddress((void**)&Kb,  g_K);
    cudaGetSymbolAddress((void**)&Vb,  g_V);
    cudaGetSymbolAddress((void**)&Ob,  g_O);

    const int M = Bq * Sq;   // 4096

    static bool attr_set = false;
    if (!attr_set) {
        cudaFuncSetAttribute(gemm_tf32, cudaFuncAttributeMaxDynamicSharedMemorySize, GEMM_SMEM);
        cudaFuncSetAttribute(gemm_tf32_kv, cudaFuncAttributeMaxDynamicSharedMemorySize, GEMM_SMEM);
        cudaFuncSetAttribute(attn_kernel, cudaFuncAttributeMaxDynamicSharedMemorySize, ATTN_SMEM);
        attr_set = true;
    }

    // 1) LayerNorms (fused)
    ln3_kernel<<<dim3(M, 3), 256>>>(x_q, x_k, x_v, gam, bet, xnq, xnk, xnv);

    // 2) Projections (tf32 tensor cores)
    gemm_tf32<<<dim3(Dm / 256, M / 128), 256, GEMM_SMEM>>>(xnq, Wq, bq, Qb, M, NQ * DQh, Dm);
    gemm_tf32_kv<<<dim3(1, M / 128, 2), 256, GEMM_SMEM>>>(
        xnk, xnv, Wk, Wv, bk, bv, Kb, Vb, M, NKV * DQh, Dm);

    // 3) RoPE
    {
        int pq = Bq * Sq * NQ * 32;
        int pk = Bq * Sq * NKV * 32;
        rope_kernel<<<(pq + 255) / 256, 256>>>(Qb, NQ, pq);
        rope_kernel<<<(pk + 255) / 256, 256>>>(Kb, NKV, pk);
    }

    // 4) Attention (single kernel: stats sweep + prob/PV sweep)
    attn_kernel<<<dim3(Sq / 128, NQ, Bq), 256, ATTN_SMEM>>>(lens, attn);

    // 5) Output projection
    gemm_tf32<<<dim3(Dm / 256, M / 128), 256, GEMM_SMEM>>>(Ob, Wo, bo, out, M, Dm, Dm);
}

// round 7
// speedup vs baseline: 2.6101x; 1.0701x over previous
#include <cuda_runtime.h>
#include <cuda_bf16.h>
#include <cmath>

// Problem constants
#define Bq     2
#define Sq     2048
#define Dm     1024
#define NQ     16
#define NKV    4
#define GRP    4
#define DQh    64
#define DVh    64

// Scratch (device globals — no allocation allowed)
__device__ float g_xnq[Bq*Sq*Dm];
__device__ float g_xnk[Bq*Sq*Dm];
__device__ float g_xnv[Bq*Sq*Dm];
__device__ float g_Q  [Bq*Sq*NQ*DQh];
__device__ float g_K  [Bq*Sq*NKV*DQh];
__device__ float g_V  [Bq*Sq*NKV*DVh];
__device__ float g_O  [Bq*Sq*NQ*DVh];

// tf32 helpers
__device__ __forceinline__ unsigned f2tf(float x) {
    unsigned u;
    asm("cvt.rna.tf32.f32 %0, %1;" : "=r"(u) : "f"(x));
    return u;
}
__device__ __forceinline__ float f2tff(float x) { return __uint_as_float(f2tf(x)); }

#define MMA_TF32(c, a, b)                                                      \
    asm volatile("mma.sync.aligned.m16n8k8.row.col.f32.tf32.tf32.f32 "         \
                 "{%0,%1,%2,%3},{%4,%5,%6,%7},{%8,%9},{%0,%1,%2,%3};"          \
                 : "+f"((c)[0]), "+f"((c)[1]), "+f"((c)[2]), "+f"((c)[3])      \
                 : "r"((a)[0]), "r"((a)[1]), "r"((a)[2]), "r"((a)[3]),         \
                   "r"((b)[0]), "r"((b)[1]))

__device__ __forceinline__ void ldsmx4(unsigned r[4], unsigned saddr) {
    asm volatile("ldmatrix.sync.aligned.m8n8.x4.shared.b16 {%0,%1,%2,%3}, [%4];"
                 : "=r"(r[0]), "=r"(r[1]), "=r"(r[2]), "=r"(r[3])
                 : "r"(saddr));
}
__device__ __forceinline__ unsigned lane_frag_addr(const float* base, int lane,
                                                   int r0, int ldm) {
    const float* p = base + (size_t)(r0 + ((lane >> 3) & 1) * 8 + (lane & 7)) * ldm
                          + (lane >> 4) * 4;
    return (unsigned)__cvta_generic_to_shared(p);
}

__device__ __forceinline__ void cpasync16(unsigned dst, const void* src) {
    asm volatile("cp.async.cg.shared.global [%0], [%1], 16;" :: "r"(dst), "l"(src));
}
#define CP_COMMIT() asm volatile("cp.async.commit_group;")
#define CP_WAIT0()  asm volatile("cp.async.wait_group 0;")
#define CP_WAIT1()  asm volatile("cp.async.wait_group 1;")

// ---------------------------------------------------------------------------
// Fused LayerNorm x3
// ---------------------------------------------------------------------------
__global__ void ln3_kernel(const float* __restrict__ xq,
                           const float* __restrict__ xk,
                           const float* __restrict__ xv,
                           const float* __restrict__ gamma,
                           const float* __restrict__ beta,
                           float* __restrict__ yq,
                           float* __restrict__ yk,
                           float* __restrict__ yv)
{
    int row = blockIdx.x;
    int which = blockIdx.y;
    const float* x = (which == 0) ? xq : (which == 1) ? xk : xv;
    float* y       = (which == 0) ? yq : (which == 1) ? yk : yv;
    int tid = threadIdx.x;
    const float4* xr = (const float4*)(x + (size_t)row * Dm);
    float4 v = xr[tid];
    float s  = v.x + v.y + v.z + v.w;
    float ss = v.x*v.x + v.y*v.y + v.z*v.z + v.w*v.w;
    #pragma unroll
    for (int o = 16; o > 0; o >>= 1) {
        s  += __shfl_down_sync(0xffffffffu, s,  o);
        ss += __shfl_down_sync(0xffffffffu, ss, o);
    }
    __shared__ float as[8], bs[8];
    __shared__ float s_mu, s_inv;
    if ((tid & 31) == 0) { as[tid >> 5] = s; bs[tid >> 5] = ss; }
    __syncthreads();
    if (tid == 0) {
        float S = 0.f, SS = 0.f;
        #pragma unroll
        for (int i = 0; i < 8; i++) { S += as[i]; SS += bs[i]; }
        float mu  = S * (1.0f / Dm);
        float var = SS * (1.0f / Dm) - mu * mu;
        s_mu  = mu;
        s_inv = rsqrtf(var + 1e-5f);
    }
    __syncthreads();
    float mu = s_mu, inv = s_inv;
    float4 g  = ((const float4*)gamma)[tid];
    float4 bb = ((const float4*)beta )[tid];
    float4 o;
    o.x = (v.x - mu) * inv * g.x + bb.x;
    o.y = (v.y - mu) * inv * g.y + bb.y;
    o.z = (v.z - mu) * inv * g.z + bb.z;
    o.w = (v.w - mu) * inv * g.w + bb.w;
    ((float4*)(y + (size_t)row * Dm))[tid] = o;
}

// ---------------------------------------------------------------------------
// tf32 tensor-core GEMM with bias: 128x256 block, BK=16, 8 warps of 64x64.
// round_out: round the result to tf32 on store (for tensors consumed raw
// by cp.async in the attention kernel).
// ---------------------------------------------------------------------------
#define G_AS (128*20)
#define G_BS (16*264)
#define GEMM_SMEM ((2*G_AS + 2*G_BS)*4)

__device__ __forceinline__ void gemm_body(const float* __restrict__ A,
                                          const float* __restrict__ B,
                                          const float* __restrict__ bias,
                                          float* __restrict__ C,
                                          int M, int N, int K,
                                          float* smem, bool round_out)
{
    float* As = smem;               // [2][128][20]
    float* Bs = smem + 2 * G_AS;    // [2][16][264]

    int tid  = threadIdx.x;
    int lane = tid & 31, wid = tid >> 5;
    int wm = (wid & 1) * 64, wn = (wid >> 1) * 64;
    int l4 = lane >> 2, lk = lane & 3;
    int mb = blockIdx.y * 128, nb = blockIdx.x * 256;

    int ar = tid >> 1, ak = (tid & 1) * 8;
    int bk = tid >> 4, bn = (tid & 15) * 4;
    const float* Ap = A + (size_t)(mb + ar) * K + ak;
    const float* Bp = B + (size_t)bk * N + nb + bn;

    float c[4][8][4];
    #pragma unroll
    for (int mi = 0; mi < 4; mi++)
        #pragma unroll
        for (int nj = 0; nj < 8; nj++)
            #pragma unroll
            for (int q = 0; q < 4; q++) c[mi][nj][q] = 0.f;

    #pragma unroll
    for (int i = 0; i < 2; i++) {
        float4 v = *(const float4*)(Ap + i * 4);
        float4 w; w.x = f2tff(v.x); w.y = f2tff(v.y); w.z = f2tff(v.z); w.w = f2tff(v.w);
        *(float4*)&As[ar * 20 + ak + i * 4] = w;
    }
    #pragma unroll
    for (int i = 0; i < 4; i++) {
        float4 u = *(const float4*)(Bp + i * 64);
        float4 z; z.x = f2tff(u.x); z.y = f2tff(u.y); z.z = f2tff(u.z); z.w = f2tff(u.w);
        *(float4*)&Bs[bk * 264 + bn + i * 64] = z;
    }
    __syncthreads();

    int nt = K >> 4;
    for (int t = 0; t < nt; t++) {
        int cur = t & 1, nxt = cur ^ 1;
        float4 pa[2], pb[4];
        bool more = (t + 1 < nt);
        if (more) {
            #pragma unroll
            for (int i = 0; i < 2; i++)
                pa[i] = *(const float4*)(Ap + (size_t)(t + 1) * 16 + i * 4);
            #pragma unroll
            for (int i = 0; i < 4; i++)
                pb[i] = *(const float4*)(Bp + (size_t)(t + 1) * 16 * N + i * 64);
        }
        const float* Ab = As + cur * G_AS;
        const float* Bb = Bs + cur * G_BS;
        unsigned a_ptr[4];
        #pragma unroll
        for (int mi = 0; mi < 4; mi++)
            a_ptr[mi] = lane_frag_addr(Ab, lane, wm + mi * 16, 20);

        #pragma unroll
        for (int kk = 0; kk < 2; kk++) {
            int k0 = kk * 8;
            unsigned af[4][4], bf[8][2];
            #pragma unroll
            for (int mi = 0; mi < 4; mi++)
                ldsmx4(af[mi], a_ptr[mi] + kk * 32);
            #pragma unroll
            for (int nj = 0; nj < 8; nj++) {
                int cc = wn + nj * 8 + l4;
                bf[nj][0] = __float_as_uint(Bb[(k0 + lk) * 264 + cc]);
                bf[nj][1] = __float_as_uint(Bb[(k0 + lk + 4) * 264 + cc]);
            }
            #pragma unroll
            for (int mi = 0; mi < 4; mi++)
                #pragma unroll
                for (int nj = 0; nj < 8; nj++)
                    MMA_TF32(c[mi][nj], af[mi], bf[nj]);
        }
        if (more) {
            float* An = As + nxt * G_AS;
            float* Bn = Bs + nxt * G_BS;
            #pragma unroll
            for (int i = 0; i < 2; i++) {
                float4 w; w.x = f2tff(pa[i].x); w.y = f2tff(pa[i].y);
                w.z = f2tff(pa[i].z); w.w = f2tff(pa[i].w);
                *(float4*)&An[ar * 20 + ak + i * 4] = w;
            }
            #pragma unroll
            for (int i = 0; i < 4; i++) {
                float4 z; z.x = f2tff(pb[i].x); z.y = f2tff(pb[i].y);
                z.z = f2tff(pb[i].z); z.w = f2tff(pb[i].w);
                *(float4*)&Bn[bk * 264 + bn + i * 64] = z;
            }
            __syncthreads();
        }
    }

    #pragma unroll
    for (int nj = 0; nj < 8; nj++) {
        int col = nb + wn + nj * 8 + 2 * lk;
        float2 bj = *(const float2*)&bias[col];
        #pragma unroll
        for (int mi = 0; mi < 4; mi++) {
            int r0 = mb + wm + mi * 16 + l4;
            float2 o0, o1;
            o0.x = c[mi][nj][0] + bj.x; o0.y = c[mi][nj][1] + bj.y;
            o1.x = c[mi][nj][2] + bj.x; o1.y = c[mi][nj][3] + bj.y;
            if (round_out) {
                o0.x = f2tff(o0.x); o0.y = f2tff(o0.y);
                o1.x = f2tff(o1.x); o1.y = f2tff(o1.y);
            }
            *(float2*)&C[(size_t)r0 * N + col] = o0;
            *(float2*)&C[(size_t)(r0 + 8) * N + col] = o1;
        }
    }
}

__global__ void __launch_bounds__(256, 1)
gemm_tf32(const float* __restrict__ A, const float* __restrict__ B,
          const float* __restrict__ bias, float* __restrict__ C,
          int M, int N, int K)
{
    extern __shared__ float smem[];
    gemm_body(A, B, bias, C, M, N, K, smem, false);
}

__global__ void __launch_bounds__(256, 1)
gemm_tf32_kv(const float* __restrict__ Ak, const float* __restrict__ Av,
             const float* __restrict__ Wk, const float* __restrict__ Wv,
             const float* __restrict__ bk_, const float* __restrict__ bv_,
             float* __restrict__ Ck, float* __restrict__ Cv,
             int M, int N, int K)
{
    extern __shared__ float smem[];
    // V output is consumed raw by cp.async in attention -> round to tf32 here.
    if (blockIdx.z == 0) gemm_body(Ak, Wk, bk_, Ck, M, N, K, smem, false);
    else                 gemm_body(Av, Wv, bv_, Cv, M, N, K, smem, true);
}

// ---------------------------------------------------------------------------
// RoPE (interleaved pairs), in place; output rounded to tf32.
// ---------------------------------------------------------------------------
__global__ void rope_kernel(float* __restrict__ X, int heads, int total_pairs)
{
    int p = blockIdx.x * blockDim.x + threadIdx.x;
    if (p >= total_pairs) return;
    int i = p & 31;
    int t = (p / (32 * heads)) & (Sq - 1);
    float invf = exp2f(-13.287712379549449f * ((float)i * (1.0f / 32.0f)));
    float ang  = (float)t * invf;
    float sn, cs;
    sincosf(ang, &sn, &cs);
    size_t e = (size_t)p * 2;
    float x1 = X[e], x2 = X[e + 1];
    X[e]     = f2tff(x1 * cs - x2 * sn);
    X[e + 1] = f2tff(x1 * sn + x2 * cs);
}

// ---------------------------------------------------------------------------
// Attention (single kernel, two sweeps, cp.async pipelined):
//  Sweep 1: QK^T + tile-local (m,l) via shfl -> one smem combine per tile.
//  Sweep 2: recompute QK^T, p = exp(s-m)/l, write probs, O += pV.
//  K double-buffered (prefetch jt+1); V loaded async, waited just before PV.
// ---------------------------------------------------------------------------
#define A_QS (128*68)
#define A_KS (128*68)
#define A_VS (128*72)
#define A_PS (128*132)
#define ATTN_SMEM ((A_QS + 2*A_KS + A_VS + A_PS + 128*2 + 256*2) * 4)

__global__ void __launch_bounds__(256, 1)
attn_kernel(const int* __restrict__ lens, float* __restrict__ attn)
{
    extern __shared__ float sm[];
    float* Qs    = sm;                       // [128 m][68]
    float* Ks0   = Qs + A_QS;                // [128 j][68]
    float* Ks1   = Ks0 + A_KS;
    float* Vs    = Ks1 + A_KS;               // [128 j][72]
    float* Ps    = Vs + A_VS;                // [128 m][132]
    float* mrow  = Ps + A_PS;                // [128]
    float* lrow  = mrow + 128;
    float* sredm = lrow + 128;               // [2][128]
    float* sredl = sredm + 256;              // [2][128]

    int tid  = threadIdx.x;
    int lane = tid & 31, wid = tid >> 5;
    int wm = (wid >> 1) * 32;
    int wn = (wid & 1) * 64;
    int wnidx = wid & 1;
    int wd = (wid & 1) * 32;
    int l4 = lane >> 2, lk = lane & 3;

    int mt = (int)gridDim.x - 1 - (int)blockIdx.x;   // heavy-first
    int qh = blockIdx.y, b = blockIdx.z;
    int kvh = qh >> 2;
    int grp = qh & 3;
    int len = lens[b];

    unsigned ks_addr[2] = {
        (unsigned)__cvta_generic_to_shared(Ks0),
        (unsigned)__cvta_generic_to_shared(Ks1)
    };
    unsigned vs_addr = (unsigned)__cvta_generic_to_shared(Vs);

    // Load Q tile (pre-rounded tf32 by rope)
    #pragma unroll
    for (int i = 0; i < 8; i++) {
        int lin = tid + i * 256;
        int r = lin >> 4, c4 = (lin & 15) * 4;
        float4 v = *(const float4*)&g_Q[((size_t)(b * Sq + mt * 128 + r)) * (NQ * DQh) + qh * 64 + c4];
        *(float4*)&Qs[r * 68 + c4] = v;
    }
    if (tid < 128) { mrow[tid] = -3.0e38f; lrow[tid] = 0.f; }

    unsigned q_ptr[2], p_ptr[2];
    #pragma unroll
    for (int mi = 0; mi < 2; mi++) {
        q_ptr[mi] = lane_frag_addr(Qs, lane, wm + mi * 16, 68);
        p_ptr[mi] = lane_frag_addr(Ps, lane, wm + mi * 16, 132);
    }

    int jend = min(mt, (len - 1) >> 7);
    size_t attn_head = (((size_t)(b * GRP + grp)) * NKV + kvh) * Sq;

    // async tile loaders (all 256 threads, 8 x 16B each)
    #define LOAD_K_ASYNC(JT, BUFADDR)                                           \
        do {                                                                    \
            _Pragma("unroll")                                                   \
            for (int i_ = 0; i_ < 8; i_++) {                                    \
                int lin_ = tid + i_ * 256;                                      \
                int r_ = lin_ >> 4, c4_ = (lin_ & 15) * 4;                      \
                cpasync16((BUFADDR) + (unsigned)(r_ * 68 + c4_) * 4,            \
                    &g_K[((size_t)(b * Sq + (JT) * 128 + r_)) * (NKV * DQh)     \
                         + kvh * 64 + c4_]);                                    \
            }                                                                   \
        } while (0)
    #define LOAD_V_ASYNC(JT)                                                    \
        do {                                                                    \
            _Pragma("unroll")                                                   \
            for (int i_ = 0; i_ < 8; i_++) {                                    \
                int lin_ = tid + i_ * 256;                                      \
                int r_ = lin_ >> 4, c4_ = (lin_ & 15) * 4;                      \
                cpasync16(vs_addr + (unsigned)(r_ * 72 + c4_) * 4,              \
                    &g_V[((size_t)(b * Sq + (JT) * 128 + r_)) * (NKV * DQh)     \
                         + kvh * 64 + c4_]);                                    \
            }                                                                   \
        } while (0)

    // =================== Sweep 1: stats only ===================
    LOAD_K_ASYNC(0, ks_addr[0]); CP_COMMIT();
    for (int jt = 0; jt <= jend; jt++) {
        CP_WAIT0();
        __syncthreads();
        const float* Kb = (jt & 1) ? Ks1 : Ks0;
        if (jt < jend) { LOAD_K_ASYNC(jt + 1, ks_addr[(jt + 1) & 1]); CP_COMMIT(); }

        // S = Q K^T
        float s[2][8][4];
        #pragma unroll
        for (int mi = 0; mi < 2; mi++)
            #pragma unroll
            for (int nj = 0; nj < 8; nj++)
                #pragma unroll
                for (int q = 0; q < 4; q++) s[mi][nj][q] = 0.f;
        #pragma unroll
        for (int kk = 0; kk < 8; kk++) {
            int k0 = kk * 8;
            unsigned af[2][4], bf[8][2];
            #pragma unroll
            for (int mi = 0; mi < 2; mi++)
                ldsmx4(af[mi], q_ptr[mi] + kk * 32);
            #pragma unroll
            for (int nj = 0; nj < 8; nj++) {
                int cc = wn + nj * 8 + l4;
                bf[nj][0] = __float_as_uint(Kb[cc * 68 + k0 + lk]);
                bf[nj][1] = __float_as_uint(Kb[cc * 68 + k0 + lk + 4]);
            }
            #pragma unroll
            for (int mi = 0; mi < 2; mi++)
                #pragma unroll
                for (int nj = 0; nj < 8; nj++)
                    MMA_TF32(s[mi][nj], af[mi], bf[nj]);
        }

        // scale + mask
        #pragma unroll
        for (int mi = 0; mi < 2; mi++) {
            int r0 = wm + mi * 16 + l4;
            int qr0 = mt * 128 + r0, qr1 = qr0 + 8;
            #pragma unroll
            for (int nj = 0; nj < 8; nj++) {
                int kc0 = jt * 128 + wn + nj * 8 + 2 * lk, kc1 = kc0 + 1;
                s[mi][nj][0] = (kc0 > qr0 || kc0 >= len) ? -1.0e30f : s[mi][nj][0] * 0.125f;
                s[mi][nj][1] = (kc1 > qr0 || kc1 >= len) ? -1.0e30f : s[mi][nj][1] * 0.125f;
                s[mi][nj][2] = (kc0 > qr1 || kc0 >= len) ? -1.0e30f : s[mi][nj][2] * 0.125f;
                s[mi][nj][3] = (kc1 > qr1 || kc1 >= len) ? -1.0e30f : s[mi][nj][3] * 0.125f;
            }
        }

        // tile-local (m, l) via shfl in 4-lane row groups
        #pragma unroll
        for (int mi = 0; mi < 2; mi++) {
            float m0 = -3.0e38f, m1 = -3.0e38f;
            #pragma unroll
            for (int nj = 0; nj < 8; nj++) {
                m0 = fmaxf(m0, fmaxf(s[mi][nj][0], s[mi][nj][1]));
                m1 = fmaxf(m1, fmaxf(s[mi][nj][2], s[mi][nj][3]));
            }
            m0 = fmaxf(m0, __shfl_xor_sync(0xffffffffu, m0, 1));
            m0 = fmaxf(m0, __shfl_xor_sync(0xffffffffu, m0, 2));
            m1 = fmaxf(m1, __shfl_xor_sync(0xffffffffu, m1, 1));
            m1 = fmaxf(m1, __shfl_xor_sync(0xffffffffu, m1, 2));
            float s0 = 0.f, s1 = 0.f;
            #pragma unroll
            for (int nj = 0; nj < 8; nj++) {
                s0 += __expf(s[mi][nj][0] - m0) + __expf(s[mi][nj][1] - m0);
                s1 += __expf(s[mi][nj][2] - m1) + __expf(s[mi][nj][3] - m1);
            }
            s0 += __shfl_xor_sync(0xffffffffu, s0, 1);
            s0 += __shfl_xor_sync(0xffffffffu, s0, 2);
            s1 += __shfl_xor_sync(0xffffffffu, s1, 1);
            s1 += __shfl_xor_sync(0xffffffffu, s1, 2);
            if (lk == 0) {
                int r0 = wm + mi * 16 + l4;
                sredm[wnidx * 128 + r0] = m0;      sredl[wnidx * 128 + r0] = s0;
                sredm[wnidx * 128 + r0 + 8] = m1;  sredl[wnidx * 128 + r0 + 8] = s1;
            }
        }
        __syncthreads();
        if (tid < 128) {
            float ma = sredm[tid], mb2 = sredm[128 + tid];
            float la = sredl[tid], lb2 = sredl[128 + tid];
            float mtile = fmaxf(ma, mb2);
            float ltile = la * __expf(ma - mtile) + lb2 * __expf(mb2 - mtile);
            float M = mrow[tid];
            float Mn = fmaxf(M, mtile);
            lrow[tid] = lrow[tid] * __expf(M - Mn) + ltile * __expf(mtile - Mn);
            mrow[tid] = Mn;
        }
    }
    __syncthreads();

    // per-lane final stats
    float fm[2][2], fl[2][2];
    #pragma unroll
    for (int mi = 0; mi < 2; mi++) {
        int r0 = wm + mi * 16 + l4;
        fm[mi][0] = mrow[r0];        fm[mi][1] = mrow[r0 + 8];
        fl[mi][0] = 1.0f / lrow[r0]; fl[mi][1] = 1.0f / lrow[r0 + 8];
    }

    float o[2][4][4];
    #pragma unroll
    for (int mi = 0; mi < 2; mi++)
        #pragma unroll
        for (int nj = 0; nj < 4; nj++)
            #pragma unroll
            for (int q = 0; q < 4; q++) o[mi][nj][q] = 0.f;

    // =================== Sweep 2: probs + PV ===================
    LOAD_K_ASYNC(0, ks_addr[0]); CP_COMMIT();
    for (int jt = 0; jt <= jend; jt++) {
        CP_WAIT0();
        __syncthreads();
        const float* Kb = (jt & 1) ? Ks1 : Ks0;
        LOAD_V_ASYNC(jt); CP_COMMIT();
        bool more = (jt < jend);
        if (more) { LOAD_K_ASYNC(jt + 1, ks_addr[(jt + 1) & 1]); CP_COMMIT(); }

        // S = Q K^T
        float s[2][8][4];
        #pragma unroll
        for (int mi = 0; mi < 2; mi++)
            #pragma unroll
            for (int nj = 0; nj < 8; nj++)
                #pragma unroll
                for (int q = 0; q < 4; q++) s[mi][nj][q] = 0.f;
        #pragma unroll
        for (int kk = 0; kk < 8; kk++) {
            int k0 = kk * 8;
            unsigned af[2][4], bf[8][2];
            #pragma unroll
            for (int mi = 0; mi < 2; mi++)
                ldsmx4(af[mi], q_ptr[mi] + kk * 32);
            #pragma unroll
            for (int nj = 0; nj < 8; nj++) {
                int cc = wn + nj * 8 + l4;
                bf[nj][0] = __float_as_uint(Kb[cc * 68 + k0 + lk]);
                bf[nj][1] = __float_as_uint(Kb[cc * 68 + k0 + lk + 4]);
            }
            #pragma unroll
            for (int mi = 0; mi < 2; mi++)
                #pragma unroll
                for (int nj = 0; nj < 8; nj++)
                    MMA_TF32(s[mi][nj], af[mi], bf[nj]);
        }

        // final normalized probs into Ps (full fp32; masked -> 0)
        #pragma unroll
        for (int mi = 0; mi < 2; mi++) {
            int r0 = wm + mi * 16 + l4;
            int qr0 = mt * 128 + r0, qr1 = qr0 + 8;
            float mm0 = fm[mi][0], mm1 = fm[mi][1];
            float il0 = fl[mi][0], il1 = fl[mi][1];
            #pragma unroll
            for (int nj = 0; nj < 8; nj++) {
                int c0 = wn + nj * 8 + 2 * lk;
                int kc0 = jt * 128 + c0, kc1 = kc0 + 1;
                float p0 = (kc0 > qr0 || kc0 >= len) ? 0.f
                         : __expf(s[mi][nj][0] * 0.125f - mm0) * il0;
                float p1 = (kc1 > qr0 || kc1 >= len) ? 0.f
                         : __expf(s[mi][nj][1] * 0.125f - mm0) * il0;
                float p2 = (kc0 > qr1 || kc0 >= len) ? 0.f
                         : __expf(s[mi][nj][2] * 0.125f - mm1) * il1;
                float p3 = (kc1 > qr1 || kc1 >= len) ? 0.f
                         : __expf(s[mi][nj][3] * 0.125f - mm1) * il1;
                Ps[r0 * 132 + c0] = p0;
                Ps[r0 * 132 + c0 + 1] = p1;
                Ps[(r0 + 8) * 132 + c0] = p2;
                Ps[(r0 + 8) * 132 + c0 + 1] = p3;
            }
        }
        __syncthreads();

        // write final probs to gmem (coalesced) — overlaps V load
        #pragma unroll
        for (int i = 0; i < 16; i++) {
            int lin = tid + i * 256;
            int r = lin >> 5, c4 = (lin & 31) * 4;
            float4 v = *(const float4*)&Ps[r * 132 + c4];
            *(float4*)&attn[(attn_head + mt * 128 + r) * Sq + jt * 128 + c4] = v;
        }

        // wait for V (K prefetch may remain in flight)
        if (more) { CP_WAIT1(); } else { CP_WAIT0(); }
        __syncthreads();

        // O += P @ V
        #pragma unroll
        for (int kk = 0; kk < 16; kk++) {
            int k0 = kk * 8;
            unsigned af[2][4], bf[4][2];
            #pragma unroll
            for (int mi = 0; mi < 2; mi++)
                ldsmx4(af[mi], p_ptr[mi] + kk * 32);
            #pragma unroll
            for (int nj = 0; nj < 4; nj++) {
                int cc = wd + nj * 8 + l4;
                bf[nj][0] = __float_as_uint(Vs[(k0 + lk) * 72 + cc]);
                bf[nj][1] = __float_as_uint(Vs[(k0 + lk + 4) * 72 + cc]);
            }
            #pragma unroll
            for (int mi = 0; mi < 2; mi++)
                #pragma unroll
                for (int nj = 0; nj < 4; nj++)
                    MMA_TF32(o[mi][nj], af[mi], bf[nj]);
        }
    }

    // zero-fill fully masked tiles
    for (int jt = jend + 1; jt < Sq / 128; jt++) {
        float4 z = make_float4(0.f, 0.f, 0.f, 0.f);
        #pragma unroll
        for (int i = 0; i < 16; i++) {
            int lin = tid + i * 256;
            int r = lin >> 5, c4 = (lin & 31) * 4;
            *(float4*)&attn[(attn_head + mt * 128 + r) * Sq + jt * 128 + c4] = z;
        }
    }

    // epilogue: write O (already normalized)
    #pragma unroll
    for (int mi = 0; mi < 2; mi++) {
        int r0 = wm + mi * 16 + l4;
        int gr0 = b * Sq + mt * 128 + r0;
        #pragma unroll
        for (int nj = 0; nj < 4; nj++) {
            int col = qh * 64 + wd + nj * 8 + 2 * lk;
            float2 w0, w1;
            w0.x = o[mi][nj][0]; w0.y = o[mi][nj][1];
            w1.x = o[mi][nj][2]; w1.y = o[mi][nj][3];
            *(float2*)&g_O[(size_t)gr0 * (NQ * DVh) + col] = w0;
            *(float2*)&g_O[(size_t)(gr0 + 8) * (NQ * DVh) + col] = w1;
        }
    }
    #undef LOAD_K_ASYNC
    #undef LOAD_V_ASYNC
}

// ---------------------------------------------------------------------------
// Launch
// ---------------------------------------------------------------------------
extern "C" void kernel_launch(void* const* d_in, const int* in_sizes, int n_in,
                              void* d_out, int out_size)
{
    const float* x_q  = (const float*)d_in[0];
    const float* x_k  = (const float*)d_in[1];
    const float* x_v  = (const float*)d_in[2];
    const int*   lens = (const int*)  d_in[3];
    const float* gam  = (const float*)d_in[4];
    const float* bet  = (const float*)d_in[5];
    const float* Wq   = (const float*)d_in[6];
    const float* bq   = (const float*)d_in[7];
    const float* Wk   = (const float*)d_in[8];
    const float* bk   = (const float*)d_in[9];
    const float* Wv   = (const float*)d_in[10];
    const float* bv   = (const float*)d_in[11];
    const float* Wo   = (const float*)d_in[12];
    const float* bo   = (const float*)d_in[13];

    float* out  = (float*)d_out;                       // (B, S, 1024)
    float* attn = out + (size_t)Bq * Sq * Dm;          // (B, GRP, NKV, S, S)

    float *xnq, *xnk, *xnv, *Qb, *Kb, *Vb, *Ob;
    cudaGetSymbolAddress((void**)&xnq, g_xnq);
    cudaGetSymbolAddress((void**)&xnk, g_xnk);
    cudaGetSymbolAddress((void**)&xnv, g_xnv);
    cudaGetSymbolAddress((void**)&Qb,  g_Q);
    cudaGetSymbolAddress((void**)&Kb,  g_K);
    cudaGetSymbolAddress((void**)&Vb,  g_V);
    cudaGetSymbolAddress((void**)&Ob,  g_O);

    const int M = Bq * Sq;   // 4096

    static bool attr_set = false;
    if (!attr_set) {
        cudaFuncSetAttribute(gemm_tf32, cudaFuncAttributeMaxDynamicSharedMemorySize, GEMM_SMEM);
        cudaFuncSetAttribute(gemm_tf32_kv, cudaFuncAttributeMaxDynamicSharedMemorySize, GEMM_SMEM);
        cudaFuncSetAttribute(attn_kernel, cudaFuncAttributeMaxDynamicSharedMemorySize, ATTN_SMEM);
        attr_set = true;
    }

    // 1) LayerNorms (fused)
    ln3_kernel<<<dim3(M, 3), 256>>>(x_q, x_k, x_v, gam, bet, xnq, xnk, xnv);

    // 2) Projections
    gemm_tf32<<<dim3(Dm / 256, M / 128), 256, GEMM_SMEM>>>(xnq, Wq, bq, Qb, M, NQ * DQh, Dm);
    gemm_tf32_kv<<<dim3(1, M / 128, 2), 256, GEMM_SMEM>>>(
        xnk, xnv, Wk, Wv, bk, bv, Kb, Vb, M, NKV * DQh, Dm);

    // 3) RoPE (rounds Q/K to tf32)
    {
        int pq = Bq * Sq * NQ * 32;
        int pk = Bq * Sq * NKV * 32;
        rope_kernel<<<(pq + 255) / 256, 256>>>(Qb, NQ, pq);
        rope_kernel<<<(pk + 255) / 256, 256>>>(Kb, NKV, pk);
    }

    // 4) Attention (two sweeps, cp.async pipelined)
    attn_kernel<<<dim3(Sq / 128, NQ, Bq), 256, ATTN_SMEM>>>(lens, attn);

    // 5) Output projection
    gemm_tf32<<<dim3(Dm / 256, M / 128), 256, GEMM_SMEM>>>(Ob, Wo, bo, out, M, Dm, Dm);
}

// round 8
// speedup vs baseline: 3.7450x; 1.4348x over previous
#include <cuda_runtime.h>
#include <cuda_fp16.h>
#include <cmath>

// Problem constants
#define Bq     2
#define Sq     2048
#define Dm     1024
#define NQ     16
#define NKV    4
#define GRP    4
#define DQh    64
#define DVh    64

// Scratch (device globals — no allocation allowed)
__device__ float g_xnq[Bq*Sq*Dm];
__device__ float g_xnk[Bq*Sq*Dm];
__device__ float g_xnv[Bq*Sq*Dm];
__device__ __align__(16) __half g_Qh[Bq*Sq*NQ*DQh];
__device__ __align__(16) __half g_Kh[Bq*Sq*NKV*DQh];
__device__ __align__(16) __half g_Vh[Bq*Sq*NKV*DVh];
__device__ float g_O  [Bq*Sq*NQ*DVh];

// fp16 mma: m16n8k16, f32 accum
#define MMA_F16(c, a, b0, b1)                                                  \
    asm volatile("mma.sync.aligned.m16n8k16.row.col.f32.f16.f16.f32 "          \
                 "{%0,%1,%2,%3},{%4,%5,%6,%7},{%8,%9},{%0,%1,%2,%3};"          \
                 : "+f"((c)[0]), "+f"((c)[1]), "+f"((c)[2]), "+f"((c)[3])      \
                 : "r"((a)[0]), "r"((a)[1]), "r"((a)[2]), "r"((a)[3]),         \
                   "r"(b0), "r"(b1))

__device__ __forceinline__ void ldsmx4(unsigned r[4], unsigned saddr) {
    asm volatile("ldmatrix.sync.aligned.m8n8.x4.shared.b16 {%0,%1,%2,%3}, [%4];"
                 : "=r"(r[0]), "=r"(r[1]), "=r"(r[2]), "=r"(r[3])
                 : "r"(saddr));
}
__device__ __forceinline__ void ldsmx4t(unsigned r[4], unsigned saddr) {
    asm volatile("ldmatrix.sync.aligned.m8n8.x4.trans.shared.b16 {%0,%1,%2,%3}, [%4];"
                 : "=r"(r[0]), "=r"(r[1]), "=r"(r[2]), "=r"(r[3])
                 : "r"(saddr));
}

// A-operand (row-major m16 x k16) ldmatrix lane address; add kk*32 bytes per k16 step
__device__ __forceinline__ unsigned a_frag_addr(const __half* base, int lane,
                                                int r0, int ldm) {
    const __half* p = base + (size_t)(r0 + (lane & 7) + ((lane >> 3) & 1) * 8) * ldm
                           + ((lane >> 4) & 1) * 8;
    return (unsigned)__cvta_generic_to_shared(p);
}
// B-operand, source stored n-major [n][k] (k contiguous): non-trans ldmatrix.
// covers n16 x k16 -> frags {b0(n0),b1(n0),b0(n0+8),b1(n0+8)}; add kk*32 B per k step
__device__ __forceinline__ unsigned bn_frag_addr(const __half* base, int lane,
                                                 int n0, int ldm) {
    const __half* p = base + (size_t)(n0 + (lane & 7) + ((lane >> 4) & 1) * 8) * ldm
                           + ((lane >> 3) & 1) * 8;
    return (unsigned)__cvta_generic_to_shared(p);
}
// B-operand, source stored k-major [k][n] (n contiguous): trans ldmatrix.
// covers k16 x n16 -> frags {b0(n0),b1(n0),b0(n0+8),b1(n0+8)}; add 16*ldm*2 B per k step
__device__ __forceinline__ unsigned bt_frag_addr(const __half* base, int lane,
                                                 int k0, int n0, int ldm) {
    const __half* p = base + (size_t)(k0 + (lane & 7) + ((lane >> 3) & 1) * 8) * ldm
                           + n0 + ((lane >> 4) & 1) * 8;
    return (unsigned)__cvta_generic_to_shared(p);
}

__device__ __forceinline__ void cpasync16(unsigned dst, const void* src) {
    asm volatile("cp.async.cg.shared.global [%0], [%1], 16;" :: "r"(dst), "l"(src));
}
#define CP_COMMIT() asm volatile("cp.async.commit_group;")
#define CP_WAIT0()  asm volatile("cp.async.wait_group 0;")
#define CP_WAIT1()  asm volatile("cp.async.wait_group 1;")

__device__ __forceinline__ __half2 f22h(float a, float b) {
    return __floats2half2_rn(a, b);
}

// ---------------------------------------------------------------------------
// Fused LayerNorm x3
// ---------------------------------------------------------------------------
__global__ void ln3_kernel(const float* __restrict__ xq,
                           const float* __restrict__ xk,
                           const float* __restrict__ xv,
                           const float* __restrict__ gamma,
                           const float* __restrict__ beta,
                           float* __restrict__ yq,
                           float* __restrict__ yk,
                           float* __restrict__ yv)
{
    int row = blockIdx.x;
    int which = blockIdx.y;
    const float* x = (which == 0) ? xq : (which == 1) ? xk : xv;
    float* y       = (which == 0) ? yq : (which == 1) ? yk : yv;
    int tid = threadIdx.x;
    const float4* xr = (const float4*)(x + (size_t)row * Dm);
    float4 v = xr[tid];
    float s  = v.x + v.y + v.z + v.w;
    float ss = v.x*v.x + v.y*v.y + v.z*v.z + v.w*v.w;
    #pragma unroll
    for (int o = 16; o > 0; o >>= 1) {
        s  += __shfl_down_sync(0xffffffffu, s,  o);
        ss += __shfl_down_sync(0xffffffffu, ss, o);
    }
    __shared__ float as[8], bs[8];
    __shared__ float s_mu, s_inv;
    if ((tid & 31) == 0) { as[tid >> 5] = s; bs[tid >> 5] = ss; }
    __syncthreads();
    if (tid == 0) {
        float S = 0.f, SS = 0.f;
        #pragma unroll
        for (int i = 0; i < 8; i++) { S += as[i]; SS += bs[i]; }
        float mu  = S * (1.0f / Dm);
        float var = SS * (1.0f / Dm) - mu * mu;
        s_mu  = mu;
        s_inv = rsqrtf(var + 1e-5f);
    }
    __syncthreads();
    float mu = s_mu, inv = s_inv;
    float4 g  = ((const float4*)gamma)[tid];
    float4 bb = ((const float4*)beta )[tid];
    float4 o;
    o.x = (v.x - mu) * inv * g.x + bb.x;
    o.y = (v.y - mu) * inv * g.y + bb.y;
    o.z = (v.z - mu) * inv * g.z + bb.z;
    o.w = (v.w - mu) * inv * g.w + bb.w;
    ((float4*)(y + (size_t)row * Dm))[tid] = o;
}

// ---------------------------------------------------------------------------
// fp16 tensor-core GEMM with bias: 128x256 block, BK=16, 8 warps of 64x64.
// A fp32 [M][K] -> cvt fp16 staged. B fp32 [K][N] -> cvt fp16 staged (trans ldsm).
// Output: fp32 (Cf) or fp16 (Ch).
// ---------------------------------------------------------------------------
#define G_ALD 24
#define G_BLD 264
#define G_AS (128*G_ALD)
#define G_BS (16*G_BLD)
#define GEMM_SMEM ((2*G_AS + 2*G_BS)*2)

__device__ __forceinline__ void gemm_body(const float* __restrict__ A,
                                          const float* __restrict__ B,
                                          const float* __restrict__ bias,
                                          float* __restrict__ Cf,
                                          __half* __restrict__ Ch,
                                          int M, int N, int K,
                                          __half* smem)
{
    __half* As = smem;                 // [2][128][24]
    __half* Bs = smem + 2 * G_AS;      // [2][16][264]

    int tid  = threadIdx.x;
    int lane = tid & 31, wid = tid >> 5;
    int wm = (wid & 1) * 64, wn = (wid >> 1) * 64;
    int l4 = lane >> 2, lk = lane & 3;
    int mb = blockIdx.y * 128, nb = blockIdx.x * 256;

    int ar = tid >> 1, ak = (tid & 1) * 8;     // A: row, fp32 col base
    int bk = tid >> 4, bl = (tid & 15) * 8;    // B: row, half-col base (x2 chunks of 8, stride 128)
    const float* Ap = A + (size_t)(mb + ar) * K + ak;
    const float* Bp = B + (size_t)bk * N + nb;

    float c[4][8][4];
    #pragma unroll
    for (int mi = 0; mi < 4; mi++)
        #pragma unroll
        for (int nj = 0; nj < 8; nj++)
            #pragma unroll
            for (int q = 0; q < 4; q++) c[mi][nj][q] = 0.f;

    // stage tile 0
    {
        float4 a0 = *(const float4*)(Ap);
        float4 a1 = *(const float4*)(Ap + 4);
        *(__half2*)&As[ar * G_ALD + ak + 0] = f22h(a0.x, a0.y);
        *(__half2*)&As[ar * G_ALD + ak + 2] = f22h(a0.z, a0.w);
        *(__half2*)&As[ar * G_ALD + ak + 4] = f22h(a1.x, a1.y);
        *(__half2*)&As[ar * G_ALD + ak + 6] = f22h(a1.z, a1.w);
        #pragma unroll
        for (int cch = 0; cch < 2; cch++) {
            int col = bl + cch * 128;
            float4 b0 = *(const float4*)(Bp + col);
            float4 b1 = *(const float4*)(Bp + col + 4);
            *(__half2*)&Bs[bk * G_BLD + col + 0] = f22h(b0.x, b0.y);
            *(__half2*)&Bs[bk * G_BLD + col + 2] = f22h(b0.z, b0.w);
            *(__half2*)&Bs[bk * G_BLD + col + 4] = f22h(b1.x, b1.y);
            *(__half2*)&Bs[bk * G_BLD + col + 6] = f22h(b1.z, b1.w);
        }
    }
    __syncthreads();

    int nt = K >> 4;
    for (int t = 0; t < nt; t++) {
        int cur = t & 1, nxt = cur ^ 1;
        float4 pa[2], pb[4];
        bool more = (t + 1 < nt);
        if (more) {
            pa[0] = *(const float4*)(Ap + (size_t)(t + 1) * 16);
            pa[1] = *(const float4*)(Ap + (size_t)(t + 1) * 16 + 4);
            #pragma unroll
            for (int cch = 0; cch < 2; cch++) {
                pb[cch*2]   = *(const float4*)(Bp + (size_t)(t + 1) * 16 * N + bl + cch * 128);
                pb[cch*2+1] = *(const float4*)(Bp + (size_t)(t + 1) * 16 * N + bl + cch * 128 + 4);
            }
        }
        const __half* Ab = As + cur * G_AS;
        const __half* Bb = Bs + cur * G_BS;

        unsigned af[4][4];
        #pragma unroll
        for (int mi = 0; mi < 4; mi++)
            ldsmx4(af[mi], a_frag_addr(Ab, lane, wm + mi * 16, G_ALD));
        #pragma unroll
        for (int g = 0; g < 4; g++) {
            unsigned bfr[4];
            ldsmx4t(bfr, bt_frag_addr(Bb, lane, 0, wn + g * 16, G_BLD));
            #pragma unroll
            for (int mi = 0; mi < 4; mi++) {
                MMA_F16(c[mi][2*g],   af[mi], bfr[0], bfr[1]);
                MMA_F16(c[mi][2*g+1], af[mi], bfr[2], bfr[3]);
            }
        }
        if (more) {
            __half* An = As + nxt * G_AS;
            __half* Bn = Bs + nxt * G_BS;
            *(__half2*)&An[ar * G_ALD + ak + 0] = f22h(pa[0].x, pa[0].y);
            *(__half2*)&An[ar * G_ALD + ak + 2] = f22h(pa[0].z, pa[0].w);
            *(__half2*)&An[ar * G_ALD + ak + 4] = f22h(pa[1].x, pa[1].y);
            *(__half2*)&An[ar * G_ALD + ak + 6] = f22h(pa[1].z, pa[1].w);
            #pragma unroll
            for (int cch = 0; cch < 2; cch++) {
                int col = bl + cch * 128;
                *(__half2*)&Bn[bk * G_BLD + col + 0] = f22h(pb[cch*2].x, pb[cch*2].y);
                *(__half2*)&Bn[bk * G_BLD + col + 2] = f22h(pb[cch*2].z, pb[cch*2].w);
                *(__half2*)&Bn[bk * G_BLD + col + 4] = f22h(pb[cch*2+1].x, pb[cch*2+1].y);
                *(__half2*)&Bn[bk * G_BLD + col + 6] = f22h(pb[cch*2+1].z, pb[cch*2+1].w);
            }
            __syncthreads();
        }
    }

    #pragma unroll
    for (int nj = 0; nj < 8; nj++) {
        int col = nb + wn + nj * 8 + 2 * lk;
        float2 bj = *(const float2*)&bias[col];
        #pragma unroll
        for (int mi = 0; mi < 4; mi++) {
            int r0 = mb + wm + mi * 16 + l4;
            float v0 = c[mi][nj][0] + bj.x, v1 = c[mi][nj][1] + bj.y;
            float v2 = c[mi][nj][2] + bj.x, v3 = c[mi][nj][3] + bj.y;
            if (Ch) {
                *(__half2*)&Ch[(size_t)r0 * N + col] = f22h(v0, v1);
                *(__half2*)&Ch[(size_t)(r0 + 8) * N + col] = f22h(v2, v3);
            } else {
                float2 o0; o0.x = v0; o0.y = v1;
                float2 o1; o1.x = v2; o1.y = v3;
                *(float2*)&Cf[(size_t)r0 * N + col] = o0;
                *(float2*)&Cf[(size_t)(r0 + 8) * N + col] = o1;
            }
        }
    }
}

__global__ void __launch_bounds__(256, 1)
gemm_f16(const float* __restrict__ A, const float* __restrict__ B,
         const float* __restrict__ bias, float* __restrict__ Cf,
         __half* __restrict__ Ch, int M, int N, int K)
{
    extern __shared__ __half smh[];
    gemm_body(A, B, bias, Cf, Ch, M, N, K, smh);
}

__global__ void __launch_bounds__(256, 1)
gemm_f16_kv(const float* __restrict__ Ak, const float* __restrict__ Av,
            const float* __restrict__ Wk, const float* __restrict__ Wv,
            const float* __restrict__ bk_, const float* __restrict__ bv_,
            __half* __restrict__ Ck, __half* __restrict__ Cv,
            int M, int N, int K)
{
    extern __shared__ __half smh[];
    if (blockIdx.z == 0) gemm_body(Ak, Wk, bk_, nullptr, Ck, M, N, K, smh);
    else                 gemm_body(Av, Wv, bv_, nullptr, Cv, M, N, K, smh);
}

// ---------------------------------------------------------------------------
// RoPE on fp16 buffers (pairs are adjacent -> one half2 each), in place.
// ---------------------------------------------------------------------------
__global__ void rope_kernel(__half* __restrict__ X, int heads, int total_pairs)
{
    int p = blockIdx.x * blockDim.x + threadIdx.x;
    if (p >= total_pairs) return;
    int i = p & 31;
    int t = (p / (32 * heads)) & (Sq - 1);
    float invf = exp2f(-13.287712379549449f * ((float)i * (1.0f / 32.0f)));
    float ang  = (float)t * invf;
    float sn, cs;
    sincosf(ang, &sn, &cs);
    __half2* xp = (__half2*)X + p;
    float2 v = __half22float2(*xp);
    *xp = f22h(v.x * cs - v.y * sn, v.x * sn + v.y * cs);
}

// ---------------------------------------------------------------------------
// Attention (fp16 mma, two sweeps, cp.async pipelined)
// Block: 128 q-rows; key tiles 128. Warps 4m x 2n.
// ---------------------------------------------------------------------------
#define A_QLD 72
#define A_KLD 72
#define A_VLD 72
#define A_PLD 136
#define A_QS (128*A_QLD)
#define A_KS (128*A_KLD)
#define A_VS (128*A_VLD)
#define A_PS (128*A_PLD)
#define ATTN_SMEM ((A_QS + 2*A_KS + A_VS + A_PS)*2 + (128*2 + 256*2)*4)

__global__ void __launch_bounds__(256, 1)
attn_kernel(const int* __restrict__ lens, float* __restrict__ attn)
{
    extern __shared__ __half smh[];
    __half* Qs  = smh;
    __half* Ks0 = Qs + A_QS;
    __half* Ks1 = Ks0 + A_KS;
    __half* Vs  = Ks1 + A_KS;
    __half* Ps  = Vs + A_VS;
    float* mrow  = (float*)(Ps + A_PS);
    float* lrow  = mrow + 128;
    float* sredm = lrow + 128;               // [2][128]
    float* sredl = sredm + 256;              // [2][128]

    int tid  = threadIdx.x;
    int lane = tid & 31, wid = tid >> 5;
    int wm = (wid >> 1) * 32;
    int wn = (wid & 1) * 64;
    int wnidx = wid & 1;
    int wd = (wid & 1) * 32;
    int l4 = lane >> 2, lk = lane & 3;

    int mt = (int)gridDim.x - 1 - (int)blockIdx.x;   // heavy-first
    int qh = blockIdx.y, b = blockIdx.z;
    int kvh = qh >> 2;
    int grp = qh & 3;
    int len = lens[b];

    unsigned qs_addr = (unsigned)__cvta_generic_to_shared(Qs);
    unsigned ks_addr[2] = {
        (unsigned)__cvta_generic_to_shared(Ks0),
        (unsigned)__cvta_generic_to_shared(Ks1)
    };
    unsigned vs_addr = (unsigned)__cvta_generic_to_shared(Vs);

    // async Q load (128 rows x 64 halves = 8 chunks of 16B per row)
    #pragma unroll
    for (int i = 0; i < 4; i++) {
        int lin = tid + i * 256;
        int r = lin >> 3, ch = lin & 7;
        cpasync16(qs_addr + (unsigned)(r * A_QLD + ch * 8) * 2,
                  &g_Qh[((size_t)(b * Sq + mt * 128 + r)) * (NQ * DQh) + qh * 64 + ch * 8]);
    }
    if (tid < 128) { mrow[tid] = -3.0e38f; lrow[tid] = 0.f; }

    unsigned q_ptr[2], p_ptr[2];
    #pragma unroll
    for (int mi = 0; mi < 2; mi++) {
        q_ptr[mi] = a_frag_addr(Qs, lane, wm + mi * 16, A_QLD);
        p_ptr[mi] = a_frag_addr(Ps, lane, wm + mi * 16, A_PLD);
    }
    unsigned k_ptr[2][4], v_ptr[2];
    #pragma unroll
    for (int g = 0; g < 4; g++) {
        k_ptr[0][g] = bn_frag_addr(Ks0, lane, wn + g * 16, A_KLD);
        k_ptr[1][g] = bn_frag_addr(Ks1, lane, wn + g * 16, A_KLD);
    }
    #pragma unroll
    for (int g = 0; g < 2; g++)
        v_ptr[g] = bt_frag_addr(Vs, lane, 0, wd + g * 16, A_VLD);

    int jend = min(mt, (len - 1) >> 7);
    size_t attn_head = (((size_t)(b * GRP + grp)) * NKV + kvh) * Sq;

    #define LOAD_K_ASYNC(JT, BUFADDR)                                           \
        do {                                                                    \
            _Pragma("unroll")                                                   \
            for (int i_ = 0; i_ < 4; i_++) {                                    \
                int lin_ = tid + i_ * 256;                                      \
                int r_ = lin_ >> 3, ch_ = lin_ & 7;                             \
                cpasync16((BUFADDR) + (unsigned)(r_ * A_KLD + ch_ * 8) * 2,     \
                    &g_Kh[((size_t)(b * Sq + (JT) * 128 + r_)) * (NKV * DQh)    \
                          + kvh * 64 + ch_ * 8]);                               \
            }                                                                   \
        } while (0)
    #define LOAD_V_ASYNC(JT)                                                    \
        do {                                                                    \
            _Pragma("unroll")                                                   \
            for (int i_ = 0; i_ < 4; i_++) {                                    \
                int lin_ = tid + i_ * 256;                                      \
                int r_ = lin_ >> 3, ch_ = lin_ & 7;                             \
                cpasync16(vs_addr + (unsigned)(r_ * A_VLD + ch_ * 8) * 2,       \
                    &g_Vh[((size_t)(b * Sq + (JT) * 128 + r_)) * (NKV * DQh)    \
                          + kvh * 64 + ch_ * 8]);                               \
            }                                                                   \
        } while (0)

    // QK^T into s (d = 64, 4 k16 steps)
    #define QK_MMA(KBUF)                                                        \
        do {                                                                    \
            _Pragma("unroll")                                                   \
            for (int kk = 0; kk < 4; kk++) {                                    \
                unsigned af[2][4];                                              \
                _Pragma("unroll")                                               \
                for (int mi = 0; mi < 2; mi++)                                  \
                    ldsmx4(af[mi], q_ptr[mi] + kk * 32);                        \
                _Pragma("unroll")                                               \
                for (int g = 0; g < 4; g++) {                                   \
                    unsigned bfr[4];                                            \
                    ldsmx4(bfr, k_ptr[KBUF][g] + kk * 32);                      \
                    _Pragma("unroll")                                           \
                    for (int mi = 0; mi < 2; mi++) {                            \
                        MMA_F16(s[mi][2*g],   af[mi], bfr[0], bfr[1]);          \
                        MMA_F16(s[mi][2*g+1], af[mi], bfr[2], bfr[3]);          \
                    }                                                           \
                }                                                               \
            }                                                                   \
        } while (0)

    // =================== Sweep 1: stats only ===================
    LOAD_K_ASYNC(0, ks_addr[0]); CP_COMMIT();
    for (int jt = 0; jt <= jend; jt++) {
        CP_WAIT0();
        __syncthreads();
        int kb = jt & 1;
        if (jt < jend) { LOAD_K_ASYNC(jt + 1, ks_addr[(jt + 1) & 1]); CP_COMMIT(); }

        float s[2][8][4];
        #pragma unroll
        for (int mi = 0; mi < 2; mi++)
            #pragma unroll
            for (int nj = 0; nj < 8; nj++)
                #pragma unroll
                for (int q = 0; q < 4; q++) s[mi][nj][q] = 0.f;
        QK_MMA(kb);

        // scale + mask
        #pragma unroll
        for (int mi = 0; mi < 2; mi++) {
            int r0 = wm + mi * 16 + l4;
            int qr0 = mt * 128 + r0, qr1 = qr0 + 8;
            #pragma unroll
            for (int nj = 0; nj < 8; nj++) {
                int kc0 = jt * 128 + wn + nj * 8 + 2 * lk, kc1 = kc0 + 1;
                s[mi][nj][0] = (kc0 > qr0 || kc0 >= len) ? -1.0e30f : s[mi][nj][0] * 0.125f;
                s[mi][nj][1] = (kc1 > qr0 || kc1 >= len) ? -1.0e30f : s[mi][nj][1] * 0.125f;
                s[mi][nj][2] = (kc0 > qr1 || kc0 >= len) ? -1.0e30f : s[mi][nj][2] * 0.125f;
                s[mi][nj][3] = (kc1 > qr1 || kc1 >= len) ? -1.0e30f : s[mi][nj][3] * 0.125f;
            }
        }

        // tile-local (m, l) via shfl in 4-lane row groups
        #pragma unroll
        for (int mi = 0; mi < 2; mi++) {
            float m0 = -3.0e38f, m1 = -3.0e38f;
            #pragma unroll
            for (int nj = 0; nj < 8; nj++) {
                m0 = fmaxf(m0, fmaxf(s[mi][nj][0], s[mi][nj][1]));
                m1 = fmaxf(m1, fmaxf(s[mi][nj][2], s[mi][nj][3]));
            }
            m0 = fmaxf(m0, __shfl_xor_sync(0xffffffffu, m0, 1));
            m0 = fmaxf(m0, __shfl_xor_sync(0xffffffffu, m0, 2));
            m1 = fmaxf(m1, __shfl_xor_sync(0xffffffffu, m1, 1));
            m1 = fmaxf(m1, __shfl_xor_sync(0xffffffffu, m1, 2));
            float s0 = 0.f, s1 = 0.f;
            #pragma unroll
            for (int nj = 0; nj < 8; nj++) {
                s0 += __expf(s[mi][nj][0] - m0) + __expf(s[mi][nj][1] - m0);
                s1 += __expf(s[mi][nj][2] - m1) + __expf(s[mi][nj][3] - m1);
            }
            s0 += __shfl_xor_sync(0xffffffffu, s0, 1);
            s0 += __shfl_xor_sync(0xffffffffu, s0, 2);
            s1 += __shfl_xor_sync(0xffffffffu, s1, 1);
            s1 += __shfl_xor_sync(0xffffffffu, s1, 2);
            if (lk == 0) {
                int r0 = wm + mi * 16 + l4;
                sredm[wnidx * 128 + r0] = m0;      sredl[wnidx * 128 + r0] = s0;
                sredm[wnidx * 128 + r0 + 8] = m1;  sredl[wnidx * 128 + r0 + 8] = s1;
            }
        }
        __syncthreads();
        if (tid < 128) {
            float ma = sredm[tid], mb2 = sredm[128 + tid];
            float la = sredl[tid], lb2 = sredl[128 + tid];
            float mtile = fmaxf(ma, mb2);
            float ltile = la * __expf(ma - mtile) + lb2 * __expf(mb2 - mtile);
            float M = mrow[tid];
            float Mn = fmaxf(M, mtile);
            lrow[tid] = lrow[tid] * __expf(M - Mn) + ltile * __expf(mtile - Mn);
            mrow[tid] = Mn;
        }
    }
    __syncthreads();

    float fm[2][2], fl[2][2];
    #pragma unroll
    for (int mi = 0; mi < 2; mi++) {
        int r0 = wm + mi * 16 + l4;
        fm[mi][0] = mrow[r0];        fm[mi][1] = mrow[r0 + 8];
        fl[mi][0] = 1.0f / lrow[r0]; fl[mi][1] = 1.0f / lrow[r0 + 8];
    }

    float o[2][4][4];
    #pragma unroll
    for (int mi = 0; mi < 2; mi++)
        #pragma unroll
        for (int nj = 0; nj < 4; nj++)
            #pragma unroll
            for (int q = 0; q < 4; q++) o[mi][nj][q] = 0.f;

    // =================== Sweep 2: probs + PV ===================
    LOAD_K_ASYNC(0, ks_addr[0]); CP_COMMIT();
    for (int jt = 0; jt <= jend; jt++) {
        CP_WAIT0();
        __syncthreads();
        int kb = jt & 1;
        LOAD_V_ASYNC(jt); CP_COMMIT();
        bool more = (jt < jend);
        if (more) { LOAD_K_ASYNC(jt + 1, ks_addr[(jt + 1) & 1]); CP_COMMIT(); }

        float s[2][8][4];
        #pragma unroll
        for (int mi = 0; mi < 2; mi++)
            #pragma unroll
            for (int nj = 0; nj < 8; nj++)
                #pragma unroll
                for (int q = 0; q < 4; q++) s[mi][nj][q] = 0.f;
        QK_MMA(kb);

        // final probs: fp32 -> gmem directly; fp16 -> Ps for PV mma
        #pragma unroll
        for (int mi = 0; mi < 2; mi++) {
            int r0 = wm + mi * 16 + l4;
            int qr0 = mt * 128 + r0, qr1 = qr0 + 8;
            float mm0 = fm[mi][0], mm1 = fm[mi][1];
            float il0 = fl[mi][0], il1 = fl[mi][1];
            #pragma unroll
            for (int nj = 0; nj < 8; nj++) {
                int c0 = wn + nj * 8 + 2 * lk;
                int kc0 = jt * 128 + c0, kc1 = kc0 + 1;
                float p0 = (kc0 > qr0 || kc0 >= len) ? 0.f
                         : __expf(s[mi][nj][0] * 0.125f - mm0) * il0;
                float p1 = (kc1 > qr0 || kc1 >= len) ? 0.f
                         : __expf(s[mi][nj][1] * 0.125f - mm0) * il0;
                float p2 = (kc0 > qr1 || kc0 >= len) ? 0.f
                         : __expf(s[mi][nj][2] * 0.125f - mm1) * il1;
                float p3 = (kc1 > qr1 || kc1 >= len) ? 0.f
                         : __expf(s[mi][nj][3] * 0.125f - mm1) * il1;
                float2 w0; w0.x = p0; w0.y = p1;
                float2 w1; w1.x = p2; w1.y = p3;
                *(float2*)&attn[(attn_head + qr0) * Sq + kc0] = w0;
                *(float2*)&attn[(attn_head + qr1) * Sq + kc0] = w1;
                *(__half2*)&Ps[r0 * A_PLD + c0] = f22h(p0, p1);
                *(__half2*)&Ps[(r0 + 8) * A_PLD + c0] = f22h(p2, p3);
            }
        }
        __syncthreads();

        // wait for V (K prefetch may remain in flight)
        if (more) { CP_WAIT1(); } else { CP_WAIT0(); }
        __syncthreads();

        // O += P @ V (k = j, 8 k16 steps)
        #pragma unroll
        for (int kk = 0; kk < 8; kk++) {
            unsigned af[2][4];
            #pragma unroll
            for (int mi = 0; mi < 2; mi++)
                ldsmx4(af[mi], p_ptr[mi] + kk * 32);
            #pragma unroll
            for (int g = 0; g < 2; g++) {
                unsigned bfr[4];
                ldsmx4t(bfr, v_ptr[g] + kk * 16 * A_VLD * 2);
                #pragma unroll
                for (int mi = 0; mi < 2; mi++) {
                    MMA_F16(o[mi][2*g],   af[mi], bfr[0], bfr[1]);
                    MMA_F16(o[mi][2*g+1], af[mi], bfr[2], bfr[3]);
                }
            }
        }
    }

    // zero-fill fully masked tiles
    for (int jt = jend + 1; jt < Sq / 128; jt++) {
        float4 z = make_float4(0.f, 0.f, 0.f, 0.f);
        #pragma unroll
        for (int i = 0; i < 16; i++) {
            int lin = tid + i * 256;
            int r = lin >> 5, c4 = (lin & 31) * 4;
            *(float4*)&attn[(attn_head + mt * 128 + r) * Sq + jt * 128 + c4] = z;
        }
    }

    // epilogue: write O
    #pragma unroll
    for (int mi = 0; mi < 2; mi++) {
        int r0 = wm + mi * 16 + l4;
        int gr0 = b * Sq + mt * 128 + r0;
        #pragma unroll
        for (int nj = 0; nj < 4; nj++) {
            int col = qh * 64 + wd + nj * 8 + 2 * lk;
            float2 w0, w1;
            w0.x = o[mi][nj][0]; w0.y = o[mi][nj][1];
            w1.x = o[mi][nj][2]; w1.y = o[mi][nj][3];
            *(float2*)&g_O[(size_t)gr0 * (NQ * DVh) + col] = w0;
            *(float2*)&g_O[(size_t)(gr0 + 8) * (NQ * DVh) + col] = w1;
        }
    }
    #undef LOAD_K_ASYNC
    #undef LOAD_V_ASYNC
    #undef QK_MMA
}

// ---------------------------------------------------------------------------
// Launch
// ---------------------------------------------------------------------------
extern "C" void kernel_launch(void* const* d_in, const int* in_sizes, int n_in,
                              void* d_out, int out_size)
{
    const float* x_q  = (const float*)d_in[0];
    const float* x_k  = (const float*)d_in[1];
    const float* x_v  = (const float*)d_in[2];
    const int*   lens = (const int*)  d_in[3];
    const float* gam  = (const float*)d_in[4];
    const float* bet  = (const float*)d_in[5];
    const float* Wq   = (const float*)d_in[6];
    const float* bq   = (const float*)d_in[7];
    const float* Wk   = (const float*)d_in[8];
    const float* bk   = (const float*)d_in[9];
    const float* Wv   = (const float*)d_in[10];
    const float* bv   = (const float*)d_in[11];
    const float* Wo   = (const float*)d_in[12];
    const float* bo   = (const float*)d_in[13];

    float* out  = (float*)d_out;                       // (B, S, 1024)
    float* attn = out + (size_t)Bq * Sq * Dm;          // (B, GRP, NKV, S, S)

    float *xnq, *xnk, *xnv, *Ob;
    __half *Qh, *Kh, *Vh;
    cudaGetSymbolAddress((void**)&xnq, g_xnq);
    cudaGetSymbolAddress((void**)&xnk, g_xnk);
    cudaGetSymbolAddress((void**)&xnv, g_xnv);
    cudaGetSymbolAddress((void**)&Qh,  g_Qh);
    cudaGetSymbolAddress((void**)&Kh,  g_Kh);
    cudaGetSymbolAddress((void**)&Vh,  g_Vh);
    cudaGetSymbolAddress((void**)&Ob,  g_O);

    const int M = Bq * Sq;   // 4096

    static bool attr_set = false;
    if (!attr_set) {
        cudaFuncSetAttribute(gemm_f16, cudaFuncAttributeMaxDynamicSharedMemorySize, GEMM_SMEM);
        cudaFuncSetAttribute(gemm_f16_kv, cudaFuncAttributeMaxDynamicSharedMemorySize, GEMM_SMEM);
        cudaFuncSetAttribute(attn_kernel, cudaFuncAttributeMaxDynamicSharedMemorySize, ATTN_SMEM);
        attr_set = true;
    }

    // 1) LayerNorms (fused)
    ln3_kernel<<<dim3(M, 3), 256>>>(x_q, x_k, x_v, gam, bet, xnq, xnk, xnv);

    // 2) Projections (fp16 tensor cores; Q/K/V outputs fp16)
    gemm_f16<<<dim3(Dm / 256, M / 128), 256, GEMM_SMEM>>>(xnq, Wq, bq, nullptr, Qh, M, NQ * DQh, Dm);
    gemm_f16_kv<<<dim3(1, M / 128, 2), 256, GEMM_SMEM>>>(
        xnk, xnv, Wk, Wv, bk, bv, Kh, Vh, M, NKV * DQh, Dm);

    // 3) RoPE on fp16 Q/K
    {
        int pq = Bq * Sq * NQ * 32;
        int pk = Bq * Sq * NKV * 32;
        rope_kernel<<<(pq + 255) / 256, 256>>>(Qh, NQ, pq);
        rope_kernel<<<(pk + 255) / 256, 256>>>(Kh, NKV, pk);
    }

    // 4) Attention (fp16 mma, two sweeps)
    attn_kernel<<<dim3(Sq / 128, NQ, Bq), 256, ATTN_SMEM>>>(lens, attn);

    // 5) Output projection (fp32 out)
    gemm_f16<<<dim3(Dm / 256, M / 128), 256, GEMM_SMEM>>>(Ob, Wo, bo, out, nullptr, M, Dm, Dm);
}